// round 11
// baseline (speedup 1.0000x reference)
#include <cuda_runtime.h>
#include <cuda_bf16.h>
#include <math.h>
#include <stdint.h>

#define Bsz  96
#define Hs   96
#define Ds   768
#define H2   9216
#define KQVN 27648

// ---------------- scratch (static device memory, no allocation) ----------------
__device__ float g_i[Bsz * Hs];
__device__ float g_f[Bsz * Hs];
__device__ float g_o[Bsz * H2];
__device__ float g_kqv[Bsz * KQVN];          // [96, 27648] : k | q | v (k pre-scaled by 1/96)
__device__ float g_vkT_part[16 * Hs * Hs];
__device__ float g_vkT[Hs * Hs];
__device__ int   g_denom[H2];                // float bits via atomicMax on non-neg floats
// pre-split bf16 operands
__device__ unsigned short g_AT[H2 * 192];    // n^T  [9216, 96hi|96lo]
__device__ unsigned short g_BT[H2 * 192];    // q^T
__device__ unsigned short g_npT[H2 * 192];   // n_prev^T
__device__ unsigned short g_kT[H2 * 192];    // k^T
__device__ unsigned short g_xs[Bsz * 1536];  // x split [96, 768hi|768lo]
__device__ unsigned short g_hps[Bsz * 192];  // h_prev split
__device__ unsigned short g_fis[Bsz * 384];  // [f hi|lo | i hi|lo]
__device__ unsigned short g_Cs[Bsz * 192];   // C split

// ---------------- helpers ----------------
__device__ __forceinline__ uint32_t smem_u32(const void* p) {
    uint32_t a;
    asm("{ .reg .u64 t; cvta.to.shared.u64 t, %1; cvt.u32.u64 %0, t; }" : "=r"(a) : "l"(p));
    return a;
}
#define LDSM_X4(r0, r1, r2, r3, addr) \
    asm volatile("ldmatrix.sync.aligned.m8n8.x4.shared.b16 {%0,%1,%2,%3}, [%4];" \
                 : "=r"(r0), "=r"(r1), "=r"(r2), "=r"(r3) : "r"(addr))
#define MMA16816(d, a, b0, b1) \
    asm volatile("mma.sync.aligned.m16n8k16.row.col.f32.bf16.bf16.f32 " \
                 "{%0,%1,%2,%3},{%4,%5,%6,%7},{%8,%9},{%0,%1,%2,%3};" \
                 : "+f"((d)[0]), "+f"((d)[1]), "+f"((d)[2]), "+f"((d)[3]) \
                 : "r"((a)[0]), "r"((a)[1]), "r"((a)[2]), "r"((a)[3]), "r"(b0), "r"(b1))

// ---------------- misc splits + denom zero, one launch ----------------
__global__ __launch_bounds__(256)
void split_misc(const float* __restrict__ x, const float* __restrict__ hp,
                unsigned short* __restrict__ xs_u16, unsigned short* __restrict__ hps_u16,
                int* __restrict__ denom) {
    int blk = blockIdx.x, tid = threadIdx.x;
    if (blk < 288) {                      // x split: 96x768
        __nv_bfloat16* xs = (__nv_bfloat16*)xs_u16;
        int e = blk * 256 + tid;
        int r = e / Ds, c = e % Ds;
        float v = x[e];
        __nv_bfloat16 hi = __float2bfloat16(v);
        xs[(size_t)r * 1536 + c] = hi;
        xs[(size_t)r * 1536 + Ds + c] = __float2bfloat16(v - __bfloat162float(hi));
    } else if (blk < 324) {               // h_prev split: 96x96
        __nv_bfloat16* hs = (__nv_bfloat16*)hps_u16;
        int e = (blk - 288) * 256 + tid;
        int r = e / Hs, c = e % Hs;
        float v = hp[e];
        __nv_bfloat16 hi = __float2bfloat16(v);
        hs[(size_t)r * 192 + c] = hi;
        hs[(size_t)r * 192 + Hs + c] = __float2bfloat16(v - __bfloat162float(hi));
    } else {                              // zero denom
        int e = (blk - 324) * 256 + tid;
        denom[e] = 0;
    }
}

// ---------------- fast transpose+split: dst[r][j]=hi(src[j][r]), dst[r][96+j]=lo ----
__global__ __launch_bounds__(256)
void prep_splitT(const float* __restrict__ src, int ld,
                 unsigned short* __restrict__ dst_u16) {
    __nv_bfloat16* dst = (__nv_bfloat16*)dst_u16;
    __shared__ float t[32][68];
    int r0 = blockIdx.x * 64, j0 = blockIdx.y * 32, tid = threadIdx.x;
#pragma unroll
    for (int it = 0; it < 2; it++) {
        int e = tid + it * 256;
        int jj = e >> 4, c4 = (e & 15) * 4;
        float4 v = *(const float4*)(src + (size_t)(j0 + jj) * ld + r0 + c4);
        *(float4*)&t[jj][c4] = v;
    }
    __syncthreads();
#pragma unroll
    for (int it = 0; it < 2; it++) {
        int e = tid + it * 256;
        int rr = e >> 3, q = e & 7;
        int isLo = q >> 2, jb = (q & 3) * 8;
        __nv_bfloat16 vals[8];
#pragma unroll
        for (int w = 0; w < 8; w++) {
            float f = t[jb + w][rr];
            __nv_bfloat16 hi = __float2bfloat16(f);
            vals[w] = isLo ? __float2bfloat16(f - __bfloat162float(hi)) : hi;
        }
        *(uint4*)(dst + (size_t)(r0 + rr) * 192 + isLo * 96 + j0 + jb) = *(uint4*)vals;
    }
}

// ---------------- gates: i = exp(x wix^T + b), f = exp(hp wfx^T + b), + split ----
__global__ __launch_bounds__(256)
void gates_kernel(const float* __restrict__ x, const float* __restrict__ hp,
                  const float* __restrict__ wix_w, const float* __restrict__ wix_b,
                  const float* __restrict__ wfx_w, const float* __restrict__ wfx_b,
                  float* __restrict__ gi, float* __restrict__ gf,
                  unsigned short* __restrict__ fis_u16) {
    int gw = blockIdx.x * 8 + (threadIdx.x >> 5);
    int lane = threadIdx.x & 31;
    int isI = gw < Bsz * Hs;
    int o = isI ? gw : gw - Bsz * Hs;
    int b = o / Hs, n = o % Hs;
    const float* a = isI ? x + (size_t)b * Ds : hp + (size_t)b * Hs;
    const float* w = isI ? wix_w + (size_t)n * Ds : wfx_w + (size_t)n * Hs;
    int K = isI ? Ds : Hs;
    float acc = 0.f;
    for (int k = lane; k < K; k += 32) acc += a[k] * w[k];
#pragma unroll
    for (int off = 16; off; off >>= 1) acc += __shfl_xor_sync(0xffffffffu, acc, off);
    if (lane == 0) {
        float v = expf(acc + (isI ? wix_b[n] : wfx_b[n]));
        (isI ? gi : gf)[o] = v;
        __nv_bfloat16* fis = (__nv_bfloat16*)fis_u16;
        __nv_bfloat16 hi = __float2bfloat16(v);
        int base = b * 384 + (isI ? 192 : 0) + n;
        fis[base] = hi;
        fis[base + 96] = __float2bfloat16(v - __bfloat162float(hi));
    }
}

// ======== Variant A: HMMA NT GEMM (N-tile 64, occ 3, double-buffered pipeline) ====
// EPI 0: kqv (bias + scale k) + fused kT/qT transpose-split epilogue
// EPI 1: sigmoid(bias)
template <int EPI, int KTOT>
__global__ __launch_bounds__(256, 3)
void hmma_convA(const unsigned short* __restrict__ Asp_u16,
                const float* __restrict__ Bm,
                const float* __restrict__ bias,
                float* __restrict__ out, int ldo,
                unsigned short* __restrict__ kT_u16,
                unsigned short* __restrict__ qT_u16) {
    const __nv_bfloat16* Asp = (const __nv_bfloat16*)Asp_u16;
    extern __shared__ __nv_bfloat16 dyn[];
    // double buffers; sT (epilogue staging) aliases dyn[0..12288) after final sync
    __nv_bfloat16* sAb[2] = {dyn, dyn + 6912};             // [96][72] each
    __nv_bfloat16* sBb[2] = {dyn + 13824, dyn + 18432};    // [64][72] each
    __nv_bfloat16* sT = dyn;
    int tid = threadIdx.x, warp = tid >> 5, lane = tid & 31;
    int n0 = blockIdx.x * 64;
    int wm = warp & 1, wn = warp >> 1;
    float acc[3][2][4] = {};

    uint4 aPre[3];
    float4 bPre[2];
    const int NC = KTOT / 32;

    // prologue: issue loads for chunk 0
#pragma unroll
    for (int t = 0; t < 3; t++) {
        int e = tid + t * 256;
        int r = e >> 3, col = (e & 7) * 8;
        int sc = (col < 32) ? col : (KTOT + col - 32);
        aPre[t] = *(const uint4*)(Asp + (size_t)r * (2 * KTOT) + sc);
    }
#pragma unroll
    for (int t = 0; t < 2; t++) {
        int e = tid + t * 256;
        int r = e >> 3, g = e & 7;
        bPre[t] = *(const float4*)(Bm + (size_t)(n0 + r) * KTOT + g * 4);
    }

#pragma unroll 1
    for (int c = 0; c < NC; c++) {
        __nv_bfloat16* sAr = sAb[c & 1];
        __nv_bfloat16* sBr = sBb[c & 1];
        // store chunk c (safe: iter c-2 LDSMs on this buffer completed before sync c-1)
#pragma unroll
        for (int t = 0; t < 3; t++) {
            int e = tid + t * 256;
            int r = e >> 3, col = (e & 7) * 8;
            *(uint4*)&sAr[r * 72 + col] = aPre[t];
        }
#pragma unroll
        for (int t = 0; t < 2; t++) {
            int e = tid + t * 256;
            int r = e >> 3, g = e & 7;
            float vv[4] = {bPre[t].x, bPre[t].y, bPre[t].z, bPre[t].w};
#pragma unroll
            for (int j = 0; j < 4; j++) {
                __nv_bfloat16 hi = __float2bfloat16(vv[j]);
                sBr[r * 72 + g * 4 + j] = hi;
                sBr[r * 72 + 32 + g * 4 + j] = __float2bfloat16(vv[j] - __bfloat162float(hi));
            }
        }
        // issue loads for chunk c+1 (overlap with sync + MMA below)
        if (c + 1 < NC) {
            int k0 = (c + 1) * 32;
#pragma unroll
            for (int t = 0; t < 3; t++) {
                int e = tid + t * 256;
                int r = e >> 3, col = (e & 7) * 8;
                int sc = (col < 32) ? (k0 + col) : (KTOT + k0 + col - 32);
                aPre[t] = *(const uint4*)(Asp + (size_t)r * (2 * KTOT) + sc);
            }
#pragma unroll
            for (int t = 0; t < 2; t++) {
                int e = tid + t * 256;
                int r = e >> 3, g = e & 7;
                bPre[t] = *(const float4*)(Bm + (size_t)(n0 + r) * KTOT + k0 + g * 4);
            }
        }
        __syncthreads();
        uint32_t aBase = smem_u32(sAr);
        uint32_t bBase = smem_u32(sBr);
        int aRow = wm * 48 + (lane & 15);
        int aCol = (lane >> 4) << 3;
        int bRow = wn * 16 + (lane & 7) + ((lane >> 4) << 3);
        int bCol = ((lane >> 3) & 1) << 3;
        // merged passes: A_hi x (B_hi, B_lo)
#pragma unroll
        for (int ks = 0; ks < 2; ks++) {
            int ka = ks * 16 + aCol, kb = ks * 16 + bCol;
            uint32_t af[3][4], bh[4], bl[4];
#pragma unroll
            for (int mi = 0; mi < 3; mi++) {
                uint32_t addr = aBase + (uint32_t)(((aRow + mi * 16) * 72 + ka) * 2);
                LDSM_X4(af[mi][0], af[mi][1], af[mi][2], af[mi][3], addr);
            }
            {
                uint32_t addr = bBase + (uint32_t)((bRow * 72 + kb) * 2);
                LDSM_X4(bh[0], bh[1], bh[2], bh[3], addr);
                addr = bBase + (uint32_t)((bRow * 72 + kb + 32) * 2);
                LDSM_X4(bl[0], bl[1], bl[2], bl[3], addr);
            }
#pragma unroll
            for (int mi = 0; mi < 3; mi++)
#pragma unroll
                for (int nj = 0; nj < 2; nj++) {
                    MMA16816(acc[mi][nj], af[mi], bh[nj * 2], bh[nj * 2 + 1]);
                    MMA16816(acc[mi][nj], af[mi], bl[nj * 2], bl[nj * 2 + 1]);
                }
        }
        // pass 2: A_lo x B_hi
#pragma unroll
        for (int ks = 0; ks < 2; ks++) {
            int ka = 32 + ks * 16 + aCol, kb = ks * 16 + bCol;
            uint32_t af[3][4], bh[4];
#pragma unroll
            for (int mi = 0; mi < 3; mi++) {
                uint32_t addr = aBase + (uint32_t)(((aRow + mi * 16) * 72 + ka) * 2);
                LDSM_X4(af[mi][0], af[mi][1], af[mi][2], af[mi][3], addr);
            }
            {
                uint32_t addr = bBase + (uint32_t)((bRow * 72 + kb) * 2);
                LDSM_X4(bh[0], bh[1], bh[2], bh[3], addr);
            }
#pragma unroll
            for (int mi = 0; mi < 3; mi++)
#pragma unroll
                for (int nj = 0; nj < 2; nj++)
                    MMA16816(acc[mi][nj], af[mi], bh[nj * 2], bh[nj * 2 + 1]);
        }
    }
    __syncthreads();   // pipeline drained; sT may alias buffers now
    const bool doT = (EPI == 0) && (n0 < 2 * H2);
#pragma unroll
    for (int mi = 0; mi < 3; mi++)
#pragma unroll
        for (int nj = 0; nj < 2; nj++)
#pragma unroll
            for (int r = 0; r < 4; r++) {
                int m = wm * 48 + mi * 16 + (lane >> 2) + ((r >> 1) * 8);
                int gl = wn * 16 + nj * 8 + (lane & 3) * 2 + (r & 1);
                int gn = n0 + gl;
                float v = acc[mi][nj][r] + bias[gn];
                if (EPI == 0) { if (gn < H2) v *= (1.0f / 96.0f); }
                if (EPI == 1) v = 1.0f / (1.0f + expf(-v));
                out[(size_t)m * ldo + gn] = v;
                if (doT) {
                    __nv_bfloat16 hi = __float2bfloat16(v);
                    sT[gl * 192 + m] = hi;
                    sT[gl * 192 + 96 + m] = __float2bfloat16(v - __bfloat162float(hi));
                }
            }
    if (doT) {
        __syncthreads();
        __nv_bfloat16* dstT = (__nv_bfloat16*)((n0 < H2) ? kT_u16 : qT_u16);
        int cb = (n0 < H2) ? n0 : (n0 - H2);
        for (int e = tid; e < 64 * 24; e += 256) {
            int row = e / 24, g = e % 24;
            *(uint4*)(dstT + (size_t)(cb + row) * 192 + g * 8) = *(uint4*)(sT + row * 192 + g * 8);
        }
    }
}

// ======== Variant B: HMMA NT GEMM, pre-split bf16 B [N, 192], up to 2 K-segments ====
// EPI 2: n (+ fused AT transpose-split), EPI 3: h = o * acc / denom
template <int EPI>
__global__ __launch_bounds__(256, 2)
void hmma_preB(const unsigned short* __restrict__ Asp_u16, int lda,
               const unsigned short* __restrict__ B1_u16,
               const unsigned short* __restrict__ B2_u16,
               int nseg,
               const float* __restrict__ omat,
               const int* __restrict__ denomBits,
               float* __restrict__ out, int ldo,
               unsigned short* __restrict__ AT_u16) {
    const __nv_bfloat16* Asp = (const __nv_bfloat16*)Asp_u16;
    extern __shared__ __nv_bfloat16 dsm[];
    __nv_bfloat16* sA = dsm;             // [96][200]
    __nv_bfloat16* sB = dsm + 96 * 200;  // [64][200]
    int tid = threadIdx.x, warp = tid >> 5, lane = tid & 31;
    int n0 = blockIdx.x * 64;
    int wm = warp & 1, wn = warp >> 1;
    float acc[3][2][4] = {};

#pragma unroll 1
    for (int s = 0; s < nseg; s++) {
        const __nv_bfloat16* Bseg =
            (s == 0) ? (const __nv_bfloat16*)B1_u16 : (const __nv_bfloat16*)B2_u16;
        __syncthreads();
        for (int e = tid; e < 96 * 24; e += 256) {
            int r = e / 24, g = e % 24;
            *(uint4*)(sA + r * 200 + g * 8) =
                *(const uint4*)(Asp + (size_t)r * lda + s * 192 + g * 8);
        }
        for (int e = tid; e < 64 * 24; e += 256) {
            int r = e / 24, g = e % 24;
            *(uint4*)(sB + r * 200 + g * 8) =
                *(const uint4*)(Bseg + (size_t)(n0 + r) * 192 + g * 8);
        }
        __syncthreads();
        uint32_t aBase = smem_u32(sA), bBase = smem_u32(sB);
        int aRow = wm * 48 + (lane & 15), aCol = (lane >> 4) << 3;
        int bRow = wn * 16 + (lane & 7) + ((lane >> 4) << 3);
        int bCol = ((lane >> 3) & 1) << 3;
        // merged passes: A_hi x (B_hi, B_lo)
#pragma unroll
        for (int ks = 0; ks < 6; ks++) {
            int ka = ks * 16 + aCol, kb = ks * 16 + bCol;
            uint32_t af[3][4], bh[4], bl[4];
#pragma unroll
            for (int mi = 0; mi < 3; mi++) {
                uint32_t addr = aBase + (uint32_t)(((aRow + mi * 16) * 200 + ka) * 2);
                LDSM_X4(af[mi][0], af[mi][1], af[mi][2], af[mi][3], addr);
            }
            {
                uint32_t addr = bBase + (uint32_t)((bRow * 200 + kb) * 2);
                LDSM_X4(bh[0], bh[1], bh[2], bh[3], addr);
                addr = bBase + (uint32_t)((bRow * 200 + kb + 96) * 2);
                LDSM_X4(bl[0], bl[1], bl[2], bl[3], addr);
            }
#pragma unroll
            for (int mi = 0; mi < 3; mi++)
#pragma unroll
                for (int nj = 0; nj < 2; nj++) {
                    MMA16816(acc[mi][nj], af[mi], bh[nj * 2], bh[nj * 2 + 1]);
                    MMA16816(acc[mi][nj], af[mi], bl[nj * 2], bl[nj * 2 + 1]);
                }
        }
        // pass 2: A_lo x B_hi
#pragma unroll
        for (int ks = 0; ks < 6; ks++) {
            int ka = 96 + ks * 16 + aCol, kb = ks * 16 + bCol;
            uint32_t af[3][4], bh[4];
#pragma unroll
            for (int mi = 0; mi < 3; mi++) {
                uint32_t addr = aBase + (uint32_t)(((aRow + mi * 16) * 200 + ka) * 2);
                LDSM_X4(af[mi][0], af[mi][1], af[mi][2], af[mi][3], addr);
            }
            {
                uint32_t addr = bBase + (uint32_t)((bRow * 200 + kb) * 2);
                LDSM_X4(bh[0], bh[1], bh[2], bh[3], addr);
            }
#pragma unroll
            for (int mi = 0; mi < 3; mi++)
#pragma unroll
                for (int nj = 0; nj < 2; nj++)
                    MMA16816(acc[mi][nj], af[mi], bh[nj * 2], bh[nj * 2 + 1]);
        }
    }
    if (EPI == 2) __syncthreads();   // before reusing sA as staging
#pragma unroll
    for (int mi = 0; mi < 3; mi++)
#pragma unroll
        for (int nj = 0; nj < 2; nj++)
#pragma unroll
            for (int r = 0; r < 4; r++) {
                int m = wm * 48 + mi * 16 + (lane >> 2) + ((r >> 1) * 8);
                int gl = wn * 16 + nj * 8 + (lane & 3) * 2 + (r & 1);
                int gn = n0 + gl;
                float v = acc[mi][nj][r];
                if (EPI == 3)
                    v = omat[(size_t)m * H2 + gn] * v / __int_as_float(denomBits[gn]);
                out[(size_t)m * ldo + gn] = v;
                if (EPI == 2) {
                    __nv_bfloat16 hi = __float2bfloat16(v);
                    sA[gl * 192 + m] = hi;
                    sA[gl * 192 + 96 + m] = __float2bfloat16(v - __bfloat162float(hi));
                }
            }
    if (EPI == 2) {
        __syncthreads();
        __nv_bfloat16* AT = (__nv_bfloat16*)AT_u16;
        for (int e = tid; e < 64 * 24; e += 256) {
            int row = e / 24, g = e % 24;
            *(uint4*)(AT + (size_t)(n0 + row) * 192 + g * 8) = *(uint4*)(sA + row * 192 + g * 8);
        }
    }
}

// ================= HMMA denom: A-resident, 6 B tiles per CTA =================
#define SMN_LD 200

__global__ __launch_bounds__(256, 2)
void denom_mma_kernel(const unsigned short* __restrict__ AT,
                      const unsigned short* __restrict__ BT,
                      int* __restrict__ denom) {
    extern __shared__ __align__(16) unsigned short sm[];
    unsigned short* sA = sm;
    unsigned short* sB = sm + 128 * SMN_LD;
    int tid = threadIdx.x;
    int r0 = blockIdx.x * 128;
    int cbase = blockIdx.y * 768;   // 6 tiles of 128

    // A tile loaded once per CTA
    for (int e = tid; e < 128 * 24; e += 256) {
        int row = e / 24, c8 = (e % 24) * 8;
        *(float4*)(sA + row * SMN_LD + c8) = *(const float4*)(AT + (size_t)(r0 + row) * 192 + c8);
    }

    int warp = tid >> 5, lane = tid & 31;
    int wm = warp & 1, wn = warp >> 1;
    uint32_t aBase = smem_u32(sA);
    uint32_t bBase = smem_u32(sB);

    int aRow = wm * 64 + (lane & 15);
    int aColL = (lane >> 4) << 3;
    int bRow = wn * 32 + (lane & 7) + ((lane >> 4) << 3);
    int bColL = ((lane >> 3) & 1) << 3;

    float mx[4][2];
#pragma unroll
    for (int mi = 0; mi < 4; mi++) { mx[mi][0] = 0.f; mx[mi][1] = 0.f; }

#pragma unroll 1
    for (int t = 0; t < 6; t++) {
        __syncthreads();
        for (int e = tid; e < 128 * 24; e += 256) {
            int row = e / 24, c8 = (e % 24) * 8;
            *(float4*)(sB + row * SMN_LD + c8) =
                *(const float4*)(BT + (size_t)(cbase + t * 128 + row) * 192 + c8);
        }
        __syncthreads();

        float acc[4][4][4];
#pragma unroll
        for (int mi = 0; mi < 4; mi++)
#pragma unroll
            for (int nj = 0; nj < 4; nj++)
#pragma unroll
                for (int r = 0; r < 4; r++) acc[mi][nj][r] = 0.f;

#pragma unroll 1
        for (int ks = 0; ks < 6; ks++) {
            int ka = ks * 16 + aColL;
            int kb = ks * 16 + bColL;
            uint32_t af[4][4], bh[2][4], bl[2][4];
#pragma unroll
            for (int mi = 0; mi < 4; mi++) {
                uint32_t addr = aBase + (uint32_t)(((aRow + mi * 16) * SMN_LD + ka) * 2);
                LDSM_X4(af[mi][0], af[mi][1], af[mi][2], af[mi][3], addr);
            }
#pragma unroll
            for (int nj2 = 0; nj2 < 2; nj2++) {
                uint32_t addr = bBase + (uint32_t)(((bRow + nj2 * 16) * SMN_LD + kb) * 2);
                LDSM_X4(bh[nj2][0], bh[nj2][1], bh[nj2][2], bh[nj2][3], addr);
                addr = bBase + (uint32_t)(((bRow + nj2 * 16) * SMN_LD + kb + 96) * 2);
                LDSM_X4(bl[nj2][0], bl[nj2][1], bl[nj2][2], bl[nj2][3], addr);
            }
#pragma unroll
            for (int mi = 0; mi < 4; mi++)
#pragma unroll
                for (int nj = 0; nj < 4; nj++) {
                    MMA16816(acc[mi][nj], af[mi], bh[nj >> 1][(nj & 1) * 2],
                             bh[nj >> 1][(nj & 1) * 2 + 1]);
                    MMA16816(acc[mi][nj], af[mi], bl[nj >> 1][(nj & 1) * 2],
                             bl[nj >> 1][(nj & 1) * 2 + 1]);
                }
        }
#pragma unroll 1
        for (int ks = 0; ks < 6; ks++) {
            int ka = 96 + ks * 16 + aColL;
            int kb = ks * 16 + bColL;
            uint32_t af[4][4], bh[2][4];
#pragma unroll
            for (int mi = 0; mi < 4; mi++) {
                uint32_t addr = aBase + (uint32_t)(((aRow + mi * 16) * SMN_LD + ka) * 2);
                LDSM_X4(af[mi][0], af[mi][1], af[mi][2], af[mi][3], addr);
            }
#pragma unroll
            for (int nj2 = 0; nj2 < 2; nj2++) {
                uint32_t addr = bBase + (uint32_t)(((bRow + nj2 * 16) * SMN_LD + kb) * 2);
                LDSM_X4(bh[nj2][0], bh[nj2][1], bh[nj2][2], bh[nj2][3], addr);
            }
#pragma unroll
            for (int mi = 0; mi < 4; mi++)
#pragma unroll
                for (int nj = 0; nj < 4; nj++)
                    MMA16816(acc[mi][nj], af[mi], bh[nj >> 1][(nj & 1) * 2],
                             bh[nj >> 1][(nj & 1) * 2 + 1]);
        }

#pragma unroll
        for (int mi = 0; mi < 4; mi++) {
#pragma unroll
            for (int nj = 0; nj < 4; nj++) {
                mx[mi][0] = fmaxf(mx[mi][0], fmaxf(fabsf(acc[mi][nj][0]), fabsf(acc[mi][nj][1])));
                mx[mi][1] = fmaxf(mx[mi][1], fmaxf(fabsf(acc[mi][nj][2]), fabsf(acc[mi][nj][3])));
            }
        }
    }

#pragma unroll
    for (int mi = 0; mi < 4; mi++) {
        float m0 = mx[mi][0], m1 = mx[mi][1];
        m0 = fmaxf(m0, __shfl_xor_sync(0xffffffffu, m0, 1));
        m0 = fmaxf(m0, __shfl_xor_sync(0xffffffffu, m0, 2));
        m1 = fmaxf(m1, __shfl_xor_sync(0xffffffffu, m1, 1));
        m1 = fmaxf(m1, __shfl_xor_sync(0xffffffffu, m1, 2));
        if ((lane & 3) == 0) {
            int rbase = r0 + wm * 64 + mi * 16 + (lane >> 2);
            atomicMax(&denom[rbase], __float_as_int(m0));
            atomicMax(&denom[rbase + 8], __float_as_int(m1));
        }
    }
}

// ---------------- v @ k^T : deterministic split-K (16 chunks of 576) ----------------
__global__ __launch_bounds__(256)
void vkt_part_kernel(const float* __restrict__ kqv, float* __restrict__ part) {
    const float* V  = kqv + 2 * H2;
    const float* Km = kqv;
    __shared__ float As[32][17];
    __shared__ float Bs[32][17];
    int tid = threadIdx.x, tx = tid & 15, ty = tid >> 4;
    int m0 = blockIdx.x * 32, n0 = blockIdx.y * 32;
    int kbase = blockIdx.z * 576;
    float a00 = 0, a01 = 0, a10 = 0, a11 = 0;
    for (int k0 = 0; k0 < 576; k0 += 16) {
        for (int e = tid; e < 32 * 16; e += 256) {
            int m = e >> 4, k = e & 15;
            As[m][k] = V[(size_t)(m0 + m) * KQVN + kbase + k0 + k];
            Bs[m][k] = Km[(size_t)(n0 + m) * KQVN + kbase + k0 + k];
        }
        __syncthreads();
#pragma unroll
        for (int kk = 0; kk < 16; kk++) {
            float av0 = As[ty][kk],      av1 = As[ty + 16][kk];
            float bv0 = Bs[tx][kk],      bv1 = Bs[tx + 16][kk];
            a00 += av0 * bv0; a01 += av0 * bv1;
            a10 += av1 * bv0; a11 += av1 * bv1;
        }
        __syncthreads();
    }
    float* p = part + blockIdx.z * (Hs * Hs);
    p[(m0 + ty) * Hs + (n0 + tx)]           = a00;
    p[(m0 + ty) * Hs + (n0 + tx + 16)]      = a01;
    p[(m0 + ty + 16) * Hs + (n0 + tx)]      = a10;
    p[(m0 + ty + 16) * Hs + (n0 + tx + 16)] = a11;
}

__global__ void vkt_reduce_kernel(const float* __restrict__ part, float* __restrict__ vkt) {
    int idx = blockIdx.x * blockDim.x + threadIdx.x;
    if (idx < Hs * Hs) {
        float s = 0.f;
#pragma unroll
        for (int c = 0; c < 16; c++) s += part[c * (Hs * Hs) + idx];
        vkt[idx] = s;
    }
}

// ---------------- C = f @ C_prev + i @ vkT   (96x96), + split ----------------
__global__ void c_kernel(const float* __restrict__ f, const float* __restrict__ i_,
                         const float* __restrict__ C_prev, const float* __restrict__ vkt,
                         float* __restrict__ outC, unsigned short* __restrict__ Cs_u16) {
    __shared__ float fs[Hs], is[Hs];
    int b = blockIdx.x, n = threadIdx.x;
    fs[n] = f[b * Hs + n];
    is[n] = i_[b * Hs + n];
    __syncthreads();
    float acc = 0.f;
    for (int h = 0; h < Hs; h++)
        acc += fs[h] * C_prev[h * Hs + n] + is[h] * vkt[h * Hs + n];
    outC[b * Hs + n] = acc;
    __nv_bfloat16* Cs = (__nv_bfloat16*)Cs_u16;
    __nv_bfloat16 hi = __float2bfloat16(acc);
    Cs[b * 192 + n] = hi;
    Cs[b * 192 + 96 + n] = __float2bfloat16(acc - __bfloat162float(hi));
}

// ---------------- launch ----------------
extern "C" void kernel_launch(void* const* d_in, const int* in_sizes, int n_in,
                              void* d_out, int out_size) {
    const float* x      = (const float*)d_in[0];
    const float* h_prev = (const float*)d_in[1];
    const float* C_prev = (const float*)d_in[2];
    const float* n_prev = (const float*)d_in[3];
    const float* wix_w  = (const float*)d_in[4];
    const float* wix_b  = (const float*)d_in[5];
    const float* wfx_w  = (const float*)d_in[6];
    const float* wfx_b  = (const float*)d_in[7];
    const float* Wox_w  = (const float*)d_in[8];
    const float* Wox_b  = (const float*)d_in[9];
    const float* Wkqv_w = (const float*)d_in[10];
    const float* Wkqv_b = (const float*)d_in[11];

    float* out   = (float*)d_out;
    float* out_h = out;                       // [96, 9216]
    float* out_C = out + Bsz * H2;            // [96, 96]
    float* out_n = out_C + Bsz * Hs;          // [96, 9216]

    float *p_i, *p_f, *p_o, *p_kqv, *p_part, *p_vkt;
    int* p_denom;
    unsigned short *p_AT, *p_BT, *p_npT, *p_kT, *p_xs, *p_hps, *p_fis, *p_Cs;
    cudaGetSymbolAddress((void**)&p_i,     g_i);
    cudaGetSymbolAddress((void**)&p_f,     g_f);
    cudaGetSymbolAddress((void**)&p_o,     g_o);
    cudaGetSymbolAddress((void**)&p_kqv,   g_kqv);
    cudaGetSymbolAddress((void**)&p_part,  g_vkT_part);
    cudaGetSymbolAddress((void**)&p_vkt,   g_vkT);
    cudaGetSymbolAddress((void**)&p_denom, g_denom);
    cudaGetSymbolAddress((void**)&p_AT,    g_AT);
    cudaGetSymbolAddress((void**)&p_BT,    g_BT);
    cudaGetSymbolAddress((void**)&p_npT,   g_npT);
    cudaGetSymbolAddress((void**)&p_kT,    g_kT);
    cudaGetSymbolAddress((void**)&p_xs,    g_xs);
    cudaGetSymbolAddress((void**)&p_hps,   g_hps);
    cudaGetSymbolAddress((void**)&p_fis,   g_fis);
    cudaGetSymbolAddress((void**)&p_Cs,    g_Cs);

    const int DENOM_SMEM = 2 * 128 * SMN_LD * 2;   // 102400
    const int PREB_SMEM  = (96 + 64) * 200 * 2;    // 64000
    const int CONV_SMEM  = 23040 * 2;              // 46080 (double-buffered)
    cudaFuncSetAttribute(denom_mma_kernel,
                         cudaFuncAttributeMaxDynamicSharedMemorySize, DENOM_SMEM);
    cudaFuncSetAttribute(hmma_preB<2>,
                         cudaFuncAttributeMaxDynamicSharedMemorySize, PREB_SMEM);
    cudaFuncSetAttribute(hmma_preB<3>,
                         cudaFuncAttributeMaxDynamicSharedMemorySize, PREB_SMEM);
    cudaFuncSetAttribute(hmma_convA<0, Ds>,
                         cudaFuncAttributeMaxDynamicSharedMemorySize, CONV_SMEM);
    cudaFuncSetAttribute(hmma_convA<1, Hs>,
                         cudaFuncAttributeMaxDynamicSharedMemorySize, CONV_SMEM);

    // x/h_prev splits + denom zero (one launch)
    split_misc<<<360, 256>>>(x, h_prev, p_xs, p_hps, p_denom);

    // n_prev^T split
    prep_splitT<<<dim3(H2 / 64, 3), 256>>>(n_prev, H2, p_npT);

    // i, f gates + split (one launch)
    gates_kernel<<<2304, 256>>>(x, h_prev, wix_w, wix_b, wfx_w, wfx_b, p_i, p_f, p_fis);

    // kqv = x @ Wkqv^T + b (HMMA, double-buffered pipeline) + fused kT/qT splits
    hmma_convA<0, Ds><<<KQVN / 64, 256, CONV_SMEM>>>(p_xs, Wkqv_w, Wkqv_b, p_kqv, KQVN,
                                                     p_kT, p_BT);

    // o = sigmoid(h_prev @ Wox^T + b)
    hmma_convA<1, Hs><<<H2 / 64, 256, CONV_SMEM>>>(p_hps, Wox_w, Wox_b, p_o, H2,
                                                   nullptr, nullptr);

    // n = f @ n_prev + i @ k  (HMMA) + fused AT transpose-split
    hmma_preB<2><<<H2 / 64, 256, PREB_SMEM>>>(p_fis, 384, p_npT, p_kT, 2,
                                              nullptr, nullptr, out_n, H2, p_AT);

    // vkT = v @ k^T
    vkt_part_kernel<<<dim3(3, 3, 16), 256>>>(p_kqv, p_part);
    vkt_reduce_kernel<<<36, 256>>>(p_part, p_vkt);

    // C = f @ C_prev + i @ vkT (+ split)
    c_kernel<<<Bsz, Hs>>>(p_f, p_i, C_prev, p_vkt, out_C, p_Cs);

    // denom = max_c |n^T q|  (A-resident, 6 B tiles per CTA)
    denom_mma_kernel<<<dim3(72, 12), 256, DENOM_SMEM>>>(p_AT, p_BT, p_denom);

    // h = o * (C @ q) / denom
    hmma_preB<3><<<H2 / 64, 256, PREB_SMEM>>>(p_Cs, 192, p_BT, nullptr, 1,
                                              p_o, p_denom, out_h, H2, nullptr);
}

// round 12
// speedup vs baseline: 1.0669x; 1.0669x over previous
#include <cuda_runtime.h>
#include <cuda_bf16.h>
#include <math.h>
#include <stdint.h>

#define Bsz  96
#define Hs   96
#define Ds   768
#define H2   9216
#define KQVN 27648

// ---------------- scratch (static device memory, no allocation) ----------------
__device__ float g_i[Bsz * Hs];
__device__ float g_f[Bsz * Hs];
__device__ float g_o[Bsz * H2];
__device__ float g_kqv[Bsz * KQVN];          // [96, 27648] : k | q | v (k pre-scaled by 1/96)
__device__ float g_vkT_part[16 * Hs * Hs];
__device__ float g_vkT[Hs * Hs];
__device__ int   g_denom[H2];                // float bits via atomicMax on non-neg floats
// pre-split bf16 operands
__device__ unsigned short g_AT[H2 * 192];    // n^T  [9216, 96hi|96lo]
__device__ unsigned short g_BT[H2 * 192];    // q^T
__device__ unsigned short g_npT[H2 * 192];   // n_prev^T
__device__ unsigned short g_kT[H2 * 192];    // k^T
__device__ unsigned short g_xs[Bsz * 1536];  // x split [96, 768hi|768lo]
__device__ unsigned short g_hps[Bsz * 192];  // h_prev split
__device__ unsigned short g_fis[Bsz * 384];  // [f hi|lo | i hi|lo]
__device__ unsigned short g_Cs[Bsz * 192];   // C split

// ---------------- helpers ----------------
__device__ __forceinline__ uint32_t smem_u32(const void* p) {
    uint32_t a;
    asm("{ .reg .u64 t; cvta.to.shared.u64 t, %1; cvt.u32.u64 %0, t; }" : "=r"(a) : "l"(p));
    return a;
}
#define LDSM_X4(r0, r1, r2, r3, addr) \
    asm volatile("ldmatrix.sync.aligned.m8n8.x4.shared.b16 {%0,%1,%2,%3}, [%4];" \
                 : "=r"(r0), "=r"(r1), "=r"(r2), "=r"(r3) : "r"(addr))
#define MMA16816(d, a, b0, b1) \
    asm volatile("mma.sync.aligned.m16n8k16.row.col.f32.bf16.bf16.f32 " \
                 "{%0,%1,%2,%3},{%4,%5,%6,%7},{%8,%9},{%0,%1,%2,%3};" \
                 : "+f"((d)[0]), "+f"((d)[1]), "+f"((d)[2]), "+f"((d)[3]) \
                 : "r"((a)[0]), "r"((a)[1]), "r"((a)[2]), "r"((a)[3]), "r"(b0), "r"(b1))

// ================= merged preamble: npT transpose-split | x/h splits | gates ======
// blocks [0,432): n_prev^T split ; [432,792): misc splits + denom zero ; [792,3096): gates
__global__ __launch_bounds__(256)
void preamble_kernel(const float* __restrict__ x, const float* __restrict__ hp,
                     const float* __restrict__ n_prev,
                     const float* __restrict__ wix_w, const float* __restrict__ wix_b,
                     const float* __restrict__ wfx_w, const float* __restrict__ wfx_b,
                     unsigned short* __restrict__ xs_u16, unsigned short* __restrict__ hps_u16,
                     unsigned short* __restrict__ npT_u16,
                     float* __restrict__ gi, float* __restrict__ gf,
                     unsigned short* __restrict__ fis_u16,
                     int* __restrict__ denom) {
    __shared__ float t[32][68];
    int blk = blockIdx.x, tid = threadIdx.x;
    if (blk < 432) {
        // ---- transpose+split of n_prev [96,9216] -> npT [9216,192] ----
        __nv_bfloat16* dst = (__nv_bfloat16*)npT_u16;
        int bx = blk % 144, by = blk / 144;
        int r0 = bx * 64, j0 = by * 32;
#pragma unroll
        for (int it = 0; it < 2; it++) {
            int e = tid + it * 256;
            int jj = e >> 4, c4 = (e & 15) * 4;
            float4 v = *(const float4*)(n_prev + (size_t)(j0 + jj) * H2 + r0 + c4);
            *(float4*)&t[jj][c4] = v;
        }
        __syncthreads();
#pragma unroll
        for (int it = 0; it < 2; it++) {
            int e = tid + it * 256;
            int rr = e >> 3, q = e & 7;
            int isLo = q >> 2, jb = (q & 3) * 8;
            __nv_bfloat16 vals[8];
#pragma unroll
            for (int w = 0; w < 8; w++) {
                float f = t[jb + w][rr];
                __nv_bfloat16 hi = __float2bfloat16(f);
                vals[w] = isLo ? __float2bfloat16(f - __bfloat162float(hi)) : hi;
            }
            *(uint4*)(dst + (size_t)(r0 + rr) * 192 + isLo * 96 + j0 + jb) = *(uint4*)vals;
        }
    } else if (blk < 792) {
        int b2 = blk - 432;
        if (b2 < 288) {                       // x split: 96x768
            __nv_bfloat16* xs = (__nv_bfloat16*)xs_u16;
            int e = b2 * 256 + tid;
            int r = e / Ds, c = e % Ds;
            float v = x[e];
            __nv_bfloat16 hi = __float2bfloat16(v);
            xs[(size_t)r * 1536 + c] = hi;
            xs[(size_t)r * 1536 + Ds + c] = __float2bfloat16(v - __bfloat162float(hi));
        } else if (b2 < 324) {                // h_prev split: 96x96
            __nv_bfloat16* hs = (__nv_bfloat16*)hps_u16;
            int e = (b2 - 288) * 256 + tid;
            int r = e / Hs, c = e % Hs;
            float v = hp[e];
            __nv_bfloat16 hi = __float2bfloat16(v);
            hs[(size_t)r * 192 + c] = hi;
            hs[(size_t)r * 192 + Hs + c] = __float2bfloat16(v - __bfloat162float(hi));
        } else {                              // zero denom
            int e = (b2 - 324) * 256 + tid;
            denom[e] = 0;
        }
    } else {
        // ---- gates: one warp per output ----
        int gw = (blk - 792) * 8 + (tid >> 5);
        int lane = tid & 31;
        int isI = gw < Bsz * Hs;
        int o = isI ? gw : gw - Bsz * Hs;
        int b = o / Hs, n = o % Hs;
        const float* a = isI ? x + (size_t)b * Ds : hp + (size_t)b * Hs;
        const float* w = isI ? wix_w + (size_t)n * Ds : wfx_w + (size_t)n * Hs;
        int K = isI ? Ds : Hs;
        float acc = 0.f;
        for (int k = lane; k < K; k += 32) acc += a[k] * w[k];
#pragma unroll
        for (int off = 16; off; off >>= 1) acc += __shfl_xor_sync(0xffffffffu, acc, off);
        if (lane == 0) {
            float v = expf(acc + (isI ? wix_b[n] : wfx_b[n]));
            (isI ? gi : gf)[o] = v;
            __nv_bfloat16* fis = (__nv_bfloat16*)fis_u16;
            __nv_bfloat16 hi = __float2bfloat16(v);
            int base = b * 384 + (isI ? 192 : 0) + n;
            fis[base] = hi;
            fis[base + 96] = __float2bfloat16(v - __bfloat162float(hi));
        }
    }
}

// ======== Variant A: HMMA NT GEMM (N-tile 64, occ 3), B fp32 converted on the fly ====
// Two-sync structure (R10-proven); c+1 loads issued BEFORE the 2nd sync.
// EPI 0: kqv (bias + scale k) + fused kT/qT transpose-split epilogue
// EPI 1: sigmoid(bias)
template <int EPI, int KTOT>
__global__ __launch_bounds__(256, 3)
void hmma_convA(const unsigned short* __restrict__ Asp_u16,
                const float* __restrict__ Bm,
                const float* __restrict__ bias,
                float* __restrict__ out, int ldo,
                unsigned short* __restrict__ kT_u16,
                unsigned short* __restrict__ qT_u16) {
    const __nv_bfloat16* Asp = (const __nv_bfloat16*)Asp_u16;
    extern __shared__ __nv_bfloat16 dyn[];
    __nv_bfloat16* sAr = dyn;                        // [96][72]
    __nv_bfloat16* sBr = dyn + 96 * 72;              // [64][72]
    __nv_bfloat16* sT  = dyn + 96 * 72 + 64 * 72;    // [64][192] (EPI 0 only)
    int tid = threadIdx.x, warp = tid >> 5, lane = tid & 31;
    int n0 = blockIdx.x * 64;
    int wm = warp & 1, wn = warp >> 1;
    float acc[3][2][4] = {};

    uint4 aPre[3];
    float4 bPre[2];
    const int NC = KTOT / 32;

#pragma unroll 1
    for (int c = 0; c < NC; c++) {
        if (c == 0) {
#pragma unroll
            for (int t = 0; t < 3; t++) {
                int e = tid + t * 256;
                int r = e >> 3, col = (e & 7) * 8;
                int sc = (col < 32) ? col : (KTOT + col - 32);
                aPre[t] = *(const uint4*)(Asp + (size_t)r * (2 * KTOT) + sc);
            }
#pragma unroll
            for (int t = 0; t < 2; t++) {
                int e = tid + t * 256;
                int r = e >> 3, g = e & 7;
                bPre[t] = *(const float4*)(Bm + (size_t)(n0 + r) * KTOT + g * 4);
            }
        }
        __syncthreads();
#pragma unroll
        for (int t = 0; t < 3; t++) {
            int e = tid + t * 256;
            int r = e >> 3, col = (e & 7) * 8;
            *(uint4*)&sAr[r * 72 + col] = aPre[t];
        }
#pragma unroll
        for (int t = 0; t < 2; t++) {
            int e = tid + t * 256;
            int r = e >> 3, g = e & 7;
            float vv[4] = {bPre[t].x, bPre[t].y, bPre[t].z, bPre[t].w};
#pragma unroll
            for (int j = 0; j < 4; j++) {
                __nv_bfloat16 hi = __float2bfloat16(vv[j]);
                sBr[r * 72 + g * 4 + j] = hi;
                sBr[r * 72 + 32 + g * 4 + j] = __float2bfloat16(vv[j] - __bfloat162float(hi));
            }
        }
        // issue loads for chunk c+1 BEFORE the sync (regs+global only: no smem hazard)
        if (c + 1 < NC) {
            int k0 = (c + 1) * 32;
#pragma unroll
            for (int t = 0; t < 3; t++) {
                int e = tid + t * 256;
                int r = e >> 3, col = (e & 7) * 8;
                int sc = (col < 32) ? (k0 + col) : (KTOT + k0 + col - 32);
                aPre[t] = *(const uint4*)(Asp + (size_t)r * (2 * KTOT) + sc);
            }
#pragma unroll
            for (int t = 0; t < 2; t++) {
                int e = tid + t * 256;
                int r = e >> 3, g = e & 7;
                bPre[t] = *(const float4*)(Bm + (size_t)(n0 + r) * KTOT + k0 + g * 4);
            }
        }
        __syncthreads();
        uint32_t aBase = smem_u32(sAr);
        uint32_t bBase = smem_u32(sBr);
        int aRow = wm * 48 + (lane & 15);
        int aCol = (lane >> 4) << 3;
        int bRow = wn * 16 + (lane & 7) + ((lane >> 4) << 3);
        int bCol = ((lane >> 3) & 1) << 3;
        // merged passes: A_hi x (B_hi, B_lo)
#pragma unroll
        for (int ks = 0; ks < 2; ks++) {
            int ka = ks * 16 + aCol, kb = ks * 16 + bCol;
            uint32_t af[3][4], bh[4], bl[4];
#pragma unroll
            for (int mi = 0; mi < 3; mi++) {
                uint32_t addr = aBase + (uint32_t)(((aRow + mi * 16) * 72 + ka) * 2);
                LDSM_X4(af[mi][0], af[mi][1], af[mi][2], af[mi][3], addr);
            }
            {
                uint32_t addr = bBase + (uint32_t)((bRow * 72 + kb) * 2);
                LDSM_X4(bh[0], bh[1], bh[2], bh[3], addr);
                addr = bBase + (uint32_t)((bRow * 72 + kb + 32) * 2);
                LDSM_X4(bl[0], bl[1], bl[2], bl[3], addr);
            }
#pragma unroll
            for (int mi = 0; mi < 3; mi++)
#pragma unroll
                for (int nj = 0; nj < 2; nj++) {
                    MMA16816(acc[mi][nj], af[mi], bh[nj * 2], bh[nj * 2 + 1]);
                    MMA16816(acc[mi][nj], af[mi], bl[nj * 2], bl[nj * 2 + 1]);
                }
        }
        // pass 2: A_lo x B_hi
#pragma unroll
        for (int ks = 0; ks < 2; ks++) {
            int ka = 32 + ks * 16 + aCol, kb = ks * 16 + bCol;
            uint32_t af[3][4], bh[4];
#pragma unroll
            for (int mi = 0; mi < 3; mi++) {
                uint32_t addr = aBase + (uint32_t)(((aRow + mi * 16) * 72 + ka) * 2);
                LDSM_X4(af[mi][0], af[mi][1], af[mi][2], af[mi][3], addr);
            }
            {
                uint32_t addr = bBase + (uint32_t)((bRow * 72 + kb) * 2);
                LDSM_X4(bh[0], bh[1], bh[2], bh[3], addr);
            }
#pragma unroll
            for (int mi = 0; mi < 3; mi++)
#pragma unroll
                for (int nj = 0; nj < 2; nj++)
                    MMA16816(acc[mi][nj], af[mi], bh[nj * 2], bh[nj * 2 + 1]);
        }
    }
    const bool doT = (EPI == 0) && (n0 < 2 * H2);
#pragma unroll
    for (int mi = 0; mi < 3; mi++)
#pragma unroll
        for (int nj = 0; nj < 2; nj++)
#pragma unroll
            for (int r = 0; r < 4; r++) {
                int m = wm * 48 + mi * 16 + (lane >> 2) + ((r >> 1) * 8);
                int gl = wn * 16 + nj * 8 + (lane & 3) * 2 + (r & 1);
                int gn = n0 + gl;
                float v = acc[mi][nj][r] + bias[gn];
                if (EPI == 0) { if (gn < H2) v *= (1.0f / 96.0f); }
                if (EPI == 1) v = 1.0f / (1.0f + expf(-v));
                out[(size_t)m * ldo + gn] = v;
                if (doT) {
                    __nv_bfloat16 hi = __float2bfloat16(v);
                    sT[gl * 192 + m] = hi;
                    sT[gl * 192 + 96 + m] = __float2bfloat16(v - __bfloat162float(hi));
                }
            }
    if (doT) {
        __syncthreads();
        __nv_bfloat16* dstT = (__nv_bfloat16*)((n0 < H2) ? kT_u16 : qT_u16);
        int cb = (n0 < H2) ? n0 : (n0 - H2);
        for (int e = tid; e < 64 * 24; e += 256) {
            int row = e / 24, g = e % 24;
            *(uint4*)(dstT + (size_t)(cb + row) * 192 + g * 8) = *(uint4*)(sT + row * 192 + g * 8);
        }
    }
}

// ======== Variant B: HMMA NT GEMM, pre-split bf16 B [N, 192], up to 2 K-segments ====
// EPI 2: n (+ fused AT transpose-split), EPI 3: h = o * acc / denom
template <int EPI>
__global__ __launch_bounds__(256, 2)
void hmma_preB(const unsigned short* __restrict__ Asp_u16, int lda,
               const unsigned short* __restrict__ B1_u16,
               const unsigned short* __restrict__ B2_u16,
               int nseg,
               const float* __restrict__ omat,
               const int* __restrict__ denomBits,
               float* __restrict__ out, int ldo,
               unsigned short* __restrict__ AT_u16) {
    const __nv_bfloat16* Asp = (const __nv_bfloat16*)Asp_u16;
    extern __shared__ __nv_bfloat16 dsm[];
    __nv_bfloat16* sA = dsm;             // [96][200]
    __nv_bfloat16* sB = dsm + 96 * 200;  // [64][200]
    int tid = threadIdx.x, warp = tid >> 5, lane = tid & 31;
    int n0 = blockIdx.x * 64;
    int wm = warp & 1, wn = warp >> 1;
    float acc[3][2][4] = {};

#pragma unroll 1
    for (int s = 0; s < nseg; s++) {
        const __nv_bfloat16* Bseg =
            (s == 0) ? (const __nv_bfloat16*)B1_u16 : (const __nv_bfloat16*)B2_u16;
        __syncthreads();
        for (int e = tid; e < 96 * 24; e += 256) {
            int r = e / 24, g = e % 24;
            *(uint4*)(sA + r * 200 + g * 8) =
                *(const uint4*)(Asp + (size_t)r * lda + s * 192 + g * 8);
        }
        for (int e = tid; e < 64 * 24; e += 256) {
            int r = e / 24, g = e % 24;
            *(uint4*)(sB + r * 200 + g * 8) =
                *(const uint4*)(Bseg + (size_t)(n0 + r) * 192 + g * 8);
        }
        __syncthreads();
        uint32_t aBase = smem_u32(sA), bBase = smem_u32(sB);
        int aRow = wm * 48 + (lane & 15), aCol = (lane >> 4) << 3;
        int bRow = wn * 16 + (lane & 7) + ((lane >> 4) << 3);
        int bCol = ((lane >> 3) & 1) << 3;
        // merged passes: A_hi x (B_hi, B_lo)
#pragma unroll
        for (int ks = 0; ks < 6; ks++) {
            int ka = ks * 16 + aCol, kb = ks * 16 + bCol;
            uint32_t af[3][4], bh[4], bl[4];
#pragma unroll
            for (int mi = 0; mi < 3; mi++) {
                uint32_t addr = aBase + (uint32_t)(((aRow + mi * 16) * 200 + ka) * 2);
                LDSM_X4(af[mi][0], af[mi][1], af[mi][2], af[mi][3], addr);
            }
            {
                uint32_t addr = bBase + (uint32_t)((bRow * 200 + kb) * 2);
                LDSM_X4(bh[0], bh[1], bh[2], bh[3], addr);
                addr = bBase + (uint32_t)((bRow * 200 + kb + 96) * 2);
                LDSM_X4(bl[0], bl[1], bl[2], bl[3], addr);
            }
#pragma unroll
            for (int mi = 0; mi < 3; mi++)
#pragma unroll
                for (int nj = 0; nj < 2; nj++) {
                    MMA16816(acc[mi][nj], af[mi], bh[nj * 2], bh[nj * 2 + 1]);
                    MMA16816(acc[mi][nj], af[mi], bl[nj * 2], bl[nj * 2 + 1]);
                }
        }
        // pass 2: A_lo x B_hi
#pragma unroll
        for (int ks = 0; ks < 6; ks++) {
            int ka = 96 + ks * 16 + aCol, kb = ks * 16 + bCol;
            uint32_t af[3][4], bh[4];
#pragma unroll
            for (int mi = 0; mi < 3; mi++) {
                uint32_t addr = aBase + (uint32_t)(((aRow + mi * 16) * 200 + ka) * 2);
                LDSM_X4(af[mi][0], af[mi][1], af[mi][2], af[mi][3], addr);
            }
            {
                uint32_t addr = bBase + (uint32_t)((bRow * 200 + kb) * 2);
                LDSM_X4(bh[0], bh[1], bh[2], bh[3], addr);
            }
#pragma unroll
            for (int mi = 0; mi < 3; mi++)
#pragma unroll
                for (int nj = 0; nj < 2; nj++)
                    MMA16816(acc[mi][nj], af[mi], bh[nj * 2], bh[nj * 2 + 1]);
        }
    }
    if (EPI == 2) __syncthreads();   // before reusing sA as staging
#pragma unroll
    for (int mi = 0; mi < 3; mi++)
#pragma unroll
        for (int nj = 0; nj < 2; nj++)
#pragma unroll
            for (int r = 0; r < 4; r++) {
                int m = wm * 48 + mi * 16 + (lane >> 2) + ((r >> 1) * 8);
                int gl = wn * 16 + nj * 8 + (lane & 3) * 2 + (r & 1);
                int gn = n0 + gl;
                float v = acc[mi][nj][r];
                if (EPI == 3)
                    v = omat[(size_t)m * H2 + gn] * v / __int_as_float(denomBits[gn]);
                out[(size_t)m * ldo + gn] = v;
                if (EPI == 2) {
                    __nv_bfloat16 hi = __float2bfloat16(v);
                    sA[gl * 192 + m] = hi;
                    sA[gl * 192 + 96 + m] = __float2bfloat16(v - __bfloat162float(hi));
                }
            }
    if (EPI == 2) {
        __syncthreads();
        __nv_bfloat16* AT = (__nv_bfloat16*)AT_u16;
        for (int e = tid; e < 64 * 24; e += 256) {
            int row = e / 24, g = e % 24;
            *(uint4*)(AT + (size_t)(n0 + row) * 192 + g * 8) = *(uint4*)(sA + row * 192 + g * 8);
        }
    }
}

// ================= HMMA denom: A-resident, 6 B tiles per CTA =================
#define SMN_LD 200

__global__ __launch_bounds__(256, 2)
void denom_mma_kernel(const unsigned short* __restrict__ AT,
                      const unsigned short* __restrict__ BT,
                      int* __restrict__ denom) {
    extern __shared__ __align__(16) unsigned short sm[];
    unsigned short* sA = sm;
    unsigned short* sB = sm + 128 * SMN_LD;
    int tid = threadIdx.x;
    int r0 = blockIdx.x * 128;
    int cbase = blockIdx.y * 768;   // 6 tiles of 128

    // A tile loaded once per CTA
    for (int e = tid; e < 128 * 24; e += 256) {
        int row = e / 24, c8 = (e % 24) * 8;
        *(float4*)(sA + row * SMN_LD + c8) = *(const float4*)(AT + (size_t)(r0 + row) * 192 + c8);
    }

    int warp = tid >> 5, lane = tid & 31;
    int wm = warp & 1, wn = warp >> 1;
    uint32_t aBase = smem_u32(sA);
    uint32_t bBase = smem_u32(sB);

    int aRow = wm * 64 + (lane & 15);
    int aColL = (lane >> 4) << 3;
    int bRow = wn * 32 + (lane & 7) + ((lane >> 4) << 3);
    int bColL = ((lane >> 3) & 1) << 3;

    float mx[4][2];
#pragma unroll
    for (int mi = 0; mi < 4; mi++) { mx[mi][0] = 0.f; mx[mi][1] = 0.f; }

#pragma unroll 1
    for (int t = 0; t < 6; t++) {
        __syncthreads();
        for (int e = tid; e < 128 * 24; e += 256) {
            int row = e / 24, c8 = (e % 24) * 8;
            *(float4*)(sB + row * SMN_LD + c8) =
                *(const float4*)(BT + (size_t)(cbase + t * 128 + row) * 192 + c8);
        }
        __syncthreads();

        float acc[4][4][4];
#pragma unroll
        for (int mi = 0; mi < 4; mi++)
#pragma unroll
            for (int nj = 0; nj < 4; nj++)
#pragma unroll
                for (int r = 0; r < 4; r++) acc[mi][nj][r] = 0.f;

#pragma unroll 1
        for (int ks = 0; ks < 6; ks++) {
            int ka = ks * 16 + aColL;
            int kb = ks * 16 + bColL;
            uint32_t af[4][4], bh[2][4], bl[2][4];
#pragma unroll
            for (int mi = 0; mi < 4; mi++) {
                uint32_t addr = aBase + (uint32_t)(((aRow + mi * 16) * SMN_LD + ka) * 2);
                LDSM_X4(af[mi][0], af[mi][1], af[mi][2], af[mi][3], addr);
            }
#pragma unroll
            for (int nj2 = 0; nj2 < 2; nj2++) {
                uint32_t addr = bBase + (uint32_t)(((bRow + nj2 * 16) * SMN_LD + kb) * 2);
                LDSM_X4(bh[nj2][0], bh[nj2][1], bh[nj2][2], bh[nj2][3], addr);
                addr = bBase + (uint32_t)(((bRow + nj2 * 16) * SMN_LD + kb + 96) * 2);
                LDSM_X4(bl[nj2][0], bl[nj2][1], bl[nj2][2], bl[nj2][3], addr);
            }
#pragma unroll
            for (int mi = 0; mi < 4; mi++)
#pragma unroll
                for (int nj = 0; nj < 4; nj++) {
                    MMA16816(acc[mi][nj], af[mi], bh[nj >> 1][(nj & 1) * 2],
                             bh[nj >> 1][(nj & 1) * 2 + 1]);
                    MMA16816(acc[mi][nj], af[mi], bl[nj >> 1][(nj & 1) * 2],
                             bl[nj >> 1][(nj & 1) * 2 + 1]);
                }
        }
#pragma unroll 1
        for (int ks = 0; ks < 6; ks++) {
            int ka = 96 + ks * 16 + aColL;
            int kb = ks * 16 + bColL;
            uint32_t af[4][4], bh[2][4];
#pragma unroll
            for (int mi = 0; mi < 4; mi++) {
                uint32_t addr = aBase + (uint32_t)(((aRow + mi * 16) * SMN_LD + ka) * 2);
                LDSM_X4(af[mi][0], af[mi][1], af[mi][2], af[mi][3], addr);
            }
#pragma unroll
            for (int nj2 = 0; nj2 < 2; nj2++) {
                uint32_t addr = bBase + (uint32_t)(((bRow + nj2 * 16) * SMN_LD + kb) * 2);
                LDSM_X4(bh[nj2][0], bh[nj2][1], bh[nj2][2], bh[nj2][3], addr);
            }
#pragma unroll
            for (int mi = 0; mi < 4; mi++)
#pragma unroll
                for (int nj = 0; nj < 4; nj++)
                    MMA16816(acc[mi][nj], af[mi], bh[nj >> 1][(nj & 1) * 2],
                             bh[nj >> 1][(nj & 1) * 2 + 1]);
        }

#pragma unroll
        for (int mi = 0; mi < 4; mi++) {
#pragma unroll
            for (int nj = 0; nj < 4; nj++) {
                mx[mi][0] = fmaxf(mx[mi][0], fmaxf(fabsf(acc[mi][nj][0]), fabsf(acc[mi][nj][1])));
                mx[mi][1] = fmaxf(mx[mi][1], fmaxf(fabsf(acc[mi][nj][2]), fabsf(acc[mi][nj][3])));
            }
        }
    }

#pragma unroll
    for (int mi = 0; mi < 4; mi++) {
        float m0 = mx[mi][0], m1 = mx[mi][1];
        m0 = fmaxf(m0, __shfl_xor_sync(0xffffffffu, m0, 1));
        m0 = fmaxf(m0, __shfl_xor_sync(0xffffffffu, m0, 2));
        m1 = fmaxf(m1, __shfl_xor_sync(0xffffffffu, m1, 1));
        m1 = fmaxf(m1, __shfl_xor_sync(0xffffffffu, m1, 2));
        if ((lane & 3) == 0) {
            int rbase = r0 + wm * 64 + mi * 16 + (lane >> 2);
            atomicMax(&denom[rbase], __float_as_int(m0));
            atomicMax(&denom[rbase + 8], __float_as_int(m1));
        }
    }
}

// ---------------- v @ k^T : deterministic split-K (16 chunks of 576) ----------------
__global__ __launch_bounds__(256)
void vkt_part_kernel(const float* __restrict__ kqv, float* __restrict__ part) {
    const float* V  = kqv + 2 * H2;
    const float* Km = kqv;
    __shared__ float As[32][17];
    __shared__ float Bs[32][17];
    int tid = threadIdx.x, tx = tid & 15, ty = tid >> 4;
    int m0 = blockIdx.x * 32, n0 = blockIdx.y * 32;
    int kbase = blockIdx.z * 576;
    float a00 = 0, a01 = 0, a10 = 0, a11 = 0;
    for (int k0 = 0; k0 < 576; k0 += 16) {
        for (int e = tid; e < 32 * 16; e += 256) {
            int m = e >> 4, k = e & 15;
            As[m][k] = V[(size_t)(m0 + m) * KQVN + kbase + k0 + k];
            Bs[m][k] = Km[(size_t)(n0 + m) * KQVN + kbase + k0 + k];
        }
        __syncthreads();
#pragma unroll
        for (int kk = 0; kk < 16; kk++) {
            float av0 = As[ty][kk],      av1 = As[ty + 16][kk];
            float bv0 = Bs[tx][kk],      bv1 = Bs[tx + 16][kk];
            a00 += av0 * bv0; a01 += av0 * bv1;
            a10 += av1 * bv0; a11 += av1 * bv1;
        }
        __syncthreads();
    }
    float* p = part + blockIdx.z * (Hs * Hs);
    p[(m0 + ty) * Hs + (n0 + tx)]           = a00;
    p[(m0 + ty) * Hs + (n0 + tx + 16)]      = a01;
    p[(m0 + ty + 16) * Hs + (n0 + tx)]      = a10;
    p[(m0 + ty + 16) * Hs + (n0 + tx + 16)] = a11;
}

__global__ void vkt_reduce_kernel(const float* __restrict__ part, float* __restrict__ vkt) {
    int idx = blockIdx.x * blockDim.x + threadIdx.x;
    if (idx < Hs * Hs) {
        float s = 0.f;
#pragma unroll
        for (int c = 0; c < 16; c++) s += part[c * (Hs * Hs) + idx];
        vkt[idx] = s;
    }
}

// ---------------- C = f @ C_prev + i @ vkT   (96x96), + split ----------------
__global__ void c_kernel(const float* __restrict__ f, const float* __restrict__ i_,
                         const float* __restrict__ C_prev, const float* __restrict__ vkt,
                         float* __restrict__ outC, unsigned short* __restrict__ Cs_u16) {
    __shared__ float fs[Hs], is[Hs];
    int b = blockIdx.x, n = threadIdx.x;
    fs[n] = f[b * Hs + n];
    is[n] = i_[b * Hs + n];
    __syncthreads();
    float acc = 0.f;
    for (int h = 0; h < Hs; h++)
        acc += fs[h] * C_prev[h * Hs + n] + is[h] * vkt[h * Hs + n];
    outC[b * Hs + n] = acc;
    __nv_bfloat16* Cs = (__nv_bfloat16*)Cs_u16;
    __nv_bfloat16 hi = __float2bfloat16(acc);
    Cs[b * 192 + n] = hi;
    Cs[b * 192 + 96 + n] = __float2bfloat16(acc - __bfloat162float(hi));
}

// ---------------- launch ----------------
extern "C" void kernel_launch(void* const* d_in, const int* in_sizes, int n_in,
                              void* d_out, int out_size) {
    const float* x      = (const float*)d_in[0];
    const float* h_prev = (const float*)d_in[1];
    const float* C_prev = (const float*)d_in[2];
    const float* n_prev = (const float*)d_in[3];
    const float* wix_w  = (const float*)d_in[4];
    const float* wix_b  = (const float*)d_in[5];
    const float* wfx_w  = (const float*)d_in[6];
    const float* wfx_b  = (const float*)d_in[7];
    const float* Wox_w  = (const float*)d_in[8];
    const float* Wox_b  = (const float*)d_in[9];
    const float* Wkqv_w = (const float*)d_in[10];
    const float* Wkqv_b = (const float*)d_in[11];

    float* out   = (float*)d_out;
    float* out_h = out;                       // [96, 9216]
    float* out_C = out + Bsz * H2;            // [96, 96]
    float* out_n = out_C + Bsz * Hs;          // [96, 9216]

    float *p_i, *p_f, *p_o, *p_kqv, *p_part, *p_vkt;
    int* p_denom;
    unsigned short *p_AT, *p_BT, *p_npT, *p_kT, *p_xs, *p_hps, *p_fis, *p_Cs;
    cudaGetSymbolAddress((void**)&p_i,     g_i);
    cudaGetSymbolAddress((void**)&p_f,     g_f);
    cudaGetSymbolAddress((void**)&p_o,     g_o);
    cudaGetSymbolAddress((void**)&p_kqv,   g_kqv);
    cudaGetSymbolAddress((void**)&p_part,  g_vkT_part);
    cudaGetSymbolAddress((void**)&p_vkt,   g_vkT);
    cudaGetSymbolAddress((void**)&p_denom, g_denom);
    cudaGetSymbolAddress((void**)&p_AT,    g_AT);
    cudaGetSymbolAddress((void**)&p_BT,    g_BT);
    cudaGetSymbolAddress((void**)&p_npT,   g_npT);
    cudaGetSymbolAddress((void**)&p_kT,    g_kT);
    cudaGetSymbolAddress((void**)&p_xs,    g_xs);
    cudaGetSymbolAddress((void**)&p_hps,   g_hps);
    cudaGetSymbolAddress((void**)&p_fis,   g_fis);
    cudaGetSymbolAddress((void**)&p_Cs,    g_Cs);

    const int DENOM_SMEM = 2 * 128 * SMN_LD * 2;                 // 102400
    const int PREB_SMEM  = (96 + 64) * 200 * 2;                  // 64000
    const int CONV_SMEM  = (96 * 72 + 64 * 72 + 64 * 192) * 2;   // 47616
    const int CONV1_SMEM = (96 * 72 + 64 * 72) * 2;              // 23040
    cudaFuncSetAttribute(denom_mma_kernel,
                         cudaFuncAttributeMaxDynamicSharedMemorySize, DENOM_SMEM);
    cudaFuncSetAttribute(hmma_preB<2>,
                         cudaFuncAttributeMaxDynamicSharedMemorySize, PREB_SMEM);
    cudaFuncSetAttribute(hmma_preB<3>,
                         cudaFuncAttributeMaxDynamicSharedMemorySize, PREB_SMEM);
    cudaFuncSetAttribute(hmma_convA<0, Ds>,
                         cudaFuncAttributeMaxDynamicSharedMemorySize, CONV_SMEM);
    cudaFuncSetAttribute(hmma_convA<1, Hs>,
                         cudaFuncAttributeMaxDynamicSharedMemorySize, CONV1_SMEM);

    // preamble: npT transpose-split | x/h splits + denom zero | gates (one launch)
    preamble_kernel<<<3096, 256>>>(x, h_prev, n_prev, wix_w, wix_b, wfx_w, wfx_b,
                                   p_xs, p_hps, p_npT, p_i, p_f, p_fis, p_denom);

    // kqv = x @ Wkqv^T + b (HMMA) + fused kT/qT transpose-splits
    hmma_convA<0, Ds><<<KQVN / 64, 256, CONV_SMEM>>>(p_xs, Wkqv_w, Wkqv_b, p_kqv, KQVN,
                                                     p_kT, p_BT);

    // o = sigmoid(h_prev @ Wox^T + b)
    hmma_convA<1, Hs><<<H2 / 64, 256, CONV1_SMEM>>>(p_hps, Wox_w, Wox_b, p_o, H2,
                                                    nullptr, nullptr);

    // n = f @ n_prev + i @ k  (HMMA) + fused AT transpose-split
    hmma_preB<2><<<H2 / 64, 256, PREB_SMEM>>>(p_fis, 384, p_npT, p_kT, 2,
                                              nullptr, nullptr, out_n, H2, p_AT);

    // vkT = v @ k^T
    vkt_part_kernel<<<dim3(3, 3, 16), 256>>>(p_kqv, p_part);
    vkt_reduce_kernel<<<36, 256>>>(p_part, p_vkt);

    // C = f @ C_prev + i @ vkT (+ split)
    c_kernel<<<Bsz, Hs>>>(p_f, p_i, C_prev, p_vkt, out_C, p_Cs);

    // denom = max_c |n^T q|  (A-resident, 6 B tiles per CTA)
    denom_mma_kernel<<<dim3(72, 12), 256, DENOM_SMEM>>>(p_AT, p_BT, p_denom);

    // h = o * (C @ q) / denom
    hmma_preB<3><<<H2 / 64, 256, PREB_SMEM>>>(p_Cs, 192, p_BT, nullptr, 1,
                                              p_o, p_denom, out_h, H2, nullptr);
}

// round 13
// speedup vs baseline: 1.1074x; 1.0379x over previous
#include <cuda_runtime.h>
#include <cuda_bf16.h>
#include <math.h>
#include <stdint.h>

#define Bsz  96
#define Hs   96
#define Ds   768
#define H2   9216
#define KQVN 27648

// ---------------- scratch (static device memory, no allocation) ----------------
__device__ float g_i[Bsz * Hs];
__device__ float g_f[Bsz * Hs];
__device__ float g_o[Bsz * H2];
__device__ float g_kqv[Bsz * KQVN];          // [96, 27648] : k | q | v (k pre-scaled by 1/96)
__device__ float g_vkT_part[16 * Hs * Hs];
__device__ float g_vkT[Hs * Hs];
__device__ int   g_denom[H2];                // float bits via atomicMax on non-neg floats
// pre-split bf16 operands
__device__ unsigned short g_AT[H2 * 192];    // n^T  [9216, 96hi|96lo]
__device__ unsigned short g_BT[H2 * 192];    // q^T
__device__ unsigned short g_npT[H2 * 192];   // n_prev^T
__device__ unsigned short g_kT[H2 * 192];    // k^T
__device__ unsigned short g_xs[Bsz * 1536];  // x split [96, 768hi|768lo]
__device__ unsigned short g_hps[Bsz * 192];  // h_prev split
__device__ unsigned short g_fis[Bsz * 384];  // [f hi|lo | i hi|lo]
__device__ unsigned short g_Cs[Bsz * 192];   // C split

// ---------------- helpers ----------------
__device__ __forceinline__ uint32_t smem_u32(const void* p) {
    uint32_t a;
    asm("{ .reg .u64 t; cvta.to.shared.u64 t, %1; cvt.u32.u64 %0, t; }" : "=r"(a) : "l"(p));
    return a;
}
#define LDSM_X4(r0, r1, r2, r3, addr) \
    asm volatile("ldmatrix.sync.aligned.m8n8.x4.shared.b16 {%0,%1,%2,%3}, [%4];" \
                 : "=r"(r0), "=r"(r1), "=r"(r2), "=r"(r3) : "r"(addr))
#define MMA16816(d, a, b0, b1) \
    asm volatile("mma.sync.aligned.m16n8k16.row.col.f32.bf16.bf16.f32 " \
                 "{%0,%1,%2,%3},{%4,%5,%6,%7},{%8,%9},{%0,%1,%2,%3};" \
                 : "+f"((d)[0]), "+f"((d)[1]), "+f"((d)[2]), "+f"((d)[3]) \
                 : "r"((a)[0]), "r"((a)[1]), "r"((a)[2]), "r"((a)[3]), "r"(b0), "r"(b1))

// ================= merged preamble: npT transpose-split | x/h splits | gates ======
__global__ __launch_bounds__(256)
void preamble_kernel(const float* __restrict__ x, const float* __restrict__ hp,
                     const float* __restrict__ n_prev,
                     const float* __restrict__ wix_w, const float* __restrict__ wix_b,
                     const float* __restrict__ wfx_w, const float* __restrict__ wfx_b,
                     unsigned short* __restrict__ xs_u16, unsigned short* __restrict__ hps_u16,
                     unsigned short* __restrict__ npT_u16,
                     float* __restrict__ gi, float* __restrict__ gf,
                     unsigned short* __restrict__ fis_u16,
                     int* __restrict__ denom) {
    __shared__ float t[32][68];
    int blk = blockIdx.x, tid = threadIdx.x;
    if (blk < 432) {
        __nv_bfloat16* dst = (__nv_bfloat16*)npT_u16;
        int bx = blk % 144, by = blk / 144;
        int r0 = bx * 64, j0 = by * 32;
#pragma unroll
        for (int it = 0; it < 2; it++) {
            int e = tid + it * 256;
            int jj = e >> 4, c4 = (e & 15) * 4;
            float4 v = *(const float4*)(n_prev + (size_t)(j0 + jj) * H2 + r0 + c4);
            *(float4*)&t[jj][c4] = v;
        }
        __syncthreads();
#pragma unroll
        for (int it = 0; it < 2; it++) {
            int e = tid + it * 256;
            int rr = e >> 3, q = e & 7;
            int isLo = q >> 2, jb = (q & 3) * 8;
            __nv_bfloat16 vals[8];
#pragma unroll
            for (int w = 0; w < 8; w++) {
                float f = t[jb + w][rr];
                __nv_bfloat16 hi = __float2bfloat16(f);
                vals[w] = isLo ? __float2bfloat16(f - __bfloat162float(hi)) : hi;
            }
            *(uint4*)(dst + (size_t)(r0 + rr) * 192 + isLo * 96 + j0 + jb) = *(uint4*)vals;
        }
    } else if (blk < 792) {
        int b2 = blk - 432;
        if (b2 < 288) {
            __nv_bfloat16* xs = (__nv_bfloat16*)xs_u16;
            int e = b2 * 256 + tid;
            int r = e / Ds, c = e % Ds;
            float v = x[e];
            __nv_bfloat16 hi = __float2bfloat16(v);
            xs[(size_t)r * 1536 + c] = hi;
            xs[(size_t)r * 1536 + Ds + c] = __float2bfloat16(v - __bfloat162float(hi));
        } else if (b2 < 324) {
            __nv_bfloat16* hs = (__nv_bfloat16*)hps_u16;
            int e = (b2 - 288) * 256 + tid;
            int r = e / Hs, c = e % Hs;
            float v = hp[e];
            __nv_bfloat16 hi = __float2bfloat16(v);
            hs[(size_t)r * 192 + c] = hi;
            hs[(size_t)r * 192 + Hs + c] = __float2bfloat16(v - __bfloat162float(hi));
        } else {
            int e = (b2 - 324) * 256 + tid;
            denom[e] = 0;
        }
    } else {
        int gw = (blk - 792) * 8 + (tid >> 5);
        int lane = tid & 31;
        int isI = gw < Bsz * Hs;
        int o = isI ? gw : gw - Bsz * Hs;
        int b = o / Hs, n = o % Hs;
        const float* a = isI ? x + (size_t)b * Ds : hp + (size_t)b * Hs;
        const float* w = isI ? wix_w + (size_t)n * Ds : wfx_w + (size_t)n * Hs;
        int K = isI ? Ds : Hs;
        float acc = 0.f;
        for (int k = lane; k < K; k += 32) acc += a[k] * w[k];
#pragma unroll
        for (int off = 16; off; off >>= 1) acc += __shfl_xor_sync(0xffffffffu, acc, off);
        if (lane == 0) {
            float v = expf(acc + (isI ? wix_b[n] : wfx_b[n]));
            (isI ? gi : gf)[o] = v;
            __nv_bfloat16* fis = (__nv_bfloat16*)fis_u16;
            __nv_bfloat16 hi = __float2bfloat16(v);
            int base = b * 384 + (isI ? 192 : 0) + n;
            fis[base] = hi;
            fis[base + 96] = __float2bfloat16(v - __bfloat162float(hi));
        }
    }
}

// ======== UBER convA: kqv (blocks 0..431) + o (blocks 432..575) in one launch ====
__global__ __launch_bounds__(256, 3)
void hmma_conv_uber(const unsigned short* __restrict__ xs_u16,
                    const unsigned short* __restrict__ hps_u16,
                    const float* __restrict__ Wkqv, const float* __restrict__ Wkqv_b,
                    const float* __restrict__ Wox,  const float* __restrict__ Wox_b,
                    float* __restrict__ kqv_out, float* __restrict__ o_out,
                    unsigned short* __restrict__ kT_u16,
                    unsigned short* __restrict__ qT_u16) {
    const bool isKqv = blockIdx.x < 432;
    const __nv_bfloat16* Asp = (const __nv_bfloat16*)(isKqv ? xs_u16 : hps_u16);
    const int KTOT = isKqv ? Ds : Hs;
    const float* Bm   = isKqv ? Wkqv : Wox;
    const float* bias = isKqv ? Wkqv_b : Wox_b;
    float* out = isKqv ? kqv_out : o_out;
    const int ldo = isKqv ? KQVN : H2;
    const int n0 = (isKqv ? blockIdx.x : (blockIdx.x - 432)) * 64;
    const int NC = KTOT / 32;

    extern __shared__ __nv_bfloat16 dyn[];
    __nv_bfloat16* sAr = dyn;                        // [96][72]
    __nv_bfloat16* sBr = dyn + 96 * 72;              // [64][72]
    __nv_bfloat16* sT  = dyn + 96 * 72 + 64 * 72;    // [64][192] (kqv only)
    int tid = threadIdx.x, warp = tid >> 5, lane = tid & 31;
    int wm = warp & 1, wn = warp >> 1;
    float acc[3][2][4] = {};

    uint4 aPre[3];
    float4 bPre[2];

#pragma unroll 1
    for (int c = 0; c < NC; c++) {
        if (c == 0) {
#pragma unroll
            for (int t = 0; t < 3; t++) {
                int e = tid + t * 256;
                int r = e >> 3, col = (e & 7) * 8;
                int sc = (col < 32) ? col : (KTOT + col - 32);
                aPre[t] = *(const uint4*)(Asp + (size_t)r * (2 * KTOT) + sc);
            }
#pragma unroll
            for (int t = 0; t < 2; t++) {
                int e = tid + t * 256;
                int r = e >> 3, g = e & 7;
                bPre[t] = *(const float4*)(Bm + (size_t)(n0 + r) * KTOT + g * 4);
            }
        }
        __syncthreads();
#pragma unroll
        for (int t = 0; t < 3; t++) {
            int e = tid + t * 256;
            int r = e >> 3, col = (e & 7) * 8;
            *(uint4*)&sAr[r * 72 + col] = aPre[t];
        }
#pragma unroll
        for (int t = 0; t < 2; t++) {
            int e = tid + t * 256;
            int r = e >> 3, g = e & 7;
            float vv[4] = {bPre[t].x, bPre[t].y, bPre[t].z, bPre[t].w};
#pragma unroll
            for (int j = 0; j < 4; j++) {
                __nv_bfloat16 hi = __float2bfloat16(vv[j]);
                sBr[r * 72 + g * 4 + j] = hi;
                sBr[r * 72 + 32 + g * 4 + j] = __float2bfloat16(vv[j] - __bfloat162float(hi));
            }
        }
        // issue c+1 loads before sync (regs+global only)
        if (c + 1 < NC) {
            int k0 = (c + 1) * 32;
#pragma unroll
            for (int t = 0; t < 3; t++) {
                int e = tid + t * 256;
                int r = e >> 3, col = (e & 7) * 8;
                int sc = (col < 32) ? (k0 + col) : (KTOT + k0 + col - 32);
                aPre[t] = *(const uint4*)(Asp + (size_t)r * (2 * KTOT) + sc);
            }
#pragma unroll
            for (int t = 0; t < 2; t++) {
                int e = tid + t * 256;
                int r = e >> 3, g = e & 7;
                bPre[t] = *(const float4*)(Bm + (size_t)(n0 + r) * KTOT + k0 + g * 4);
            }
        }
        __syncthreads();
        uint32_t aBase = smem_u32(sAr);
        uint32_t bBase = smem_u32(sBr);
        int aRow = wm * 48 + (lane & 15);
        int aCol = (lane >> 4) << 3;
        int bRow = wn * 16 + (lane & 7) + ((lane >> 4) << 3);
        int bCol = ((lane >> 3) & 1) << 3;
#pragma unroll
        for (int ks = 0; ks < 2; ks++) {
            int ka = ks * 16 + aCol, kb = ks * 16 + bCol;
            uint32_t af[3][4], bh[4], bl[4];
#pragma unroll
            for (int mi = 0; mi < 3; mi++) {
                uint32_t addr = aBase + (uint32_t)(((aRow + mi * 16) * 72 + ka) * 2);
                LDSM_X4(af[mi][0], af[mi][1], af[mi][2], af[mi][3], addr);
            }
            {
                uint32_t addr = bBase + (uint32_t)((bRow * 72 + kb) * 2);
                LDSM_X4(bh[0], bh[1], bh[2], bh[3], addr);
                addr = bBase + (uint32_t)((bRow * 72 + kb + 32) * 2);
                LDSM_X4(bl[0], bl[1], bl[2], bl[3], addr);
            }
#pragma unroll
            for (int mi = 0; mi < 3; mi++)
#pragma unroll
                for (int nj = 0; nj < 2; nj++) {
                    MMA16816(acc[mi][nj], af[mi], bh[nj * 2], bh[nj * 2 + 1]);
                    MMA16816(acc[mi][nj], af[mi], bl[nj * 2], bl[nj * 2 + 1]);
                }
        }
#pragma unroll
        for (int ks = 0; ks < 2; ks++) {
            int ka = 32 + ks * 16 + aCol, kb = ks * 16 + bCol;
            uint32_t af[3][4], bh[4];
#pragma unroll
            for (int mi = 0; mi < 3; mi++) {
                uint32_t addr = aBase + (uint32_t)(((aRow + mi * 16) * 72 + ka) * 2);
                LDSM_X4(af[mi][0], af[mi][1], af[mi][2], af[mi][3], addr);
            }
            {
                uint32_t addr = bBase + (uint32_t)((bRow * 72 + kb) * 2);
                LDSM_X4(bh[0], bh[1], bh[2], bh[3], addr);
            }
#pragma unroll
            for (int mi = 0; mi < 3; mi++)
#pragma unroll
                for (int nj = 0; nj < 2; nj++)
                    MMA16816(acc[mi][nj], af[mi], bh[nj * 2], bh[nj * 2 + 1]);
        }
    }
    const bool doT = isKqv && (n0 < 2 * H2);
#pragma unroll
    for (int mi = 0; mi < 3; mi++)
#pragma unroll
        for (int nj = 0; nj < 2; nj++)
#pragma unroll
            for (int r = 0; r < 4; r++) {
                int m = wm * 48 + mi * 16 + (lane >> 2) + ((r >> 1) * 8);
                int gl = wn * 16 + nj * 8 + (lane & 3) * 2 + (r & 1);
                int gn = n0 + gl;
                float v = acc[mi][nj][r] + bias[gn];
                if (isKqv) { if (gn < H2) v *= (1.0f / 96.0f); }
                else       v = 1.0f / (1.0f + expf(-v));
                out[(size_t)m * ldo + gn] = v;
                if (doT) {
                    __nv_bfloat16 hi = __float2bfloat16(v);
                    sT[gl * 192 + m] = hi;
                    sT[gl * 192 + 96 + m] = __float2bfloat16(v - __bfloat162float(hi));
                }
            }
    if (doT) {
        __syncthreads();
        __nv_bfloat16* dstT = (__nv_bfloat16*)((n0 < H2) ? kT_u16 : qT_u16);
        int cb = (n0 < H2) ? n0 : (n0 - H2);
        for (int e = tid; e < 64 * 24; e += 256) {
            int row = e / 24, g = e % 24;
            *(uint4*)(dstT + (size_t)(cb + row) * 192 + g * 8) = *(uint4*)(sT + row * 192 + g * 8);
        }
    }
}

// ======== Variant B: HMMA NT GEMM, N-tile 32, pre-split bf16 B [N, 192] ========
// EPI 2: n (+ fused AT transpose-split), EPI 3: h = o * acc / denom
template <int EPI>
__global__ __launch_bounds__(256, 3)
void hmma_preB(const unsigned short* __restrict__ Asp_u16, int lda,
               const unsigned short* __restrict__ B1_u16,
               const unsigned short* __restrict__ B2_u16,
               int nseg,
               const float* __restrict__ omat,
               const int* __restrict__ denomBits,
               float* __restrict__ out, int ldo,
               unsigned short* __restrict__ AT_u16) {
    const __nv_bfloat16* Asp = (const __nv_bfloat16*)Asp_u16;
    extern __shared__ __nv_bfloat16 dsm[];
    __nv_bfloat16* sA = dsm;             // [96][200]
    __nv_bfloat16* sB = dsm + 96 * 200;  // [32][200]
    int tid = threadIdx.x, warp = tid >> 5, lane = tid & 31;
    int n0 = blockIdx.x * 32;
    int wm = warp & 1, wn = warp >> 1;   // warp: M 48 x N 8
    float acc[3][4] = {};

#pragma unroll 1
    for (int s = 0; s < nseg; s++) {
        const __nv_bfloat16* Bseg =
            (s == 0) ? (const __nv_bfloat16*)B1_u16 : (const __nv_bfloat16*)B2_u16;
        __syncthreads();
        for (int e = tid; e < 96 * 24; e += 256) {
            int r = e / 24, g = e % 24;
            *(uint4*)(sA + r * 200 + g * 8) =
                *(const uint4*)(Asp + (size_t)r * lda + s * 192 + g * 8);
        }
        for (int e = tid; e < 32 * 24; e += 256) {
            int r = e / 24, g = e % 24;
            *(uint4*)(sB + r * 200 + g * 8) =
                *(const uint4*)(Bseg + (size_t)(n0 + r) * 192 + g * 8);
        }
        __syncthreads();
        uint32_t aBase = smem_u32(sA), bBase = smem_u32(sB);
        int aRow = wm * 48 + (lane & 15), aCol = (lane >> 4) << 3;
        int bRowOff = (wn * 8 + (lane & 7)) * 200 + ((lane >> 3) << 3);
        // combined: per k32 block, one x4 B load covers two k16 steps
#pragma unroll
        for (int ks2 = 0; ks2 < 3; ks2++) {
            uint32_t bh[4], bl[4];
            {
                uint32_t addr = bBase + (uint32_t)((bRowOff + ks2 * 32) * 2);
                LDSM_X4(bh[0], bh[1], bh[2], bh[3], addr);
                addr = bBase + (uint32_t)((bRowOff + 96 + ks2 * 32) * 2);
                LDSM_X4(bl[0], bl[1], bl[2], bl[3], addr);
            }
#pragma unroll
            for (int sub = 0; sub < 2; sub++) {
                int ka = ks2 * 32 + sub * 16 + aCol;
                uint32_t afh[3][4], afl[3][4];
#pragma unroll
                for (int mi = 0; mi < 3; mi++) {
                    uint32_t addr = aBase + (uint32_t)(((aRow + mi * 16) * 200 + ka) * 2);
                    LDSM_X4(afh[mi][0], afh[mi][1], afh[mi][2], afh[mi][3], addr);
                    addr = aBase + (uint32_t)(((aRow + mi * 16) * 200 + 96 + ka) * 2);
                    LDSM_X4(afl[mi][0], afl[mi][1], afl[mi][2], afl[mi][3], addr);
                }
#pragma unroll
                for (int mi = 0; mi < 3; mi++) {
                    MMA16816(acc[mi], afh[mi], bh[sub * 2], bh[sub * 2 + 1]);
                    MMA16816(acc[mi], afh[mi], bl[sub * 2], bl[sub * 2 + 1]);
                    MMA16816(acc[mi], afl[mi], bh[sub * 2], bh[sub * 2 + 1]);
                }
            }
        }
    }
    if (EPI == 2) __syncthreads();   // before reusing sA as staging
#pragma unroll
    for (int mi = 0; mi < 3; mi++)
#pragma unroll
        for (int r = 0; r < 4; r++) {
            int m = wm * 48 + mi * 16 + (lane >> 2) + ((r >> 1) * 8);
            int gl = wn * 8 + (lane & 3) * 2 + (r & 1);
            int gn = n0 + gl;
            float v = acc[mi][r];
            if (EPI == 3)
                v = omat[(size_t)m * H2 + gn] * v / __int_as_float(denomBits[gn]);
            out[(size_t)m * ldo + gn] = v;
            if (EPI == 2) {
                __nv_bfloat16 hi = __float2bfloat16(v);
                sA[gl * 192 + m] = hi;
                sA[gl * 192 + 96 + m] = __float2bfloat16(v - __bfloat162float(hi));
            }
        }
    if (EPI == 2) {
        __syncthreads();
        __nv_bfloat16* AT = (__nv_bfloat16*)AT_u16;
        for (int e = tid; e < 32 * 24; e += 256) {
            int row = e / 24, g = e % 24;
            *(uint4*)(AT + (size_t)(n0 + row) * 192 + g * 8) = *(uint4*)(sA + row * 192 + g * 8);
        }
    }
}

// ================= HMMA denom: A-resident, 6 B tiles per CTA =================
#define SMN_LD 200

__global__ __launch_bounds__(256, 2)
void denom_mma_kernel(const unsigned short* __restrict__ AT,
                      const unsigned short* __restrict__ BT,
                      int* __restrict__ denom) {
    extern __shared__ __align__(16) unsigned short sm[];
    unsigned short* sA = sm;
    unsigned short* sB = sm + 128 * SMN_LD;
    int tid = threadIdx.x;
    int r0 = blockIdx.x * 128;
    int cbase = blockIdx.y * 768;

    for (int e = tid; e < 128 * 24; e += 256) {
        int row = e / 24, c8 = (e % 24) * 8;
        *(float4*)(sA + row * SMN_LD + c8) = *(const float4*)(AT + (size_t)(r0 + row) * 192 + c8);
    }

    int warp = tid >> 5, lane = tid & 31;
    int wm = warp & 1, wn = warp >> 1;
    uint32_t aBase = smem_u32(sA);
    uint32_t bBase = smem_u32(sB);

    int aRow = wm * 64 + (lane & 15);
    int aColL = (lane >> 4) << 3;
    int bRow = wn * 32 + (lane & 7) + ((lane >> 4) << 3);
    int bColL = ((lane >> 3) & 1) << 3;

    float mx[4][2];
#pragma unroll
    for (int mi = 0; mi < 4; mi++) { mx[mi][0] = 0.f; mx[mi][1] = 0.f; }

#pragma unroll 1
    for (int t = 0; t < 6; t++) {
        __syncthreads();
        for (int e = tid; e < 128 * 24; e += 256) {
            int row = e / 24, c8 = (e % 24) * 8;
            *(float4*)(sB + row * SMN_LD + c8) =
                *(const float4*)(BT + (size_t)(cbase + t * 128 + row) * 192 + c8);
        }
        __syncthreads();

        float acc[4][4][4];
#pragma unroll
        for (int mi = 0; mi < 4; mi++)
#pragma unroll
            for (int nj = 0; nj < 4; nj++)
#pragma unroll
                for (int r = 0; r < 4; r++) acc[mi][nj][r] = 0.f;

#pragma unroll 1
        for (int ks = 0; ks < 6; ks++) {
            int ka = ks * 16 + aColL;
            int kb = ks * 16 + bColL;
            uint32_t af[4][4], bh[2][4], bl[2][4];
#pragma unroll
            for (int mi = 0; mi < 4; mi++) {
                uint32_t addr = aBase + (uint32_t)(((aRow + mi * 16) * SMN_LD + ka) * 2);
                LDSM_X4(af[mi][0], af[mi][1], af[mi][2], af[mi][3], addr);
            }
#pragma unroll
            for (int nj2 = 0; nj2 < 2; nj2++) {
                uint32_t addr = bBase + (uint32_t)(((bRow + nj2 * 16) * SMN_LD + kb) * 2);
                LDSM_X4(bh[nj2][0], bh[nj2][1], bh[nj2][2], bh[nj2][3], addr);
                addr = bBase + (uint32_t)(((bRow + nj2 * 16) * SMN_LD + kb + 96) * 2);
                LDSM_X4(bl[nj2][0], bl[nj2][1], bl[nj2][2], bl[nj2][3], addr);
            }
#pragma unroll
            for (int mi = 0; mi < 4; mi++)
#pragma unroll
                for (int nj = 0; nj < 4; nj++) {
                    MMA16816(acc[mi][nj], af[mi], bh[nj >> 1][(nj & 1) * 2],
                             bh[nj >> 1][(nj & 1) * 2 + 1]);
                    MMA16816(acc[mi][nj], af[mi], bl[nj >> 1][(nj & 1) * 2],
                             bl[nj >> 1][(nj & 1) * 2 + 1]);
                }
        }
#pragma unroll 1
        for (int ks = 0; ks < 6; ks++) {
            int ka = 96 + ks * 16 + aColL;
            int kb = ks * 16 + bColL;
            uint32_t af[4][4], bh[2][4];
#pragma unroll
            for (int mi = 0; mi < 4; mi++) {
                uint32_t addr = aBase + (uint32_t)(((aRow + mi * 16) * SMN_LD + ka) * 2);
                LDSM_X4(af[mi][0], af[mi][1], af[mi][2], af[mi][3], addr);
            }
#pragma unroll
            for (int nj2 = 0; nj2 < 2; nj2++) {
                uint32_t addr = bBase + (uint32_t)(((bRow + nj2 * 16) * SMN_LD + kb) * 2);
                LDSM_X4(bh[nj2][0], bh[nj2][1], bh[nj2][2], bh[nj2][3], addr);
            }
#pragma unroll
            for (int mi = 0; mi < 4; mi++)
#pragma unroll
                for (int nj = 0; nj < 4; nj++)
                    MMA16816(acc[mi][nj], af[mi], bh[nj >> 1][(nj & 1) * 2],
                             bh[nj >> 1][(nj & 1) * 2 + 1]);
        }

#pragma unroll
        for (int mi = 0; mi < 4; mi++) {
#pragma unroll
            for (int nj = 0; nj < 4; nj++) {
                mx[mi][0] = fmaxf(mx[mi][0], fmaxf(fabsf(acc[mi][nj][0]), fabsf(acc[mi][nj][1])));
                mx[mi][1] = fmaxf(mx[mi][1], fmaxf(fabsf(acc[mi][nj][2]), fabsf(acc[mi][nj][3])));
            }
        }
    }

#pragma unroll
    for (int mi = 0; mi < 4; mi++) {
        float m0 = mx[mi][0], m1 = mx[mi][1];
        m0 = fmaxf(m0, __shfl_xor_sync(0xffffffffu, m0, 1));
        m0 = fmaxf(m0, __shfl_xor_sync(0xffffffffu, m0, 2));
        m1 = fmaxf(m1, __shfl_xor_sync(0xffffffffu, m1, 1));
        m1 = fmaxf(m1, __shfl_xor_sync(0xffffffffu, m1, 2));
        if ((lane & 3) == 0) {
            int rbase = r0 + wm * 64 + mi * 16 + (lane >> 2);
            atomicMax(&denom[rbase], __float_as_int(m0));
            atomicMax(&denom[rbase + 8], __float_as_int(m1));
        }
    }
}

// ---------------- v @ k^T : deterministic split-K (16 chunks of 576) ----------------
__global__ __launch_bounds__(256)
void vkt_part_kernel(const float* __restrict__ kqv, float* __restrict__ part) {
    const float* V  = kqv + 2 * H2;
    const float* Km = kqv;
    __shared__ float As[32][17];
    __shared__ float Bs[32][17];
    int tid = threadIdx.x, tx = tid & 15, ty = tid >> 4;
    int m0 = blockIdx.x * 32, n0 = blockIdx.y * 32;
    int kbase = blockIdx.z * 576;
    float a00 = 0, a01 = 0, a10 = 0, a11 = 0;
    for (int k0 = 0; k0 < 576; k0 += 16) {
        for (int e = tid; e < 32 * 16; e += 256) {
            int m = e >> 4, k = e & 15;
            As[m][k] = V[(size_t)(m0 + m) * KQVN + kbase + k0 + k];
            Bs[m][k] = Km[(size_t)(n0 + m) * KQVN + kbase + k0 + k];
        }
        __syncthreads();
#pragma unroll
        for (int kk = 0; kk < 16; kk++) {
            float av0 = As[ty][kk],      av1 = As[ty + 16][kk];
            float bv0 = Bs[tx][kk],      bv1 = Bs[tx + 16][kk];
            a00 += av0 * bv0; a01 += av0 * bv1;
            a10 += av1 * bv0; a11 += av1 * bv1;
        }
        __syncthreads();
    }
    float* p = part + blockIdx.z * (Hs * Hs);
    p[(m0 + ty) * Hs + (n0 + tx)]           = a00;
    p[(m0 + ty) * Hs + (n0 + tx + 16)]      = a01;
    p[(m0 + ty + 16) * Hs + (n0 + tx)]      = a10;
    p[(m0 + ty + 16) * Hs + (n0 + tx + 16)] = a11;
}

__global__ void vkt_reduce_kernel(const float* __restrict__ part, float* __restrict__ vkt) {
    int idx = blockIdx.x * blockDim.x + threadIdx.x;
    if (idx < Hs * Hs) {
        float s = 0.f;
#pragma unroll
        for (int c = 0; c < 16; c++) s += part[c * (Hs * Hs) + idx];
        vkt[idx] = s;
    }
}

// ---------------- C = f @ C_prev + i @ vkT   (96x96), + split ----------------
__global__ void c_kernel(const float* __restrict__ f, const float* __restrict__ i_,
                         const float* __restrict__ C_prev, const float* __restrict__ vkt,
                         float* __restrict__ outC, unsigned short* __restrict__ Cs_u16) {
    __shared__ float fs[Hs], is[Hs];
    int b = blockIdx.x, n = threadIdx.x;
    fs[n] = f[b * Hs + n];
    is[n] = i_[b * Hs + n];
    __syncthreads();
    float acc = 0.f;
    for (int h = 0; h < Hs; h++)
        acc += fs[h] * C_prev[h * Hs + n] + is[h] * vkt[h * Hs + n];
    outC[b * Hs + n] = acc;
    __nv_bfloat16* Cs = (__nv_bfloat16*)Cs_u16;
    __nv_bfloat16 hi = __float2bfloat16(acc);
    Cs[b * 192 + n] = hi;
    Cs[b * 192 + 96 + n] = __float2bfloat16(acc - __bfloat162float(hi));
}

// ---------------- launch ----------------
extern "C" void kernel_launch(void* const* d_in, const int* in_sizes, int n_in,
                              void* d_out, int out_size) {
    const float* x      = (const float*)d_in[0];
    const float* h_prev = (const float*)d_in[1];
    const float* C_prev = (const float*)d_in[2];
    const float* n_prev = (const float*)d_in[3];
    const float* wix_w  = (const float*)d_in[4];
    const float* wix_b  = (const float*)d_in[5];
    const float* wfx_w  = (const float*)d_in[6];
    const float* wfx_b  = (const float*)d_in[7];
    const float* Wox_w  = (const float*)d_in[8];
    const float* Wox_b  = (const float*)d_in[9];
    const float* Wkqv_w = (const float*)d_in[10];
    const float* Wkqv_b = (const float*)d_in[11];

    float* out   = (float*)d_out;
    float* out_h = out;                       // [96, 9216]
    float* out_C = out + Bsz * H2;            // [96, 96]
    float* out_n = out_C + Bsz * Hs;          // [96, 9216]

    float *p_i, *p_f, *p_o, *p_kqv, *p_part, *p_vkt;
    int* p_denom;
    unsigned short *p_AT, *p_BT, *p_npT, *p_kT, *p_xs, *p_hps, *p_fis, *p_Cs;
    cudaGetSymbolAddress((void**)&p_i,     g_i);
    cudaGetSymbolAddress((void**)&p_f,     g_f);
    cudaGetSymbolAddress((void**)&p_o,     g_o);
    cudaGetSymbolAddress((void**)&p_kqv,   g_kqv);
    cudaGetSymbolAddress((void**)&p_part,  g_vkT_part);
    cudaGetSymbolAddress((void**)&p_vkt,   g_vkT);
    cudaGetSymbolAddress((void**)&p_denom, g_denom);
    cudaGetSymbolAddress((void**)&p_AT,    g_AT);
    cudaGetSymbolAddress((void**)&p_BT,    g_BT);
    cudaGetSymbolAddress((void**)&p_npT,   g_npT);
    cudaGetSymbolAddress((void**)&p_kT,    g_kT);
    cudaGetSymbolAddress((void**)&p_xs,    g_xs);
    cudaGetSymbolAddress((void**)&p_hps,   g_hps);
    cudaGetSymbolAddress((void**)&p_fis,   g_fis);
    cudaGetSymbolAddress((void**)&p_Cs,    g_Cs);

    const int DENOM_SMEM = 2 * 128 * SMN_LD * 2;                 // 102400
    const int PREB_SMEM  = (96 + 32) * 200 * 2;                  // 51200
    const int CONV_SMEM  = (96 * 72 + 64 * 72 + 64 * 192) * 2;   // 47616
    cudaFuncSetAttribute(denom_mma_kernel,
                         cudaFuncAttributeMaxDynamicSharedMemorySize, DENOM_SMEM);
    cudaFuncSetAttribute(hmma_preB<2>,
                         cudaFuncAttributeMaxDynamicSharedMemorySize, PREB_SMEM);
    cudaFuncSetAttribute(hmma_preB<3>,
                         cudaFuncAttributeMaxDynamicSharedMemorySize, PREB_SMEM);
    cudaFuncSetAttribute(hmma_conv_uber,
                         cudaFuncAttributeMaxDynamicSharedMemorySize, CONV_SMEM);

    // preamble: npT transpose-split | x/h splits + denom zero | gates (one launch)
    preamble_kernel<<<3096, 256>>>(x, h_prev, n_prev, wix_w, wix_b, wfx_w, wfx_b,
                                   p_xs, p_hps, p_npT, p_i, p_f, p_fis, p_denom);

    // kqv (+ fused kT/qT splits) and o in ONE launch
    hmma_conv_uber<<<576, 256, CONV_SMEM>>>(p_xs, p_hps, Wkqv_w, Wkqv_b, Wox_w, Wox_b,
                                            p_kqv, p_o, p_kT, p_BT);

    // n = f @ n_prev + i @ k  (HMMA, N32 tiles) + fused AT transpose-split
    hmma_preB<2><<<H2 / 32, 256, PREB_SMEM>>>(p_fis, 384, p_npT, p_kT, 2,
                                              nullptr, nullptr, out_n, H2, p_AT);

    // vkT = v @ k^T
    vkt_part_kernel<<<dim3(3, 3, 16), 256>>>(p_kqv, p_part);
    vkt_reduce_kernel<<<36, 256>>>(p_part, p_vkt);

    // C = f @ C_prev + i @ vkT (+ split)
    c_kernel<<<Bsz, Hs>>>(p_f, p_i, C_prev, p_vkt, out_C, p_Cs);

    // denom = max_c |n^T q|  (A-resident, 6 B tiles per CTA)
    denom_mma_kernel<<<dim3(72, 12), 256, DENOM_SMEM>>>(p_AT, p_BT, p_denom);

    // h = o * (C @ q) / denom  (N32 tiles)
    hmma_preB<3><<<H2 / 32, 256, PREB_SMEM>>>(p_Cs, 192, p_BT, nullptr, 1,
                                              p_o, p_denom, out_h, H2, nullptr);
}

// round 14
// speedup vs baseline: 1.1980x; 1.0819x over previous
#include <cuda_runtime.h>
#include <cuda_bf16.h>
#include <math.h>
#include <stdint.h>

#define Bsz  96
#define Hs   96
#define Ds   768
#define H2   9216
#define KQVN 27648
#define VKT_SPLIT 48
#define VKT_CHUNK 192

// ---------------- scratch (static device memory, no allocation) ----------------
__device__ float g_i[Bsz * Hs];
__device__ float g_f[Bsz * Hs];
__device__ float g_o[Bsz * H2];
__device__ float g_kqv[Bsz * KQVN];          // [96, 27648] : k | q | v (k pre-scaled by 1/96)
__device__ float g_vkT_part[VKT_SPLIT * Hs * Hs];
__device__ float g_vkT[Hs * Hs];
__device__ int   g_denom[H2];                // float bits via atomicMax on non-neg floats
// pre-split bf16 operands
__device__ unsigned short g_AT[H2 * 192];    // n^T  [9216, 96hi|96lo]
__device__ unsigned short g_BT[H2 * 192];    // q^T
__device__ unsigned short g_npT[H2 * 192];   // n_prev^T
__device__ unsigned short g_kT[H2 * 192];    // k^T
__device__ unsigned short g_xs[Bsz * 1536];  // x split [96, 768hi|768lo]
__device__ unsigned short g_hps[Bsz * 192];  // h_prev split
__device__ unsigned short g_fis[Bsz * 384];  // [f hi|lo | i hi|lo]
__device__ unsigned short g_Cs[Bsz * 192];   // C split

// ---------------- helpers ----------------
__device__ __forceinline__ uint32_t smem_u32(const void* p) {
    uint32_t a;
    asm("{ .reg .u64 t; cvta.to.shared.u64 t, %1; cvt.u32.u64 %0, t; }" : "=r"(a) : "l"(p));
    return a;
}
#define LDSM_X4(r0, r1, r2, r3, addr) \
    asm volatile("ldmatrix.sync.aligned.m8n8.x4.shared.b16 {%0,%1,%2,%3}, [%4];" \
                 : "=r"(r0), "=r"(r1), "=r"(r2), "=r"(r3) : "r"(addr))
#define MMA16816(d, a, b0, b1) \
    asm volatile("mma.sync.aligned.m16n8k16.row.col.f32.bf16.bf16.f32 " \
                 "{%0,%1,%2,%3},{%4,%5,%6,%7},{%8,%9},{%0,%1,%2,%3};" \
                 : "+f"((d)[0]), "+f"((d)[1]), "+f"((d)[2]), "+f"((d)[3]) \
                 : "r"((a)[0]), "r"((a)[1]), "r"((a)[2]), "r"((a)[3]), "r"(b0), "r"(b1))

// ================= merged preamble: npT transpose-split | x/h splits | gates ======
__global__ __launch_bounds__(256)
void preamble_kernel(const float* __restrict__ x, const float* __restrict__ hp,
                     const float* __restrict__ n_prev,
                     const float* __restrict__ wix_w, const float* __restrict__ wix_b,
                     const float* __restrict__ wfx_w, const float* __restrict__ wfx_b,
                     unsigned short* __restrict__ xs_u16, unsigned short* __restrict__ hps_u16,
                     unsigned short* __restrict__ npT_u16,
                     float* __restrict__ gi, float* __restrict__ gf,
                     unsigned short* __restrict__ fis_u16,
                     int* __restrict__ denom) {
    __shared__ float t[32][68];
    int blk = blockIdx.x, tid = threadIdx.x;
    if (blk < 432) {
        __nv_bfloat16* dst = (__nv_bfloat16*)npT_u16;
        int bx = blk % 144, by = blk / 144;
        int r0 = bx * 64, j0 = by * 32;
#pragma unroll
        for (int it = 0; it < 2; it++) {
            int e = tid + it * 256;
            int jj = e >> 4, c4 = (e & 15) * 4;
            float4 v = *(const float4*)(n_prev + (size_t)(j0 + jj) * H2 + r0 + c4);
            *(float4*)&t[jj][c4] = v;
        }
        __syncthreads();
#pragma unroll
        for (int it = 0; it < 2; it++) {
            int e = tid + it * 256;
            int rr = e >> 3, q = e & 7;
            int isLo = q >> 2, jb = (q & 3) * 8;
            __nv_bfloat16 vals[8];
#pragma unroll
            for (int w = 0; w < 8; w++) {
                float f = t[jb + w][rr];
                __nv_bfloat16 hi = __float2bfloat16(f);
                vals[w] = isLo ? __float2bfloat16(f - __bfloat162float(hi)) : hi;
            }
            *(uint4*)(dst + (size_t)(r0 + rr) * 192 + isLo * 96 + j0 + jb) = *(uint4*)vals;
        }
    } else if (blk < 792) {
        int b2 = blk - 432;
        if (b2 < 288) {
            __nv_bfloat16* xs = (__nv_bfloat16*)xs_u16;
            int e = b2 * 256 + tid;
            int r = e / Ds, c = e % Ds;
            float v = x[e];
            __nv_bfloat16 hi = __float2bfloat16(v);
            xs[(size_t)r * 1536 + c] = hi;
            xs[(size_t)r * 1536 + Ds + c] = __float2bfloat16(v - __bfloat162float(hi));
        } else if (b2 < 324) {
            __nv_bfloat16* hs = (__nv_bfloat16*)hps_u16;
            int e = (b2 - 288) * 256 + tid;
            int r = e / Hs, c = e % Hs;
            float v = hp[e];
            __nv_bfloat16 hi = __float2bfloat16(v);
            hs[(size_t)r * 192 + c] = hi;
            hs[(size_t)r * 192 + Hs + c] = __float2bfloat16(v - __bfloat162float(hi));
        } else {
            int e = (b2 - 324) * 256 + tid;
            denom[e] = 0;
        }
    } else {
        int gw = (blk - 792) * 8 + (tid >> 5);
        int lane = tid & 31;
        int isI = gw < Bsz * Hs;
        int o = isI ? gw : gw - Bsz * Hs;
        int b = o / Hs, n = o % Hs;
        const float* a = isI ? x + (size_t)b * Ds : hp + (size_t)b * Hs;
        const float* w = isI ? wix_w + (size_t)n * Ds : wfx_w + (size_t)n * Hs;
        int K = isI ? Ds : Hs;
        float acc = 0.f;
        for (int k = lane; k < K; k += 32) acc += a[k] * w[k];
#pragma unroll
        for (int off = 16; off; off >>= 1) acc += __shfl_xor_sync(0xffffffffu, acc, off);
        if (lane == 0) {
            float v = expf(acc + (isI ? wix_b[n] : wfx_b[n]));
            (isI ? gi : gf)[o] = v;
            __nv_bfloat16* fis = (__nv_bfloat16*)fis_u16;
            __nv_bfloat16 hi = __float2bfloat16(v);
            int base = b * 384 + (isI ? 192 : 0) + n;
            fis[base] = hi;
            fis[base + 96] = __float2bfloat16(v - __bfloat162float(hi));
        }
    }
}

// ======== UBER convA: kqv (blocks 0..431) + o (blocks 432..575) in one launch ====
__global__ __launch_bounds__(256, 3)
void hmma_conv_uber(const unsigned short* __restrict__ xs_u16,
                    const unsigned short* __restrict__ hps_u16,
                    const float* __restrict__ Wkqv, const float* __restrict__ Wkqv_b,
                    const float* __restrict__ Wox,  const float* __restrict__ Wox_b,
                    float* __restrict__ kqv_out, float* __restrict__ o_out,
                    unsigned short* __restrict__ kT_u16,
                    unsigned short* __restrict__ qT_u16) {
    const bool isKqv = blockIdx.x < 432;
    const __nv_bfloat16* Asp = (const __nv_bfloat16*)(isKqv ? xs_u16 : hps_u16);
    const int KTOT = isKqv ? Ds : Hs;
    const float* Bm   = isKqv ? Wkqv : Wox;
    const float* bias = isKqv ? Wkqv_b : Wox_b;
    float* out = isKqv ? kqv_out : o_out;
    const int ldo = isKqv ? KQVN : H2;
    const int n0 = (isKqv ? blockIdx.x : (blockIdx.x - 432)) * 64;
    const int NC = KTOT / 32;

    extern __shared__ __nv_bfloat16 dyn[];
    __nv_bfloat16* sAr = dyn;                        // [96][72]
    __nv_bfloat16* sBr = dyn + 96 * 72;              // [64][72]
    __nv_bfloat16* sT  = dyn + 96 * 72 + 64 * 72;    // [64][192] (kqv only)
    int tid = threadIdx.x, warp = tid >> 5, lane = tid & 31;
    int wm = warp & 1, wn = warp >> 1;
    float acc[3][2][4] = {};

    uint4 aPre[3];
    float4 bPre[2];

#pragma unroll 1
    for (int c = 0; c < NC; c++) {
        if (c == 0) {
#pragma unroll
            for (int t = 0; t < 3; t++) {
                int e = tid + t * 256;
                int r = e >> 3, col = (e & 7) * 8;
                int sc = (col < 32) ? col : (KTOT + col - 32);
                aPre[t] = *(const uint4*)(Asp + (size_t)r * (2 * KTOT) + sc);
            }
#pragma unroll
            for (int t = 0; t < 2; t++) {
                int e = tid + t * 256;
                int r = e >> 3, g = e & 7;
                bPre[t] = *(const float4*)(Bm + (size_t)(n0 + r) * KTOT + g * 4);
            }
        }
        __syncthreads();
#pragma unroll
        for (int t = 0; t < 3; t++) {
            int e = tid + t * 256;
            int r = e >> 3, col = (e & 7) * 8;
            *(uint4*)&sAr[r * 72 + col] = aPre[t];
        }
#pragma unroll
        for (int t = 0; t < 2; t++) {
            int e = tid + t * 256;
            int r = e >> 3, g = e & 7;
            float vv[4] = {bPre[t].x, bPre[t].y, bPre[t].z, bPre[t].w};
#pragma unroll
            for (int j = 0; j < 4; j++) {
                __nv_bfloat16 hi = __float2bfloat16(vv[j]);
                sBr[r * 72 + g * 4 + j] = hi;
                sBr[r * 72 + 32 + g * 4 + j] = __float2bfloat16(vv[j] - __bfloat162float(hi));
            }
        }
        if (c + 1 < NC) {
            int k0 = (c + 1) * 32;
#pragma unroll
            for (int t = 0; t < 3; t++) {
                int e = tid + t * 256;
                int r = e >> 3, col = (e & 7) * 8;
                int sc = (col < 32) ? (k0 + col) : (KTOT + k0 + col - 32);
                aPre[t] = *(const uint4*)(Asp + (size_t)r * (2 * KTOT) + sc);
            }
#pragma unroll
            for (int t = 0; t < 2; t++) {
                int e = tid + t * 256;
                int r = e >> 3, g = e & 7;
                bPre[t] = *(const float4*)(Bm + (size_t)(n0 + r) * KTOT + k0 + g * 4);
            }
        }
        __syncthreads();
        uint32_t aBase = smem_u32(sAr);
        uint32_t bBase = smem_u32(sBr);
        int aRow = wm * 48 + (lane & 15);
        int aCol = (lane >> 4) << 3;
        int bRow = wn * 16 + (lane & 7) + ((lane >> 4) << 3);
        int bCol = ((lane >> 3) & 1) << 3;
#pragma unroll
        for (int ks = 0; ks < 2; ks++) {
            int ka = ks * 16 + aCol, kb = ks * 16 + bCol;
            uint32_t af[3][4], bh[4], bl[4];
#pragma unroll
            for (int mi = 0; mi < 3; mi++) {
                uint32_t addr = aBase + (uint32_t)(((aRow + mi * 16) * 72 + ka) * 2);
                LDSM_X4(af[mi][0], af[mi][1], af[mi][2], af[mi][3], addr);
            }
            {
                uint32_t addr = bBase + (uint32_t)((bRow * 72 + kb) * 2);
                LDSM_X4(bh[0], bh[1], bh[2], bh[3], addr);
                addr = bBase + (uint32_t)((bRow * 72 + kb + 32) * 2);
                LDSM_X4(bl[0], bl[1], bl[2], bl[3], addr);
            }
#pragma unroll
            for (int mi = 0; mi < 3; mi++)
#pragma unroll
                for (int nj = 0; nj < 2; nj++) {
                    MMA16816(acc[mi][nj], af[mi], bh[nj * 2], bh[nj * 2 + 1]);
                    MMA16816(acc[mi][nj], af[mi], bl[nj * 2], bl[nj * 2 + 1]);
                }
        }
#pragma unroll
        for (int ks = 0; ks < 2; ks++) {
            int ka = 32 + ks * 16 + aCol, kb = ks * 16 + bCol;
            uint32_t af[3][4], bh[4];
#pragma unroll
            for (int mi = 0; mi < 3; mi++) {
                uint32_t addr = aBase + (uint32_t)(((aRow + mi * 16) * 72 + ka) * 2);
                LDSM_X4(af[mi][0], af[mi][1], af[mi][2], af[mi][3], addr);
            }
            {
                uint32_t addr = bBase + (uint32_t)((bRow * 72 + kb) * 2);
                LDSM_X4(bh[0], bh[1], bh[2], bh[3], addr);
            }
#pragma unroll
            for (int mi = 0; mi < 3; mi++)
#pragma unroll
                for (int nj = 0; nj < 2; nj++)
                    MMA16816(acc[mi][nj], af[mi], bh[nj * 2], bh[nj * 2 + 1]);
        }
    }
    const bool doT = isKqv && (n0 < 2 * H2);
#pragma unroll
    for (int mi = 0; mi < 3; mi++)
#pragma unroll
        for (int nj = 0; nj < 2; nj++)
#pragma unroll
            for (int r = 0; r < 4; r++) {
                int m = wm * 48 + mi * 16 + (lane >> 2) + ((r >> 1) * 8);
                int gl = wn * 16 + nj * 8 + (lane & 3) * 2 + (r & 1);
                int gn = n0 + gl;
                float v = acc[mi][nj][r] + bias[gn];
                if (isKqv) { if (gn < H2) v *= (1.0f / 96.0f); }
                else       v = 1.0f / (1.0f + expf(-v));
                out[(size_t)m * ldo + gn] = v;
                if (doT) {
                    __nv_bfloat16 hi = __float2bfloat16(v);
                    sT[gl * 192 + m] = hi;
                    sT[gl * 192 + 96 + m] = __float2bfloat16(v - __bfloat162float(hi));
                }
            }
    if (doT) {
        __syncthreads();
        __nv_bfloat16* dstT = (__nv_bfloat16*)((n0 < H2) ? kT_u16 : qT_u16);
        int cb = (n0 < H2) ? n0 : (n0 - H2);
        for (int e = tid; e < 64 * 24; e += 256) {
            int row = e / 24, g = e % 24;
            *(uint4*)(dstT + (size_t)(cb + row) * 192 + g * 8) = *(uint4*)(sT + row * 192 + g * 8);
        }
    }
}

// ======== Variant B: HMMA NT GEMM, N-tile 32, pre-split bf16 B [N, 192] ========
// EPI 2: n (+ fused AT transpose-split), EPI 3: h = o * acc / denom
template <int EPI>
__global__ __launch_bounds__(256, 3)
void hmma_preB(const unsigned short* __restrict__ Asp_u16, int lda,
               const unsigned short* __restrict__ B1_u16,
               const unsigned short* __restrict__ B2_u16,
               int nseg,
               const float* __restrict__ omat,
               const int* __restrict__ denomBits,
               float* __restrict__ out, int ldo,
               unsigned short* __restrict__ AT_u16) {
    const __nv_bfloat16* Asp = (const __nv_bfloat16*)Asp_u16;
    extern __shared__ __nv_bfloat16 dsm[];
    __nv_bfloat16* sA = dsm;             // [96][200]
    __nv_bfloat16* sB = dsm + 96 * 200;  // [32][200]
    int tid = threadIdx.x, warp = tid >> 5, lane = tid & 31;
    int n0 = blockIdx.x * 32;
    int wm = warp & 1, wn = warp >> 1;
    float acc[3][4] = {};

#pragma unroll 1
    for (int s = 0; s < nseg; s++) {
        const __nv_bfloat16* Bseg =
            (s == 0) ? (const __nv_bfloat16*)B1_u16 : (const __nv_bfloat16*)B2_u16;
        __syncthreads();
        for (int e = tid; e < 96 * 24; e += 256) {
            int r = e / 24, g = e % 24;
            *(uint4*)(sA + r * 200 + g * 8) =
                *(const uint4*)(Asp + (size_t)r * lda + s * 192 + g * 8);
        }
        for (int e = tid; e < 32 * 24; e += 256) {
            int r = e / 24, g = e % 24;
            *(uint4*)(sB + r * 200 + g * 8) =
                *(const uint4*)(Bseg + (size_t)(n0 + r) * 192 + g * 8);
        }
        __syncthreads();
        uint32_t aBase = smem_u32(sA), bBase = smem_u32(sB);
        int aRow = wm * 48 + (lane & 15), aCol = (lane >> 4) << 3;
        int bRowOff = (wn * 8 + (lane & 7)) * 200 + ((lane >> 3) << 3);
#pragma unroll
        for (int ks2 = 0; ks2 < 3; ks2++) {
            uint32_t bh[4], bl[4];
            {
                uint32_t addr = bBase + (uint32_t)((bRowOff + ks2 * 32) * 2);
                LDSM_X4(bh[0], bh[1], bh[2], bh[3], addr);
                addr = bBase + (uint32_t)((bRowOff + 96 + ks2 * 32) * 2);
                LDSM_X4(bl[0], bl[1], bl[2], bl[3], addr);
            }
#pragma unroll
            for (int sub = 0; sub < 2; sub++) {
                int ka = ks2 * 32 + sub * 16 + aCol;
                uint32_t afh[3][4], afl[3][4];
#pragma unroll
                for (int mi = 0; mi < 3; mi++) {
                    uint32_t addr = aBase + (uint32_t)(((aRow + mi * 16) * 200 + ka) * 2);
                    LDSM_X4(afh[mi][0], afh[mi][1], afh[mi][2], afh[mi][3], addr);
                    addr = aBase + (uint32_t)(((aRow + mi * 16) * 200 + 96 + ka) * 2);
                    LDSM_X4(afl[mi][0], afl[mi][1], afl[mi][2], afl[mi][3], addr);
                }
#pragma unroll
                for (int mi = 0; mi < 3; mi++) {
                    MMA16816(acc[mi], afh[mi], bh[sub * 2], bh[sub * 2 + 1]);
                    MMA16816(acc[mi], afh[mi], bl[sub * 2], bl[sub * 2 + 1]);
                    MMA16816(acc[mi], afl[mi], bh[sub * 2], bh[sub * 2 + 1]);
                }
            }
        }
    }
    if (EPI == 2) __syncthreads();
#pragma unroll
    for (int mi = 0; mi < 3; mi++)
#pragma unroll
        for (int r = 0; r < 4; r++) {
            int m = wm * 48 + mi * 16 + (lane >> 2) + ((r >> 1) * 8);
            int gl = wn * 8 + (lane & 3) * 2 + (r & 1);
            int gn = n0 + gl;
            float v = acc[mi][r];
            if (EPI == 3)
                v = omat[(size_t)m * H2 + gn] * v / __int_as_float(denomBits[gn]);
            out[(size_t)m * ldo + gn] = v;
            if (EPI == 2) {
                __nv_bfloat16 hi = __float2bfloat16(v);
                sA[gl * 192 + m] = hi;
                sA[gl * 192 + 96 + m] = __float2bfloat16(v - __bfloat162float(hi));
            }
        }
    if (EPI == 2) {
        __syncthreads();
        __nv_bfloat16* AT = (__nv_bfloat16*)AT_u16;
        for (int e = tid; e < 32 * 24; e += 256) {
            int row = e / 24, g = e % 24;
            *(uint4*)(AT + (size_t)(n0 + row) * 192 + g * 8) = *(uint4*)(sA + row * 192 + g * 8);
        }
    }
}

// ================= HMMA denom: A-resident, 6 B tiles per CTA =================
#define SMN_LD 200

__global__ __launch_bounds__(256, 2)
void denom_mma_kernel(const unsigned short* __restrict__ AT,
                      const unsigned short* __restrict__ BT,
                      int* __restrict__ denom) {
    extern __shared__ __align__(16) unsigned short sm[];
    unsigned short* sA = sm;
    unsigned short* sB = sm + 128 * SMN_LD;
    int tid = threadIdx.x;
    int r0 = blockIdx.x * 128;
    int cbase = blockIdx.y * 768;

    for (int e = tid; e < 128 * 24; e += 256) {
        int row = e / 24, c8 = (e % 24) * 8;
        *(float4*)(sA + row * SMN_LD + c8) = *(const float4*)(AT + (size_t)(r0 + row) * 192 + c8);
    }

    int warp = tid >> 5, lane = tid & 31;
    int wm = warp & 1, wn = warp >> 1;
    uint32_t aBase = smem_u32(sA);
    uint32_t bBase = smem_u32(sB);

    int aRow = wm * 64 + (lane & 15);
    int aColL = (lane >> 4) << 3;
    int bRow = wn * 32 + (lane & 7) + ((lane >> 4) << 3);
    int bColL = ((lane >> 3) & 1) << 3;

    float mx[4][2];
#pragma unroll
    for (int mi = 0; mi < 4; mi++) { mx[mi][0] = 0.f; mx[mi][1] = 0.f; }

#pragma unroll 1
    for (int t = 0; t < 6; t++) {
        __syncthreads();
        for (int e = tid; e < 128 * 24; e += 256) {
            int row = e / 24, c8 = (e % 24) * 8;
            *(float4*)(sB + row * SMN_LD + c8) =
                *(const float4*)(BT + (size_t)(cbase + t * 128 + row) * 192 + c8);
        }
        __syncthreads();

        float acc[4][4][4];
#pragma unroll
        for (int mi = 0; mi < 4; mi++)
#pragma unroll
            for (int nj = 0; nj < 4; nj++)
#pragma unroll
                for (int r = 0; r < 4; r++) acc[mi][nj][r] = 0.f;

#pragma unroll 1
        for (int ks = 0; ks < 6; ks++) {
            int ka = ks * 16 + aColL;
            int kb = ks * 16 + bColL;
            uint32_t af[4][4], bh[2][4], bl[2][4];
#pragma unroll
            for (int mi = 0; mi < 4; mi++) {
                uint32_t addr = aBase + (uint32_t)(((aRow + mi * 16) * SMN_LD + ka) * 2);
                LDSM_X4(af[mi][0], af[mi][1], af[mi][2], af[mi][3], addr);
            }
#pragma unroll
            for (int nj2 = 0; nj2 < 2; nj2++) {
                uint32_t addr = bBase + (uint32_t)(((bRow + nj2 * 16) * SMN_LD + kb) * 2);
                LDSM_X4(bh[nj2][0], bh[nj2][1], bh[nj2][2], bh[nj2][3], addr);
                addr = bBase + (uint32_t)(((bRow + nj2 * 16) * SMN_LD + kb + 96) * 2);
                LDSM_X4(bl[nj2][0], bl[nj2][1], bl[nj2][2], bl[nj2][3], addr);
            }
#pragma unroll
            for (int mi = 0; mi < 4; mi++)
#pragma unroll
                for (int nj = 0; nj < 4; nj++) {
                    MMA16816(acc[mi][nj], af[mi], bh[nj >> 1][(nj & 1) * 2],
                             bh[nj >> 1][(nj & 1) * 2 + 1]);
                    MMA16816(acc[mi][nj], af[mi], bl[nj >> 1][(nj & 1) * 2],
                             bl[nj >> 1][(nj & 1) * 2 + 1]);
                }
        }
#pragma unroll 1
        for (int ks = 0; ks < 6; ks++) {
            int ka = 96 + ks * 16 + aColL;
            int kb = ks * 16 + bColL;
            uint32_t af[4][4], bh[2][4];
#pragma unroll
            for (int mi = 0; mi < 4; mi++) {
                uint32_t addr = aBase + (uint32_t)(((aRow + mi * 16) * SMN_LD + ka) * 2);
                LDSM_X4(af[mi][0], af[mi][1], af[mi][2], af[mi][3], addr);
            }
#pragma unroll
            for (int nj2 = 0; nj2 < 2; nj2++) {
                uint32_t addr = bBase + (uint32_t)(((bRow + nj2 * 16) * SMN_LD + kb) * 2);
                LDSM_X4(bh[nj2][0], bh[nj2][1], bh[nj2][2], bh[nj2][3], addr);
            }
#pragma unroll
            for (int mi = 0; mi < 4; mi++)
#pragma unroll
                for (int nj = 0; nj < 4; nj++)
                    MMA16816(acc[mi][nj], af[mi], bh[nj >> 1][(nj & 1) * 2],
                             bh[nj >> 1][(nj & 1) * 2 + 1]);
        }

#pragma unroll
        for (int mi = 0; mi < 4; mi++) {
#pragma unroll
            for (int nj = 0; nj < 4; nj++) {
                mx[mi][0] = fmaxf(mx[mi][0], fmaxf(fabsf(acc[mi][nj][0]), fabsf(acc[mi][nj][1])));
                mx[mi][1] = fmaxf(mx[mi][1], fmaxf(fabsf(acc[mi][nj][2]), fabsf(acc[mi][nj][3])));
            }
        }
    }

#pragma unroll
    for (int mi = 0; mi < 4; mi++) {
        float m0 = mx[mi][0], m1 = mx[mi][1];
        m0 = fmaxf(m0, __shfl_xor_sync(0xffffffffu, m0, 1));
        m0 = fmaxf(m0, __shfl_xor_sync(0xffffffffu, m0, 2));
        m1 = fmaxf(m1, __shfl_xor_sync(0xffffffffu, m1, 1));
        m1 = fmaxf(m1, __shfl_xor_sync(0xffffffffu, m1, 2));
        if ((lane & 3) == 0) {
            int rbase = r0 + wm * 64 + mi * 16 + (lane >> 2);
            atomicMax(&denom[rbase], __float_as_int(m0));
            atomicMax(&denom[rbase + 8], __float_as_int(m1));
        }
    }
}

// ---------------- v @ k^T : deterministic split-K (48 chunks of 192, float4 loads) ----
__global__ __launch_bounds__(256)
void vkt_part_kernel(const float* __restrict__ kqv, float* __restrict__ part) {
    const float* V  = kqv + 2 * H2;
    const float* Km = kqv;
    __shared__ float As[32][17];
    __shared__ float Bs[32][17];
    int tid = threadIdx.x, tx = tid & 15, ty = tid >> 4;
    int m0 = blockIdx.x * 32, n0 = blockIdx.y * 32;
    int kbase = blockIdx.z * VKT_CHUNK;
    float a00 = 0, a01 = 0, a10 = 0, a11 = 0;
    for (int k0 = 0; k0 < VKT_CHUNK; k0 += 16) {
        // 32 rows x 16 cols = 128 float4 per matrix; 256 threads load both
        {
            int e = tid;                      // 0..255
            int mat = e >> 7;                 // 0: A, 1: B
            int idx = e & 127;
            int m = idx >> 2, c4 = (idx & 3) * 4;
            const float* src = mat ? Km + (size_t)(n0 + m) * KQVN
                                   : V + (size_t)(m0 + m) * KQVN;
            float4 v = *(const float4*)(src + kbase + k0 + c4);
            float* dst = mat ? &Bs[m][c4] : &As[m][c4];
            dst[0] = v.x; dst[1] = v.y; dst[2] = v.z; dst[3] = v.w;
        }
        __syncthreads();
#pragma unroll
        for (int kk = 0; kk < 16; kk++) {
            float av0 = As[ty][kk],      av1 = As[ty + 16][kk];
            float bv0 = Bs[tx][kk],      bv1 = Bs[tx + 16][kk];
            a00 += av0 * bv0; a01 += av0 * bv1;
            a10 += av1 * bv0; a11 += av1 * bv1;
        }
        __syncthreads();
    }
    float* p = part + blockIdx.z * (Hs * Hs);
    p[(m0 + ty) * Hs + (n0 + tx)]           = a00;
    p[(m0 + ty) * Hs + (n0 + tx + 16)]      = a01;
    p[(m0 + ty + 16) * Hs + (n0 + tx)]      = a10;
    p[(m0 + ty + 16) * Hs + (n0 + tx + 16)] = a11;
}

__global__ void vkt_reduce_kernel(const float* __restrict__ part, float* __restrict__ vkt) {
    int idx = blockIdx.x * blockDim.x + threadIdx.x;
    if (idx < Hs * Hs) {
        float s = 0.f;
#pragma unroll
        for (int c = 0; c < VKT_SPLIT; c++) s += part[c * (Hs * Hs) + idx];
        vkt[idx] = s;
    }
}

// ---------------- C = f @ C_prev + i @ vkT   (96x96), + split ----------------
__global__ void c_kernel(const float* __restrict__ f, const float* __restrict__ i_,
                         const float* __restrict__ C_prev, const float* __restrict__ vkt,
                         float* __restrict__ outC, unsigned short* __restrict__ Cs_u16) {
    __shared__ float fs[Hs], is[Hs];
    int b = blockIdx.x, n = threadIdx.x;
    fs[n] = f[b * Hs + n];
    is[n] = i_[b * Hs + n];
    __syncthreads();
    float acc = 0.f;
    for (int h = 0; h < Hs; h++)
        acc += fs[h] * C_prev[h * Hs + n] + is[h] * vkt[h * Hs + n];
    outC[b * Hs + n] = acc;
    __nv_bfloat16* Cs = (__nv_bfloat16*)Cs_u16;
    __nv_bfloat16 hi = __float2bfloat16(acc);
    Cs[b * 192 + n] = hi;
    Cs[b * 192 + 96 + n] = __float2bfloat16(acc - __bfloat162float(hi));
}

// ---------------- launch ----------------
extern "C" void kernel_launch(void* const* d_in, const int* in_sizes, int n_in,
                              void* d_out, int out_size) {
    const float* x      = (const float*)d_in[0];
    const float* h_prev = (const float*)d_in[1];
    const float* C_prev = (const float*)d_in[2];
    const float* n_prev = (const float*)d_in[3];
    const float* wix_w  = (const float*)d_in[4];
    const float* wix_b  = (const float*)d_in[5];
    const float* wfx_w  = (const float*)d_in[6];
    const float* wfx_b  = (const float*)d_in[7];
    const float* Wox_w  = (const float*)d_in[8];
    const float* Wox_b  = (const float*)d_in[9];
    const float* Wkqv_w = (const float*)d_in[10];
    const float* Wkqv_b = (const float*)d_in[11];

    float* out   = (float*)d_out;
    float* out_h = out;                       // [96, 9216]
    float* out_C = out + Bsz * H2;            // [96, 96]
    float* out_n = out_C + Bsz * Hs;          // [96, 9216]

    float *p_i, *p_f, *p_o, *p_kqv, *p_part, *p_vkt;
    int* p_denom;
    unsigned short *p_AT, *p_BT, *p_npT, *p_kT, *p_xs, *p_hps, *p_fis, *p_Cs;
    cudaGetSymbolAddress((void**)&p_i,     g_i);
    cudaGetSymbolAddress((void**)&p_f,     g_f);
    cudaGetSymbolAddress((void**)&p_o,     g_o);
    cudaGetSymbolAddress((void**)&p_kqv,   g_kqv);
    cudaGetSymbolAddress((void**)&p_part,  g_vkT_part);
    cudaGetSymbolAddress((void**)&p_vkt,   g_vkT);
    cudaGetSymbolAddress((void**)&p_denom, g_denom);
    cudaGetSymbolAddress((void**)&p_AT,    g_AT);
    cudaGetSymbolAddress((void**)&p_BT,    g_BT);
    cudaGetSymbolAddress((void**)&p_npT,   g_npT);
    cudaGetSymbolAddress((void**)&p_kT,    g_kT);
    cudaGetSymbolAddress((void**)&p_xs,    g_xs);
    cudaGetSymbolAddress((void**)&p_hps,   g_hps);
    cudaGetSymbolAddress((void**)&p_fis,   g_fis);
    cudaGetSymbolAddress((void**)&p_Cs,    g_Cs);

    const int DENOM_SMEM = 2 * 128 * SMN_LD * 2;                 // 102400
    const int PREB_SMEM  = (96 + 32) * 200 * 2;                  // 51200
    const int CONV_SMEM  = (96 * 72 + 64 * 72 + 64 * 192) * 2;   // 47616
    cudaFuncSetAttribute(denom_mma_kernel,
                         cudaFuncAttributeMaxDynamicSharedMemorySize, DENOM_SMEM);
    cudaFuncSetAttribute(hmma_preB<2>,
                         cudaFuncAttributeMaxDynamicSharedMemorySize, PREB_SMEM);
    cudaFuncSetAttribute(hmma_preB<3>,
                         cudaFuncAttributeMaxDynamicSharedMemorySize, PREB_SMEM);
    cudaFuncSetAttribute(hmma_conv_uber,
                         cudaFuncAttributeMaxDynamicSharedMemorySize, CONV_SMEM);

    // preamble: npT transpose-split | x/h splits + denom zero | gates (one launch)
    preamble_kernel<<<3096, 256>>>(x, h_prev, n_prev, wix_w, wix_b, wfx_w, wfx_b,
                                   p_xs, p_hps, p_npT, p_i, p_f, p_fis, p_denom);

    // kqv (+ fused kT/qT splits) and o in ONE launch
    hmma_conv_uber<<<576, 256, CONV_SMEM>>>(p_xs, p_hps, Wkqv_w, Wkqv_b, Wox_w, Wox_b,
                                            p_kqv, p_o, p_kT, p_BT);

    // n = f @ n_prev + i @ k  (HMMA, N32 tiles) + fused AT transpose-split
    hmma_preB<2><<<H2 / 32, 256, PREB_SMEM>>>(p_fis, 384, p_npT, p_kT, 2,
                                              nullptr, nullptr, out_n, H2, p_AT);

    // vkT = v @ k^T  (48-way split-K)
    vkt_part_kernel<<<dim3(3, 3, VKT_SPLIT), 256>>>(p_kqv, p_part);
    vkt_reduce_kernel<<<36, 256>>>(p_part, p_vkt);

    // C = f @ C_prev + i @ vkT (+ split)
    c_kernel<<<Bsz, Hs>>>(p_f, p_i, C_prev, p_vkt, out_C, p_Cs);

    // denom = max_c |n^T q|  (A-resident, 6 B tiles per CTA)
    denom_mma_kernel<<<dim3(72, 12), 256, DENOM_SMEM>>>(p_AT, p_BT, p_denom);

    // h = o * (C @ q) / denom  (N32 tiles)
    hmma_preB<3><<<H2 / 32, 256, PREB_SMEM>>>(p_Cs, 192, p_BT, nullptr, 1,
                                              p_o, p_denom, out_h, H2, nullptr);
}

// round 15
// speedup vs baseline: 1.2030x; 1.0041x over previous
#include <cuda_runtime.h>
#include <cuda_bf16.h>
#include <math.h>
#include <stdint.h>

#define Bsz  96
#define Hs   96
#define Ds   768
#define H2   9216
#define KQVN 27648
#define VKT_SPLIT 96
#define VKT_CHUNK 96

// ---------------- scratch (static device memory, no allocation) ----------------
__device__ float g_i[Bsz * Hs];
__device__ float g_f[Bsz * Hs];
__device__ float g_o[Bsz * H2];
__device__ float g_kqv[Bsz * KQVN];          // [96, 27648] : k | q | v (k pre-scaled by 1/96)
__device__ float g_vkT_part[VKT_SPLIT * Hs * Hs];
__device__ float g_vkT[Hs * Hs];
__device__ int   g_denom[H2];                // float bits via atomicMax on non-neg floats
// pre-split bf16 operands
__device__ unsigned short g_AT[H2 * 192];    // n^T  [9216, 96hi|96lo]
__device__ unsigned short g_BT[H2 * 192];    // q^T
__device__ unsigned short g_npT[H2 * 192];   // n_prev^T
__device__ unsigned short g_kT[H2 * 192];    // k^T
__device__ unsigned short g_xs[Bsz * 1536];  // x split [96, 768hi|768lo]
__device__ unsigned short g_hps[Bsz * 192];  // h_prev split
__device__ unsigned short g_fis[Bsz * 384];  // [f hi|lo | i hi|lo]
__device__ unsigned short g_Cs[Bsz * 192];   // C split

// ---------------- helpers ----------------
__device__ __forceinline__ uint32_t smem_u32(const void* p) {
    uint32_t a;
    asm("{ .reg .u64 t; cvta.to.shared.u64 t, %1; cvt.u32.u64 %0, t; }" : "=r"(a) : "l"(p));
    return a;
}
#define LDSM_X4(r0, r1, r2, r3, addr) \
    asm volatile("ldmatrix.sync.aligned.m8n8.x4.shared.b16 {%0,%1,%2,%3}, [%4];" \
                 : "=r"(r0), "=r"(r1), "=r"(r2), "=r"(r3) : "r"(addr))
#define MMA16816(d, a, b0, b1) \
    asm volatile("mma.sync.aligned.m16n8k16.row.col.f32.bf16.bf16.f32 " \
                 "{%0,%1,%2,%3},{%4,%5,%6,%7},{%8,%9},{%0,%1,%2,%3};" \
                 : "+f"((d)[0]), "+f"((d)[1]), "+f"((d)[2]), "+f"((d)[3]) \
                 : "r"((a)[0]), "r"((a)[1]), "r"((a)[2]), "r"((a)[3]), "r"(b0), "r"(b1))

// ================= merged preamble: npT transpose-split | x/h splits | gates ======
__global__ __launch_bounds__(256)
void preamble_kernel(const float* __restrict__ x, const float* __restrict__ hp,
                     const float* __restrict__ n_prev,
                     const float* __restrict__ wix_w, const float* __restrict__ wix_b,
                     const float* __restrict__ wfx_w, const float* __restrict__ wfx_b,
                     unsigned short* __restrict__ xs_u16, unsigned short* __restrict__ hps_u16,
                     unsigned short* __restrict__ npT_u16,
                     float* __restrict__ gi, float* __restrict__ gf,
                     unsigned short* __restrict__ fis_u16,
                     int* __restrict__ denom) {
    __shared__ float t[32][68];
    int blk = blockIdx.x, tid = threadIdx.x;
    if (blk < 432) {
        __nv_bfloat16* dst = (__nv_bfloat16*)npT_u16;
        int bx = blk % 144, by = blk / 144;
        int r0 = bx * 64, j0 = by * 32;
#pragma unroll
        for (int it = 0; it < 2; it++) {
            int e = tid + it * 256;
            int jj = e >> 4, c4 = (e & 15) * 4;
            float4 v = *(const float4*)(n_prev + (size_t)(j0 + jj) * H2 + r0 + c4);
            *(float4*)&t[jj][c4] = v;
        }
        __syncthreads();
#pragma unroll
        for (int it = 0; it < 2; it++) {
            int e = tid + it * 256;
            int rr = e >> 3, q = e & 7;
            int isLo = q >> 2, jb = (q & 3) * 8;
            __nv_bfloat16 vals[8];
#pragma unroll
            for (int w = 0; w < 8; w++) {
                float f = t[jb + w][rr];
                __nv_bfloat16 hi = __float2bfloat16(f);
                vals[w] = isLo ? __float2bfloat16(f - __bfloat162float(hi)) : hi;
            }
            *(uint4*)(dst + (size_t)(r0 + rr) * 192 + isLo * 96 + j0 + jb) = *(uint4*)vals;
        }
    } else if (blk < 792) {
        int b2 = blk - 432;
        if (b2 < 288) {
            __nv_bfloat16* xs = (__nv_bfloat16*)xs_u16;
            int e = b2 * 256 + tid;
            int r = e / Ds, c = e % Ds;
            float v = x[e];
            __nv_bfloat16 hi = __float2bfloat16(v);
            xs[(size_t)r * 1536 + c] = hi;
            xs[(size_t)r * 1536 + Ds + c] = __float2bfloat16(v - __bfloat162float(hi));
        } else if (b2 < 324) {
            __nv_bfloat16* hs = (__nv_bfloat16*)hps_u16;
            int e = (b2 - 288) * 256 + tid;
            int r = e / Hs, c = e % Hs;
            float v = hp[e];
            __nv_bfloat16 hi = __float2bfloat16(v);
            hs[(size_t)r * 192 + c] = hi;
            hs[(size_t)r * 192 + Hs + c] = __float2bfloat16(v - __bfloat162float(hi));
        } else {
            int e = (b2 - 324) * 256 + tid;
            denom[e] = 0;
        }
    } else {
        int gw = (blk - 792) * 8 + (tid >> 5);
        int lane = tid & 31;
        int isI = gw < Bsz * Hs;
        int o = isI ? gw : gw - Bsz * Hs;
        int b = o / Hs, n = o % Hs;
        const float* a = isI ? x + (size_t)b * Ds : hp + (size_t)b * Hs;
        const float* w = isI ? wix_w + (size_t)n * Ds : wfx_w + (size_t)n * Hs;
        int K = isI ? Ds : Hs;
        float acc = 0.f;
        for (int k = lane; k < K; k += 32) acc += a[k] * w[k];
#pragma unroll
        for (int off = 16; off; off >>= 1) acc += __shfl_xor_sync(0xffffffffu, acc, off);
        if (lane == 0) {
            float v = expf(acc + (isI ? wix_b[n] : wfx_b[n]));
            (isI ? gi : gf)[o] = v;
            __nv_bfloat16* fis = (__nv_bfloat16*)fis_u16;
            __nv_bfloat16 hi = __float2bfloat16(v);
            int base = b * 384 + (isI ? 192 : 0) + n;
            fis[base] = hi;
            fis[base + 96] = __float2bfloat16(v - __bfloat162float(hi));
        }
    }
}

// ======== UBER convA: kqv (blocks 0..431) + o (blocks 432..575) in one launch ====
__global__ __launch_bounds__(256, 3)
void hmma_conv_uber(const unsigned short* __restrict__ xs_u16,
                    const unsigned short* __restrict__ hps_u16,
                    const float* __restrict__ Wkqv, const float* __restrict__ Wkqv_b,
                    const float* __restrict__ Wox,  const float* __restrict__ Wox_b,
                    float* __restrict__ kqv_out, float* __restrict__ o_out,
                    unsigned short* __restrict__ kT_u16,
                    unsigned short* __restrict__ qT_u16) {
    const bool isKqv = blockIdx.x < 432;
    const __nv_bfloat16* Asp = (const __nv_bfloat16*)(isKqv ? xs_u16 : hps_u16);
    const int KTOT = isKqv ? Ds : Hs;
    const float* Bm   = isKqv ? Wkqv : Wox;
    const float* bias = isKqv ? Wkqv_b : Wox_b;
    float* out = isKqv ? kqv_out : o_out;
    const int ldo = isKqv ? KQVN : H2;
    const int n0 = (isKqv ? blockIdx.x : (blockIdx.x - 432)) * 64;
    const int NC = KTOT / 32;

    extern __shared__ __nv_bfloat16 dyn[];
    __nv_bfloat16* sAr = dyn;                        // [96][72]
    __nv_bfloat16* sBr = dyn + 96 * 72;              // [64][72]
    __nv_bfloat16* sT  = dyn + 96 * 72 + 64 * 72;    // [64][192] (kqv only)
    int tid = threadIdx.x, warp = tid >> 5, lane = tid & 31;
    int wm = warp & 1, wn = warp >> 1;
    float acc[3][2][4] = {};

    uint4 aPre[3];
    float4 bPre[2];

#pragma unroll 1
    for (int c = 0; c < NC; c++) {
        if (c == 0) {
#pragma unroll
            for (int t = 0; t < 3; t++) {
                int e = tid + t * 256;
                int r = e >> 3, col = (e & 7) * 8;
                int sc = (col < 32) ? col : (KTOT + col - 32);
                aPre[t] = *(const uint4*)(Asp + (size_t)r * (2 * KTOT) + sc);
            }
#pragma unroll
            for (int t = 0; t < 2; t++) {
                int e = tid + t * 256;
                int r = e >> 3, g = e & 7;
                bPre[t] = *(const float4*)(Bm + (size_t)(n0 + r) * KTOT + g * 4);
            }
        }
        __syncthreads();
#pragma unroll
        for (int t = 0; t < 3; t++) {
            int e = tid + t * 256;
            int r = e >> 3, col = (e & 7) * 8;
            *(uint4*)&sAr[r * 72 + col] = aPre[t];
        }
#pragma unroll
        for (int t = 0; t < 2; t++) {
            int e = tid + t * 256;
            int r = e >> 3, g = e & 7;
            float vv[4] = {bPre[t].x, bPre[t].y, bPre[t].z, bPre[t].w};
#pragma unroll
            for (int j = 0; j < 4; j++) {
                __nv_bfloat16 hi = __float2bfloat16(vv[j]);
                sBr[r * 72 + g * 4 + j] = hi;
                sBr[r * 72 + 32 + g * 4 + j] = __float2bfloat16(vv[j] - __bfloat162float(hi));
            }
        }
        if (c + 1 < NC) {
            int k0 = (c + 1) * 32;
#pragma unroll
            for (int t = 0; t < 3; t++) {
                int e = tid + t * 256;
                int r = e >> 3, col = (e & 7) * 8;
                int sc = (col < 32) ? (k0 + col) : (KTOT + k0 + col - 32);
                aPre[t] = *(const uint4*)(Asp + (size_t)r * (2 * KTOT) + sc);
            }
#pragma unroll
            for (int t = 0; t < 2; t++) {
                int e = tid + t * 256;
                int r = e >> 3, g = e & 7;
                bPre[t] = *(const float4*)(Bm + (size_t)(n0 + r) * KTOT + k0 + g * 4);
            }
        }
        __syncthreads();
        uint32_t aBase = smem_u32(sAr);
        uint32_t bBase = smem_u32(sBr);
        int aRow = wm * 48 + (lane & 15);
        int aCol = (lane >> 4) << 3;
        int bRow = wn * 16 + (lane & 7) + ((lane >> 4) << 3);
        int bCol = ((lane >> 3) & 1) << 3;
#pragma unroll
        for (int ks = 0; ks < 2; ks++) {
            int ka = ks * 16 + aCol, kb = ks * 16 + bCol;
            uint32_t af[3][4], bh[4], bl[4];
#pragma unroll
            for (int mi = 0; mi < 3; mi++) {
                uint32_t addr = aBase + (uint32_t)(((aRow + mi * 16) * 72 + ka) * 2);
                LDSM_X4(af[mi][0], af[mi][1], af[mi][2], af[mi][3], addr);
            }
            {
                uint32_t addr = bBase + (uint32_t)((bRow * 72 + kb) * 2);
                LDSM_X4(bh[0], bh[1], bh[2], bh[3], addr);
                addr = bBase + (uint32_t)((bRow * 72 + kb + 32) * 2);
                LDSM_X4(bl[0], bl[1], bl[2], bl[3], addr);
            }
#pragma unroll
            for (int mi = 0; mi < 3; mi++)
#pragma unroll
                for (int nj = 0; nj < 2; nj++) {
                    MMA16816(acc[mi][nj], af[mi], bh[nj * 2], bh[nj * 2 + 1]);
                    MMA16816(acc[mi][nj], af[mi], bl[nj * 2], bl[nj * 2 + 1]);
                }
        }
#pragma unroll
        for (int ks = 0; ks < 2; ks++) {
            int ka = 32 + ks * 16 + aCol, kb = ks * 16 + bCol;
            uint32_t af[3][4], bh[4];
#pragma unroll
            for (int mi = 0; mi < 3; mi++) {
                uint32_t addr = aBase + (uint32_t)(((aRow + mi * 16) * 72 + ka) * 2);
                LDSM_X4(af[mi][0], af[mi][1], af[mi][2], af[mi][3], addr);
            }
            {
                uint32_t addr = bBase + (uint32_t)((bRow * 72 + kb) * 2);
                LDSM_X4(bh[0], bh[1], bh[2], bh[3], addr);
            }
#pragma unroll
            for (int mi = 0; mi < 3; mi++)
#pragma unroll
                for (int nj = 0; nj < 2; nj++)
                    MMA16816(acc[mi][nj], af[mi], bh[nj * 2], bh[nj * 2 + 1]);
        }
    }
    const bool doT = isKqv && (n0 < 2 * H2);
#pragma unroll
    for (int mi = 0; mi < 3; mi++)
#pragma unroll
        for (int nj = 0; nj < 2; nj++)
#pragma unroll
            for (int r = 0; r < 4; r++) {
                int m = wm * 48 + mi * 16 + (lane >> 2) + ((r >> 1) * 8);
                int gl = wn * 16 + nj * 8 + (lane & 3) * 2 + (r & 1);
                int gn = n0 + gl;
                float v = acc[mi][nj][r] + bias[gn];
                if (isKqv) { if (gn < H2) v *= (1.0f / 96.0f); }
                else       v = 1.0f / (1.0f + expf(-v));
                out[(size_t)m * ldo + gn] = v;
                if (doT) {
                    __nv_bfloat16 hi = __float2bfloat16(v);
                    sT[gl * 192 + m] = hi;
                    sT[gl * 192 + 96 + m] = __float2bfloat16(v - __bfloat162float(hi));
                }
            }
    if (doT) {
        __syncthreads();
        __nv_bfloat16* dstT = (__nv_bfloat16*)((n0 < H2) ? kT_u16 : qT_u16);
        int cb = (n0 < H2) ? n0 : (n0 - H2);
        for (int e = tid; e < 64 * 24; e += 256) {
            int row = e / 24, g = e % 24;
            *(uint4*)(dstT + (size_t)(cb + row) * 192 + g * 8) = *(uint4*)(sT + row * 192 + g * 8);
        }
    }
}

// ======== Variant B: HMMA NT GEMM, N-tile 32, pre-split bf16 B [N, 192] ========
// EPI 2: n (+ fused AT transpose-split), EPI 3: h = o * acc / denom
template <int EPI>
__global__ __launch_bounds__(256, 3)
void hmma_preB(const unsigned short* __restrict__ Asp_u16, int lda,
               const unsigned short* __restrict__ B1_u16,
               const unsigned short* __restrict__ B2_u16,
               int nseg,
               const float* __restrict__ omat,
               const int* __restrict__ denomBits,
               float* __restrict__ out, int ldo,
               unsigned short* __restrict__ AT_u16) {
    const __nv_bfloat16* Asp = (const __nv_bfloat16*)Asp_u16;
    extern __shared__ __nv_bfloat16 dsm[];
    __nv_bfloat16* sA = dsm;             // [96][200]
    __nv_bfloat16* sB = dsm + 96 * 200;  // [32][200]
    int tid = threadIdx.x, warp = tid >> 5, lane = tid & 31;
    int n0 = blockIdx.x * 32;
    int wm = warp & 1, wn = warp >> 1;
    float acc[3][4] = {};

#pragma unroll 1
    for (int s = 0; s < nseg; s++) {
        const __nv_bfloat16* Bseg =
            (s == 0) ? (const __nv_bfloat16*)B1_u16 : (const __nv_bfloat16*)B2_u16;
        __syncthreads();
        for (int e = tid; e < 96 * 24; e += 256) {
            int r = e / 24, g = e % 24;
            *(uint4*)(sA + r * 200 + g * 8) =
                *(const uint4*)(Asp + (size_t)r * lda + s * 192 + g * 8);
        }
        for (int e = tid; e < 32 * 24; e += 256) {
            int r = e / 24, g = e % 24;
            *(uint4*)(sB + r * 200 + g * 8) =
                *(const uint4*)(Bseg + (size_t)(n0 + r) * 192 + g * 8);
        }
        __syncthreads();
        uint32_t aBase = smem_u32(sA), bBase = smem_u32(sB);
        int aRow = wm * 48 + (lane & 15), aCol = (lane >> 4) << 3;
        int bRowOff = (wn * 8 + (lane & 7)) * 200 + ((lane >> 3) << 3);
#pragma unroll
        for (int ks2 = 0; ks2 < 3; ks2++) {
            uint32_t bh[4], bl[4];
            {
                uint32_t addr = bBase + (uint32_t)((bRowOff + ks2 * 32) * 2);
                LDSM_X4(bh[0], bh[1], bh[2], bh[3], addr);
                addr = bBase + (uint32_t)((bRowOff + 96 + ks2 * 32) * 2);
                LDSM_X4(bl[0], bl[1], bl[2], bl[3], addr);
            }
#pragma unroll
            for (int sub = 0; sub < 2; sub++) {
                int ka = ks2 * 32 + sub * 16 + aCol;
                uint32_t afh[3][4], afl[3][4];
#pragma unroll
                for (int mi = 0; mi < 3; mi++) {
                    uint32_t addr = aBase + (uint32_t)(((aRow + mi * 16) * 200 + ka) * 2);
                    LDSM_X4(afh[mi][0], afh[mi][1], afh[mi][2], afh[mi][3], addr);
                    addr = aBase + (uint32_t)(((aRow + mi * 16) * 200 + 96 + ka) * 2);
                    LDSM_X4(afl[mi][0], afl[mi][1], afl[mi][2], afl[mi][3], addr);
                }
#pragma unroll
                for (int mi = 0; mi < 3; mi++) {
                    MMA16816(acc[mi], afh[mi], bh[sub * 2], bh[sub * 2 + 1]);
                    MMA16816(acc[mi], afh[mi], bl[sub * 2], bl[sub * 2 + 1]);
                    MMA16816(acc[mi], afl[mi], bh[sub * 2], bh[sub * 2 + 1]);
                }
            }
        }
    }
    if (EPI == 2) __syncthreads();
#pragma unroll
    for (int mi = 0; mi < 3; mi++)
#pragma unroll
        for (int r = 0; r < 4; r++) {
            int m = wm * 48 + mi * 16 + (lane >> 2) + ((r >> 1) * 8);
            int gl = wn * 8 + (lane & 3) * 2 + (r & 1);
            int gn = n0 + gl;
            float v = acc[mi][r];
            if (EPI == 3)
                v = omat[(size_t)m * H2 + gn] * v / __int_as_float(denomBits[gn]);
            out[(size_t)m * ldo + gn] = v;
            if (EPI == 2) {
                __nv_bfloat16 hi = __float2bfloat16(v);
                sA[gl * 192 + m] = hi;
                sA[gl * 192 + 96 + m] = __float2bfloat16(v - __bfloat162float(hi));
            }
        }
    if (EPI == 2) {
        __syncthreads();
        __nv_bfloat16* AT = (__nv_bfloat16*)AT_u16;
        for (int e = tid; e < 32 * 24; e += 256) {
            int row = e / 24, g = e % 24;
            *(uint4*)(AT + (size_t)(n0 + row) * 192 + g * 8) = *(uint4*)(sA + row * 192 + g * 8);
        }
    }
}

// ================= HMMA denom: A-resident, 6 B tiles per CTA =================
#define SMN_LD 200

__global__ __launch_bounds__(256, 2)
void denom_mma_kernel(const unsigned short* __restrict__ AT,
                      const unsigned short* __restrict__ BT,
                      int* __restrict__ denom) {
    extern __shared__ __align__(16) unsigned short sm[];
    unsigned short* sA = sm;
    unsigned short* sB = sm + 128 * SMN_LD;
    int tid = threadIdx.x;
    int r0 = blockIdx.x * 128;
    int cbase = blockIdx.y * 768;

    for (int e = tid; e < 128 * 24; e += 256) {
        int row = e / 24, c8 = (e % 24) * 8;
        *(float4*)(sA + row * SMN_LD + c8) = *(const float4*)(AT + (size_t)(r0 + row) * 192 + c8);
    }

    int warp = tid >> 5, lane = tid & 31;
    int wm = warp & 1, wn = warp >> 1;
    uint32_t aBase = smem_u32(sA);
    uint32_t bBase = smem_u32(sB);

    int aRow = wm * 64 + (lane & 15);
    int aColL = (lane >> 4) << 3;
    int bRow = wn * 32 + (lane & 7) + ((lane >> 4) << 3);
    int bColL = ((lane >> 3) & 1) << 3;

    float mx[4][2];
#pragma unroll
    for (int mi = 0; mi < 4; mi++) { mx[mi][0] = 0.f; mx[mi][1] = 0.f; }

#pragma unroll 1
    for (int t = 0; t < 6; t++) {
        __syncthreads();
        for (int e = tid; e < 128 * 24; e += 256) {
            int row = e / 24, c8 = (e % 24) * 8;
            *(float4*)(sB + row * SMN_LD + c8) =
                *(const float4*)(BT + (size_t)(cbase + t * 128 + row) * 192 + c8);
        }
        __syncthreads();

        float acc[4][4][4];
#pragma unroll
        for (int mi = 0; mi < 4; mi++)
#pragma unroll
            for (int nj = 0; nj < 4; nj++)
#pragma unroll
                for (int r = 0; r < 4; r++) acc[mi][nj][r] = 0.f;

#pragma unroll 1
        for (int ks = 0; ks < 6; ks++) {
            int ka = ks * 16 + aColL;
            int kb = ks * 16 + bColL;
            uint32_t af[4][4], bh[2][4], bl[2][4];
#pragma unroll
            for (int mi = 0; mi < 4; mi++) {
                uint32_t addr = aBase + (uint32_t)(((aRow + mi * 16) * SMN_LD + ka) * 2);
                LDSM_X4(af[mi][0], af[mi][1], af[mi][2], af[mi][3], addr);
            }
#pragma unroll
            for (int nj2 = 0; nj2 < 2; nj2++) {
                uint32_t addr = bBase + (uint32_t)(((bRow + nj2 * 16) * SMN_LD + kb) * 2);
                LDSM_X4(bh[nj2][0], bh[nj2][1], bh[nj2][2], bh[nj2][3], addr);
                addr = bBase + (uint32_t)(((bRow + nj2 * 16) * SMN_LD + kb + 96) * 2);
                LDSM_X4(bl[nj2][0], bl[nj2][1], bl[nj2][2], bl[nj2][3], addr);
            }
#pragma unroll
            for (int mi = 0; mi < 4; mi++)
#pragma unroll
                for (int nj = 0; nj < 4; nj++) {
                    MMA16816(acc[mi][nj], af[mi], bh[nj >> 1][(nj & 1) * 2],
                             bh[nj >> 1][(nj & 1) * 2 + 1]);
                    MMA16816(acc[mi][nj], af[mi], bl[nj >> 1][(nj & 1) * 2],
                             bl[nj >> 1][(nj & 1) * 2 + 1]);
                }
        }
#pragma unroll 1
        for (int ks = 0; ks < 6; ks++) {
            int ka = 96 + ks * 16 + aColL;
            int kb = ks * 16 + bColL;
            uint32_t af[4][4], bh[2][4];
#pragma unroll
            for (int mi = 0; mi < 4; mi++) {
                uint32_t addr = aBase + (uint32_t)(((aRow + mi * 16) * SMN_LD + ka) * 2);
                LDSM_X4(af[mi][0], af[mi][1], af[mi][2], af[mi][3], addr);
            }
#pragma unroll
            for (int nj2 = 0; nj2 < 2; nj2++) {
                uint32_t addr = bBase + (uint32_t)(((bRow + nj2 * 16) * SMN_LD + kb) * 2);
                LDSM_X4(bh[nj2][0], bh[nj2][1], bh[nj2][2], bh[nj2][3], addr);
            }
#pragma unroll
            for (int mi = 0; mi < 4; mi++)
#pragma unroll
                for (int nj = 0; nj < 4; nj++)
                    MMA16816(acc[mi][nj], af[mi], bh[nj >> 1][(nj & 1) * 2],
                             bh[nj >> 1][(nj & 1) * 2 + 1]);
        }

#pragma unroll
        for (int mi = 0; mi < 4; mi++) {
#pragma unroll
            for (int nj = 0; nj < 4; nj++) {
                mx[mi][0] = fmaxf(mx[mi][0], fmaxf(fabsf(acc[mi][nj][0]), fabsf(acc[mi][nj][1])));
                mx[mi][1] = fmaxf(mx[mi][1], fmaxf(fabsf(acc[mi][nj][2]), fabsf(acc[mi][nj][3])));
            }
        }
    }

#pragma unroll
    for (int mi = 0; mi < 4; mi++) {
        float m0 = mx[mi][0], m1 = mx[mi][1];
        m0 = fmaxf(m0, __shfl_xor_sync(0xffffffffu, m0, 1));
        m0 = fmaxf(m0, __shfl_xor_sync(0xffffffffu, m0, 2));
        m1 = fmaxf(m1, __shfl_xor_sync(0xffffffffu, m1, 1));
        m1 = fmaxf(m1, __shfl_xor_sync(0xffffffffu, m1, 2));
        if ((lane & 3) == 0) {
            int rbase = r0 + wm * 64 + mi * 16 + (lane >> 2);
            atomicMax(&denom[rbase], __float_as_int(m0));
            atomicMax(&denom[rbase + 8], __float_as_int(m1));
        }
    }
}

// ---------------- v @ k^T : 96-way split-K, single-shot load, one sync ----------
__global__ __launch_bounds__(256)
void vkt_part_kernel(const float* __restrict__ kqv, float* __restrict__ part) {
    const float* V  = kqv + 2 * H2;
    const float* Km = kqv;
    __shared__ float As[32][100];
    __shared__ float Bs[32][100];
    int tid = threadIdx.x, tx = tid & 15, ty = tid >> 4;
    int m0 = blockIdx.x * 32, n0 = blockIdx.y * 32;
    int kbase = blockIdx.z * VKT_CHUNK;

    // single-shot load: 32 rows x 24 float4 per matrix = 768 f4; x2 = 1536; 6/thread
#pragma unroll
    for (int t = 0; t < 6; t++) {
        int e = tid + t * 256;
        int mat = e >= 768;
        int idx = mat ? (e - 768) : e;
        int m = idx / 24, c4 = (idx % 24) * 4;
        const float* src = mat ? Km + (size_t)(n0 + m) * KQVN
                               : V + (size_t)(m0 + m) * KQVN;
        float4 v = *(const float4*)(src + kbase + c4);
        float* dst = mat ? &Bs[m][c4] : &As[m][c4];
        dst[0] = v.x; dst[1] = v.y; dst[2] = v.z; dst[3] = v.w;
    }
    __syncthreads();

    float a00 = 0, a01 = 0, a10 = 0, a11 = 0;
#pragma unroll 4
    for (int kk = 0; kk < VKT_CHUNK; kk++) {
        float av0 = As[ty][kk],      av1 = As[ty + 16][kk];
        float bv0 = Bs[tx][kk],      bv1 = Bs[tx + 16][kk];
        a00 += av0 * bv0; a01 += av0 * bv1;
        a10 += av1 * bv0; a11 += av1 * bv1;
    }
    float* p = part + blockIdx.z * (Hs * Hs);
    p[(m0 + ty) * Hs + (n0 + tx)]           = a00;
    p[(m0 + ty) * Hs + (n0 + tx + 16)]      = a01;
    p[(m0 + ty + 16) * Hs + (n0 + tx)]      = a10;
    p[(m0 + ty + 16) * Hs + (n0 + tx + 16)] = a11;
}

__global__ void vkt_reduce_kernel(const float* __restrict__ part, float* __restrict__ vkt) {
    int idx = blockIdx.x * blockDim.x + threadIdx.x;
    if (idx < Hs * Hs) {
        float s = 0.f;
#pragma unroll
        for (int c = 0; c < VKT_SPLIT; c++) s += part[c * (Hs * Hs) + idx];
        vkt[idx] = s;
    }
}

// ---------------- C = f @ C_prev + i @ vkT   (96x96), + split ----------------
__global__ void c_kernel(const float* __restrict__ f, const float* __restrict__ i_,
                         const float* __restrict__ C_prev, const float* __restrict__ vkt,
                         float* __restrict__ outC, unsigned short* __restrict__ Cs_u16) {
    __shared__ float fs[Hs], is[Hs];
    int b = blockIdx.x, n = threadIdx.x;
    fs[n] = f[b * Hs + n];
    is[n] = i_[b * Hs + n];
    __syncthreads();
    float acc = 0.f;
    for (int h = 0; h < Hs; h++)
        acc += fs[h] * C_prev[h * Hs + n] + is[h] * vkt[h * Hs + n];
    outC[b * Hs + n] = acc;
    __nv_bfloat16* Cs = (__nv_bfloat16*)Cs_u16;
    __nv_bfloat16 hi = __float2bfloat16(acc);
    Cs[b * 192 + n] = hi;
    Cs[b * 192 + 96 + n] = __float2bfloat16(acc - __bfloat162float(hi));
}

// ---------------- launch ----------------
extern "C" void kernel_launch(void* const* d_in, const int* in_sizes, int n_in,
                              void* d_out, int out_size) {
    const float* x      = (const float*)d_in[0];
    const float* h_prev = (const float*)d_in[1];
    const float* C_prev = (const float*)d_in[2];
    const float* n_prev = (const float*)d_in[3];
    const float* wix_w  = (const float*)d_in[4];
    const float* wix_b  = (const float*)d_in[5];
    const float* wfx_w  = (const float*)d_in[6];
    const float* wfx_b  = (const float*)d_in[7];
    const float* Wox_w  = (const float*)d_in[8];
    const float* Wox_b  = (const float*)d_in[9];
    const float* Wkqv_w = (const float*)d_in[10];
    const float* Wkqv_b = (const float*)d_in[11];

    float* out   = (float*)d_out;
    float* out_h = out;                       // [96, 9216]
    float* out_C = out + Bsz * H2;            // [96, 96]
    float* out_n = out_C + Bsz * Hs;          // [96, 9216]

    float *p_i, *p_f, *p_o, *p_kqv, *p_part, *p_vkt;
    int* p_denom;
    unsigned short *p_AT, *p_BT, *p_npT, *p_kT, *p_xs, *p_hps, *p_fis, *p_Cs;
    cudaGetSymbolAddress((void**)&p_i,     g_i);
    cudaGetSymbolAddress((void**)&p_f,     g_f);
    cudaGetSymbolAddress((void**)&p_o,     g_o);
    cudaGetSymbolAddress((void**)&p_kqv,   g_kqv);
    cudaGetSymbolAddress((void**)&p_part,  g_vkT_part);
    cudaGetSymbolAddress((void**)&p_vkt,   g_vkT);
    cudaGetSymbolAddress((void**)&p_denom, g_denom);
    cudaGetSymbolAddress((void**)&p_AT,    g_AT);
    cudaGetSymbolAddress((void**)&p_BT,    g_BT);
    cudaGetSymbolAddress((void**)&p_npT,   g_npT);
    cudaGetSymbolAddress((void**)&p_kT,    g_kT);
    cudaGetSymbolAddress((void**)&p_xs,    g_xs);
    cudaGetSymbolAddress((void**)&p_hps,   g_hps);
    cudaGetSymbolAddress((void**)&p_fis,   g_fis);
    cudaGetSymbolAddress((void**)&p_Cs,    g_Cs);

    const int DENOM_SMEM = 2 * 128 * SMN_LD * 2;                 // 102400
    const int PREB_SMEM  = (96 + 32) * 200 * 2;                  // 51200
    const int CONV_SMEM  = (96 * 72 + 64 * 72 + 64 * 192) * 2;   // 47616
    cudaFuncSetAttribute(denom_mma_kernel,
                         cudaFuncAttributeMaxDynamicSharedMemorySize, DENOM_SMEM);
    cudaFuncSetAttribute(hmma_preB<2>,
                         cudaFuncAttributeMaxDynamicSharedMemorySize, PREB_SMEM);
    cudaFuncSetAttribute(hmma_preB<3>,
                         cudaFuncAttributeMaxDynamicSharedMemorySize, PREB_SMEM);
    cudaFuncSetAttribute(hmma_conv_uber,
                         cudaFuncAttributeMaxDynamicSharedMemorySize, CONV_SMEM);

    // preamble: npT transpose-split | x/h splits + denom zero | gates (one launch)
    preamble_kernel<<<3096, 256>>>(x, h_prev, n_prev, wix_w, wix_b, wfx_w, wfx_b,
                                   p_xs, p_hps, p_npT, p_i, p_f, p_fis, p_denom);

    // kqv (+ fused kT/qT splits) and o in ONE launch
    hmma_conv_uber<<<576, 256, CONV_SMEM>>>(p_xs, p_hps, Wkqv_w, Wkqv_b, Wox_w, Wox_b,
                                            p_kqv, p_o, p_kT, p_BT);

    // n = f @ n_prev + i @ k  (HMMA, N32 tiles) + fused AT transpose-split
    hmma_preB<2><<<H2 / 32, 256, PREB_SMEM>>>(p_fis, 384, p_npT, p_kT, 2,
                                              nullptr, nullptr, out_n, H2, p_AT);

    // vkT = v @ k^T  (96-way split-K, single-shot load)
    vkt_part_kernel<<<dim3(3, 3, VKT_SPLIT), 256>>>(p_kqv, p_part);
    vkt_reduce_kernel<<<36, 256>>>(p_part, p_vkt);

    // C = f @ C_prev + i @ vkT (+ split)
    c_kernel<<<Bsz, Hs>>>(p_f, p_i, C_prev, p_vkt, out_C, p_Cs);

    // denom = max_c |n^T q|  (A-resident, 6 B tiles per CTA)
    denom_mma_kernel<<<dim3(72, 12), 256, DENOM_SMEM>>>(p_AT, p_BT, p_denom);

    // h = o * (C @ q) / denom  (N32 tiles)
    hmma_preB<3><<<H2 / 32, 256, PREB_SMEM>>>(p_Cs, 192, p_BT, nullptr, 1,
                                              p_o, p_denom, out_h, H2, nullptr);
}

// round 16
// speedup vs baseline: 1.2142x; 1.0093x over previous
#include <cuda_runtime.h>
#include <cuda_bf16.h>
#include <math.h>
#include <stdint.h>

#define Bsz  96
#define Hs   96
#define Ds   768
#define H2   9216
#define KQVN 27648
#define VKT_SPLIT 96
#define VKT_CHUNK 96

// ---------------- scratch (static device memory, no allocation) ----------------
__device__ float g_i[Bsz * Hs];
__device__ float g_f[Bsz * Hs];
__device__ float g_o[Bsz * H2];
__device__ float g_kqv[Bsz * KQVN];          // [96, 27648] : k | q | v (k pre-scaled by 1/96)
__device__ float g_vkT_part[VKT_SPLIT * Hs * Hs];
__device__ float g_vkT[Hs * Hs];
__device__ int   g_denom[H2];                // float bits via atomicMax on non-neg floats
// pre-split bf16 operands
__device__ unsigned short g_AT[H2 * 192];    // n^T  [9216, 96hi|96lo]
__device__ unsigned short g_BT[H2 * 192];    // q^T
__device__ unsigned short g_npT[H2 * 192];   // n_prev^T
__device__ unsigned short g_kT[H2 * 192];    // k^T
__device__ unsigned short g_xs[Bsz * 1536];  // x split [96, 768hi|768lo]
__device__ unsigned short g_hps[Bsz * 192];  // h_prev split
__device__ unsigned short g_fis[Bsz * 384];  // [f hi|lo | i hi|lo]
__device__ unsigned short g_Cs[Bsz * 192];   // C split

// ---------------- helpers ----------------
__device__ __forceinline__ uint32_t smem_u32(const void* p) {
    uint32_t a;
    asm("{ .reg .u64 t; cvta.to.shared.u64 t, %1; cvt.u32.u64 %0, t; }" : "=r"(a) : "l"(p));
    return a;
}
#define LDSM_X4(r0, r1, r2, r3, addr) \
    asm volatile("ldmatrix.sync.aligned.m8n8.x4.shared.b16 {%0,%1,%2,%3}, [%4];" \
                 : "=r"(r0), "=r"(r1), "=r"(r2), "=r"(r3) : "r"(addr))
#define MMA16816(d, a, b0, b1) \
    asm volatile("mma.sync.aligned.m16n8k16.row.col.f32.bf16.bf16.f32 " \
                 "{%0,%1,%2,%3},{%4,%5,%6,%7},{%8,%9},{%0,%1,%2,%3};" \
                 : "+f"((d)[0]), "+f"((d)[1]), "+f"((d)[2]), "+f"((d)[3]) \
                 : "r"((a)[0]), "r"((a)[1]), "r"((a)[2]), "r"((a)[3]), "r"(b0), "r"(b1))

// ================= merged preamble: npT transpose-split | x/h splits | gates ======
__global__ __launch_bounds__(256)
void preamble_kernel(const float* __restrict__ x, const float* __restrict__ hp,
                     const float* __restrict__ n_prev,
                     const float* __restrict__ wix_w, const float* __restrict__ wix_b,
                     const float* __restrict__ wfx_w, const float* __restrict__ wfx_b,
                     unsigned short* __restrict__ xs_u16, unsigned short* __restrict__ hps_u16,
                     unsigned short* __restrict__ npT_u16,
                     float* __restrict__ gi, float* __restrict__ gf,
                     unsigned short* __restrict__ fis_u16,
                     int* __restrict__ denom) {
    __shared__ float t[32][68];
    int blk = blockIdx.x, tid = threadIdx.x;
    if (blk < 432) {
        __nv_bfloat16* dst = (__nv_bfloat16*)npT_u16;
        int bx = blk % 144, by = blk / 144;
        int r0 = bx * 64, j0 = by * 32;
#pragma unroll
        for (int it = 0; it < 2; it++) {
            int e = tid + it * 256;
            int jj = e >> 4, c4 = (e & 15) * 4;
            float4 v = *(const float4*)(n_prev + (size_t)(j0 + jj) * H2 + r0 + c4);
            *(float4*)&t[jj][c4] = v;
        }
        __syncthreads();
#pragma unroll
        for (int it = 0; it < 2; it++) {
            int e = tid + it * 256;
            int rr = e >> 3, q = e & 7;
            int isLo = q >> 2, jb = (q & 3) * 8;
            __nv_bfloat16 vals[8];
#pragma unroll
            for (int w = 0; w < 8; w++) {
                float f = t[jb + w][rr];
                __nv_bfloat16 hi = __float2bfloat16(f);
                vals[w] = isLo ? __float2bfloat16(f - __bfloat162float(hi)) : hi;
            }
            *(uint4*)(dst + (size_t)(r0 + rr) * 192 + isLo * 96 + j0 + jb) = *(uint4*)vals;
        }
    } else if (blk < 792) {
        int b2 = blk - 432;
        if (b2 < 288) {
            __nv_bfloat16* xs = (__nv_bfloat16*)xs_u16;
            int e = b2 * 256 + tid;
            int r = e / Ds, c = e % Ds;
            float v = x[e];
            __nv_bfloat16 hi = __float2bfloat16(v);
            xs[(size_t)r * 1536 + c] = hi;
            xs[(size_t)r * 1536 + Ds + c] = __float2bfloat16(v - __bfloat162float(hi));
        } else if (b2 < 324) {
            __nv_bfloat16* hs = (__nv_bfloat16*)hps_u16;
            int e = (b2 - 288) * 256 + tid;
            int r = e / Hs, c = e % Hs;
            float v = hp[e];
            __nv_bfloat16 hi = __float2bfloat16(v);
            hs[(size_t)r * 192 + c] = hi;
            hs[(size_t)r * 192 + Hs + c] = __float2bfloat16(v - __bfloat162float(hi));
        } else {
            int e = (b2 - 324) * 256 + tid;
            denom[e] = 0;
        }
    } else {
        int gw = (blk - 792) * 8 + (tid >> 5);
        int lane = tid & 31;
        int isI = gw < Bsz * Hs;
        int o = isI ? gw : gw - Bsz * Hs;
        int b = o / Hs, n = o % Hs;
        const float* a = isI ? x + (size_t)b * Ds : hp + (size_t)b * Hs;
        const float* w = isI ? wix_w + (size_t)n * Ds : wfx_w + (size_t)n * Hs;
        int K = isI ? Ds : Hs;
        float acc = 0.f;
        for (int k = lane; k < K; k += 32) acc += a[k] * w[k];
#pragma unroll
        for (int off = 16; off; off >>= 1) acc += __shfl_xor_sync(0xffffffffu, acc, off);
        if (lane == 0) {
            float v = expf(acc + (isI ? wix_b[n] : wfx_b[n]));
            (isI ? gi : gf)[o] = v;
            __nv_bfloat16* fis = (__nv_bfloat16*)fis_u16;
            __nv_bfloat16 hi = __float2bfloat16(v);
            int base = b * 384 + (isI ? 192 : 0) + n;
            fis[base] = hi;
            fis[base + 96] = __float2bfloat16(v - __bfloat162float(hi));
        }
    }
}

// ======== UBER convA: kqv (blocks 0..431) + o (blocks 432..575) in one launch ====
__global__ __launch_bounds__(256, 3)
void hmma_conv_uber(const unsigned short* __restrict__ xs_u16,
                    const unsigned short* __restrict__ hps_u16,
                    const float* __restrict__ Wkqv, const float* __restrict__ Wkqv_b,
                    const float* __restrict__ Wox,  const float* __restrict__ Wox_b,
                    float* __restrict__ kqv_out, float* __restrict__ o_out,
                    unsigned short* __restrict__ kT_u16,
                    unsigned short* __restrict__ qT_u16) {
    const bool isKqv = blockIdx.x < 432;
    const __nv_bfloat16* Asp = (const __nv_bfloat16*)(isKqv ? xs_u16 : hps_u16);
    const int KTOT = isKqv ? Ds : Hs;
    const float* Bm   = isKqv ? Wkqv : Wox;
    const float* bias = isKqv ? Wkqv_b : Wox_b;
    float* out = isKqv ? kqv_out : o_out;
    const int ldo = isKqv ? KQVN : H2;
    const int n0 = (isKqv ? blockIdx.x : (blockIdx.x - 432)) * 64;
    const int NC = KTOT / 32;

    extern __shared__ __nv_bfloat16 dyn[];
    __nv_bfloat16* sAr = dyn;                        // [96][72]
    __nv_bfloat16* sBr = dyn + 96 * 72;              // [64][72]
    __nv_bfloat16* sT  = dyn + 96 * 72 + 64 * 72;    // [64][192] (kqv only)
    int tid = threadIdx.x, warp = tid >> 5, lane = tid & 31;
    int wm = warp & 1, wn = warp >> 1;
    float acc[3][2][4] = {};

    uint4 aPre[3];
    float4 bPre[2];

#pragma unroll 1
    for (int c = 0; c < NC; c++) {
        if (c == 0) {
#pragma unroll
            for (int t = 0; t < 3; t++) {
                int e = tid + t * 256;
                int r = e >> 3, col = (e & 7) * 8;
                int sc = (col < 32) ? col : (KTOT + col - 32);
                aPre[t] = *(const uint4*)(Asp + (size_t)r * (2 * KTOT) + sc);
            }
#pragma unroll
            for (int t = 0; t < 2; t++) {
                int e = tid + t * 256;
                int r = e >> 3, g = e & 7;
                bPre[t] = *(const float4*)(Bm + (size_t)(n0 + r) * KTOT + g * 4);
            }
        }
        __syncthreads();
#pragma unroll
        for (int t = 0; t < 3; t++) {
            int e = tid + t * 256;
            int r = e >> 3, col = (e & 7) * 8;
            *(uint4*)&sAr[r * 72 + col] = aPre[t];
        }
#pragma unroll
        for (int t = 0; t < 2; t++) {
            int e = tid + t * 256;
            int r = e >> 3, g = e & 7;
            float vv[4] = {bPre[t].x, bPre[t].y, bPre[t].z, bPre[t].w};
            __nv_bfloat16 hb[4];
            float lo[4];
#pragma unroll
            for (int j = 0; j < 4; j++) {
                hb[j] = __float2bfloat16(vv[j]);
                lo[j] = vv[j] - __bfloat162float(hb[j]);
            }
            // packed 4-byte stores (2 bf16 each)
            __nv_bfloat162* p0 = (__nv_bfloat162*)&sBr[r * 72 + g * 4];
            p0[0] = __nv_bfloat162(hb[0], hb[1]);
            p0[1] = __nv_bfloat162(hb[2], hb[3]);
            __nv_bfloat162* p1 = (__nv_bfloat162*)&sBr[r * 72 + 32 + g * 4];
            p1[0] = __floats2bfloat162_rn(lo[0], lo[1]);
            p1[1] = __floats2bfloat162_rn(lo[2], lo[3]);
        }
        if (c + 1 < NC) {
            int k0 = (c + 1) * 32;
#pragma unroll
            for (int t = 0; t < 3; t++) {
                int e = tid + t * 256;
                int r = e >> 3, col = (e & 7) * 8;
                int sc = (col < 32) ? (k0 + col) : (KTOT + k0 + col - 32);
                aPre[t] = *(const uint4*)(Asp + (size_t)r * (2 * KTOT) + sc);
            }
#pragma unroll
            for (int t = 0; t < 2; t++) {
                int e = tid + t * 256;
                int r = e >> 3, g = e & 7;
                bPre[t] = *(const float4*)(Bm + (size_t)(n0 + r) * KTOT + k0 + g * 4);
            }
        }
        __syncthreads();
        uint32_t aBase = smem_u32(sAr);
        uint32_t bBase = smem_u32(sBr);
        int aRow = wm * 48 + (lane & 15);
        int aCol = (lane >> 4) << 3;
        int bRow = wn * 16 + (lane & 7) + ((lane >> 4) << 3);
        int bCol = ((lane >> 3) & 1) << 3;
#pragma unroll
        for (int ks = 0; ks < 2; ks++) {
            int ka = ks * 16 + aCol, kb = ks * 16 + bCol;
            uint32_t af[3][4], bh[4], bl[4];
#pragma unroll
            for (int mi = 0; mi < 3; mi++) {
                uint32_t addr = aBase + (uint32_t)(((aRow + mi * 16) * 72 + ka) * 2);
                LDSM_X4(af[mi][0], af[mi][1], af[mi][2], af[mi][3], addr);
            }
            {
                uint32_t addr = bBase + (uint32_t)((bRow * 72 + kb) * 2);
                LDSM_X4(bh[0], bh[1], bh[2], bh[3], addr);
                addr = bBase + (uint32_t)((bRow * 72 + kb + 32) * 2);
                LDSM_X4(bl[0], bl[1], bl[2], bl[3], addr);
            }
#pragma unroll
            for (int mi = 0; mi < 3; mi++)
#pragma unroll
                for (int nj = 0; nj < 2; nj++) {
                    MMA16816(acc[mi][nj], af[mi], bh[nj * 2], bh[nj * 2 + 1]);
                    MMA16816(acc[mi][nj], af[mi], bl[nj * 2], bl[nj * 2 + 1]);
                }
        }
#pragma unroll
        for (int ks = 0; ks < 2; ks++) {
            int ka = 32 + ks * 16 + aCol, kb = ks * 16 + bCol;
            uint32_t af[3][4], bh[4];
#pragma unroll
            for (int mi = 0; mi < 3; mi++) {
                uint32_t addr = aBase + (uint32_t)(((aRow + mi * 16) * 72 + ka) * 2);
                LDSM_X4(af[mi][0], af[mi][1], af[mi][2], af[mi][3], addr);
            }
            {
                uint32_t addr = bBase + (uint32_t)((bRow * 72 + kb) * 2);
                LDSM_X4(bh[0], bh[1], bh[2], bh[3], addr);
            }
#pragma unroll
            for (int mi = 0; mi < 3; mi++)
#pragma unroll
                for (int nj = 0; nj < 2; nj++)
                    MMA16816(acc[mi][nj], af[mi], bh[nj * 2], bh[nj * 2 + 1]);
        }
    }
    const bool doT = isKqv && (n0 < 2 * H2);
#pragma unroll
    for (int mi = 0; mi < 3; mi++)
#pragma unroll
        for (int nj = 0; nj < 2; nj++)
#pragma unroll
            for (int r = 0; r < 4; r++) {
                int m = wm * 48 + mi * 16 + (lane >> 2) + ((r >> 1) * 8);
                int gl = wn * 16 + nj * 8 + (lane & 3) * 2 + (r & 1);
                int gn = n0 + gl;
                float v = acc[mi][nj][r] + bias[gn];
                if (isKqv) { if (gn < H2) v *= (1.0f / 96.0f); }
                else       v = 1.0f / (1.0f + expf(-v));
                out[(size_t)m * ldo + gn] = v;
                if (doT) {
                    __nv_bfloat16 hi = __float2bfloat16(v);
                    sT[gl * 192 + m] = hi;
                    sT[gl * 192 + 96 + m] = __float2bfloat16(v - __bfloat162float(hi));
                }
            }
    if (doT) {
        __syncthreads();
        __nv_bfloat16* dstT = (__nv_bfloat16*)((n0 < H2) ? kT_u16 : qT_u16);
        int cb = (n0 < H2) ? n0 : (n0 - H2);
        for (int e = tid; e < 64 * 24; e += 256) {
            int row = e / 24, g = e % 24;
            *(uint4*)(dstT + (size_t)(cb + row) * 192 + g * 8) = *(uint4*)(sT + row * 192 + g * 8);
        }
    }
}

// ======== Variant B: HMMA NT GEMM, N-tile 32, pre-split bf16 B [N, 192] ========
// EPI 2: n (+ fused AT transpose-split), EPI 3: h = o * acc / denom
template <int EPI>
__global__ __launch_bounds__(256, 3)
void hmma_preB(const unsigned short* __restrict__ Asp_u16, int lda,
               const unsigned short* __restrict__ B1_u16,
               const unsigned short* __restrict__ B2_u16,
               int nseg,
               const float* __restrict__ omat,
               const int* __restrict__ denomBits,
               float* __restrict__ out, int ldo,
               unsigned short* __restrict__ AT_u16) {
    const __nv_bfloat16* Asp = (const __nv_bfloat16*)Asp_u16;
    extern __shared__ __nv_bfloat16 dsm[];
    __nv_bfloat16* sA = dsm;             // [96][200]
    __nv_bfloat16* sB = dsm + 96 * 200;  // [32][200]
    int tid = threadIdx.x, warp = tid >> 5, lane = tid & 31;
    int n0 = blockIdx.x * 32;
    int wm = warp & 1, wn = warp >> 1;
    float acc[3][4] = {};

#pragma unroll 1
    for (int s = 0; s < nseg; s++) {
        const __nv_bfloat16* Bseg =
            (s == 0) ? (const __nv_bfloat16*)B1_u16 : (const __nv_bfloat16*)B2_u16;
        __syncthreads();
        for (int e = tid; e < 96 * 24; e += 256) {
            int r = e / 24, g = e % 24;
            *(uint4*)(sA + r * 200 + g * 8) =
                *(const uint4*)(Asp + (size_t)r * lda + s * 192 + g * 8);
        }
        for (int e = tid; e < 32 * 24; e += 256) {
            int r = e / 24, g = e % 24;
            *(uint4*)(sB + r * 200 + g * 8) =
                *(const uint4*)(Bseg + (size_t)(n0 + r) * 192 + g * 8);
        }
        __syncthreads();
        uint32_t aBase = smem_u32(sA), bBase = smem_u32(sB);
        int aRow = wm * 48 + (lane & 15), aCol = (lane >> 4) << 3;
        int bRowOff = (wn * 8 + (lane & 7)) * 200 + ((lane >> 3) << 3);
#pragma unroll
        for (int ks2 = 0; ks2 < 3; ks2++) {
            uint32_t bh[4], bl[4];
            {
                uint32_t addr = bBase + (uint32_t)((bRowOff + ks2 * 32) * 2);
                LDSM_X4(bh[0], bh[1], bh[2], bh[3], addr);
                addr = bBase + (uint32_t)((bRowOff + 96 + ks2 * 32) * 2);
                LDSM_X4(bl[0], bl[1], bl[2], bl[3], addr);
            }
#pragma unroll
            for (int sub = 0; sub < 2; sub++) {
                int ka = ks2 * 32 + sub * 16 + aCol;
                uint32_t afh[3][4], afl[3][4];
#pragma unroll
                for (int mi = 0; mi < 3; mi++) {
                    uint32_t addr = aBase + (uint32_t)(((aRow + mi * 16) * 200 + ka) * 2);
                    LDSM_X4(afh[mi][0], afh[mi][1], afh[mi][2], afh[mi][3], addr);
                    addr = aBase + (uint32_t)(((aRow + mi * 16) * 200 + 96 + ka) * 2);
                    LDSM_X4(afl[mi][0], afl[mi][1], afl[mi][2], afl[mi][3], addr);
                }
#pragma unroll
                for (int mi = 0; mi < 3; mi++) {
                    MMA16816(acc[mi], afh[mi], bh[sub * 2], bh[sub * 2 + 1]);
                    MMA16816(acc[mi], afh[mi], bl[sub * 2], bl[sub * 2 + 1]);
                    MMA16816(acc[mi], afl[mi], bh[sub * 2], bh[sub * 2 + 1]);
                }
            }
        }
    }
    if (EPI == 2) __syncthreads();
#pragma unroll
    for (int mi = 0; mi < 3; mi++)
#pragma unroll
        for (int r = 0; r < 4; r++) {
            int m = wm * 48 + mi * 16 + (lane >> 2) + ((r >> 1) * 8);
            int gl = wn * 8 + (lane & 3) * 2 + (r & 1);
            int gn = n0 + gl;
            float v = acc[mi][r];
            if (EPI == 3)
                v = omat[(size_t)m * H2 + gn] * v / __int_as_float(denomBits[gn]);
            out[(size_t)m * ldo + gn] = v;
            if (EPI == 2) {
                __nv_bfloat16 hi = __float2bfloat16(v);
                sA[gl * 192 + m] = hi;
                sA[gl * 192 + 96 + m] = __float2bfloat16(v - __bfloat162float(hi));
            }
        }
    if (EPI == 2) {
        __syncthreads();
        __nv_bfloat16* AT = (__nv_bfloat16*)AT_u16;
        for (int e = tid; e < 32 * 24; e += 256) {
            int row = e / 24, g = e % 24;
            *(uint4*)(AT + (size_t)(n0 + row) * 192 + g * 8) = *(uint4*)(sA + row * 192 + g * 8);
        }
    }
}

// ================= HMMA denom: A-resident, 6 B tiles per CTA =================
#define SMN_LD 200

__global__ __launch_bounds__(256, 2)
void denom_mma_kernel(const unsigned short* __restrict__ AT,
                      const unsigned short* __restrict__ BT,
                      int* __restrict__ denom) {
    extern __shared__ __align__(16) unsigned short sm[];
    unsigned short* sA = sm;
    unsigned short* sB = sm + 128 * SMN_LD;
    int tid = threadIdx.x;
    int r0 = blockIdx.x * 128;
    int cbase = blockIdx.y * 768;

    for (int e = tid; e < 128 * 24; e += 256) {
        int row = e / 24, c8 = (e % 24) * 8;
        *(float4*)(sA + row * SMN_LD + c8) = *(const float4*)(AT + (size_t)(r0 + row) * 192 + c8);
    }

    int warp = tid >> 5, lane = tid & 31;
    int wm = warp & 1, wn = warp >> 1;
    uint32_t aBase = smem_u32(sA);
    uint32_t bBase = smem_u32(sB);

    int aRow = wm * 64 + (lane & 15);
    int aColL = (lane >> 4) << 3;
    int bRow = wn * 32 + (lane & 7) + ((lane >> 4) << 3);
    int bColL = ((lane >> 3) & 1) << 3;

    float mx[4][2];
#pragma unroll
    for (int mi = 0; mi < 4; mi++) { mx[mi][0] = 0.f; mx[mi][1] = 0.f; }

#pragma unroll 1
    for (int t = 0; t < 6; t++) {
        __syncthreads();
        for (int e = tid; e < 128 * 24; e += 256) {
            int row = e / 24, c8 = (e % 24) * 8;
            *(float4*)(sB + row * SMN_LD + c8) =
                *(const float4*)(BT + (size_t)(cbase + t * 128 + row) * 192 + c8);
        }
        __syncthreads();

        float acc[4][4][4];
#pragma unroll
        for (int mi = 0; mi < 4; mi++)
#pragma unroll
            for (int nj = 0; nj < 4; nj++)
#pragma unroll
                for (int r = 0; r < 4; r++) acc[mi][nj][r] = 0.f;

#pragma unroll 1
        for (int ks = 0; ks < 6; ks++) {
            int ka = ks * 16 + aColL;
            int kb = ks * 16 + bColL;
            uint32_t af[4][4], bh[2][4], bl[2][4];
#pragma unroll
            for (int mi = 0; mi < 4; mi++) {
                uint32_t addr = aBase + (uint32_t)(((aRow + mi * 16) * SMN_LD + ka) * 2);
                LDSM_X4(af[mi][0], af[mi][1], af[mi][2], af[mi][3], addr);
            }
#pragma unroll
            for (int nj2 = 0; nj2 < 2; nj2++) {
                uint32_t addr = bBase + (uint32_t)(((bRow + nj2 * 16) * SMN_LD + kb) * 2);
                LDSM_X4(bh[nj2][0], bh[nj2][1], bh[nj2][2], bh[nj2][3], addr);
                addr = bBase + (uint32_t)(((bRow + nj2 * 16) * SMN_LD + kb + 96) * 2);
                LDSM_X4(bl[nj2][0], bl[nj2][1], bl[nj2][2], bl[nj2][3], addr);
            }
#pragma unroll
            for (int mi = 0; mi < 4; mi++)
#pragma unroll
                for (int nj = 0; nj < 4; nj++) {
                    MMA16816(acc[mi][nj], af[mi], bh[nj >> 1][(nj & 1) * 2],
                             bh[nj >> 1][(nj & 1) * 2 + 1]);
                    MMA16816(acc[mi][nj], af[mi], bl[nj >> 1][(nj & 1) * 2],
                             bl[nj >> 1][(nj & 1) * 2 + 1]);
                }
        }
#pragma unroll 1
        for (int ks = 0; ks < 6; ks++) {
            int ka = 96 + ks * 16 + aColL;
            int kb = ks * 16 + bColL;
            uint32_t af[4][4], bh[2][4];
#pragma unroll
            for (int mi = 0; mi < 4; mi++) {
                uint32_t addr = aBase + (uint32_t)(((aRow + mi * 16) * SMN_LD + ka) * 2);
                LDSM_X4(af[mi][0], af[mi][1], af[mi][2], af[mi][3], addr);
            }
#pragma unroll
            for (int nj2 = 0; nj2 < 2; nj2++) {
                uint32_t addr = bBase + (uint32_t)(((bRow + nj2 * 16) * SMN_LD + kb) * 2);
                LDSM_X4(bh[nj2][0], bh[nj2][1], bh[nj2][2], bh[nj2][3], addr);
            }
#pragma unroll
            for (int mi = 0; mi < 4; mi++)
#pragma unroll
                for (int nj = 0; nj < 4; nj++)
                    MMA16816(acc[mi][nj], af[mi], bh[nj >> 1][(nj & 1) * 2],
                             bh[nj >> 1][(nj & 1) * 2 + 1]);
        }

#pragma unroll
        for (int mi = 0; mi < 4; mi++) {
#pragma unroll
            for (int nj = 0; nj < 4; nj++) {
                mx[mi][0] = fmaxf(mx[mi][0], fmaxf(fabsf(acc[mi][nj][0]), fabsf(acc[mi][nj][1])));
                mx[mi][1] = fmaxf(mx[mi][1], fmaxf(fabsf(acc[mi][nj][2]), fabsf(acc[mi][nj][3])));
            }
        }
    }

#pragma unroll
    for (int mi = 0; mi < 4; mi++) {
        float m0 = mx[mi][0], m1 = mx[mi][1];
        m0 = fmaxf(m0, __shfl_xor_sync(0xffffffffu, m0, 1));
        m0 = fmaxf(m0, __shfl_xor_sync(0xffffffffu, m0, 2));
        m1 = fmaxf(m1, __shfl_xor_sync(0xffffffffu, m1, 1));
        m1 = fmaxf(m1, __shfl_xor_sync(0xffffffffu, m1, 2));
        if ((lane & 3) == 0) {
            int rbase = r0 + wm * 64 + mi * 16 + (lane >> 2);
            atomicMax(&denom[rbase], __float_as_int(m0));
            atomicMax(&denom[rbase + 8], __float_as_int(m1));
        }
    }
}

// ---------------- v @ k^T : 96-way split-K, single-shot load, float4 LDS ----------
__global__ __launch_bounds__(256)
void vkt_part_kernel(const float* __restrict__ kqv, float* __restrict__ part) {
    const float* V  = kqv + 2 * H2;
    const float* Km = kqv;
    __shared__ float As[32][100];
    __shared__ float Bs[32][100];
    int tid = threadIdx.x, tx = tid & 15, ty = tid >> 4;
    int m0 = blockIdx.x * 32, n0 = blockIdx.y * 32;
    int kbase = blockIdx.z * VKT_CHUNK;

    // single-shot load: 32 rows x 24 float4 per matrix = 768 f4; x2 = 1536; 6/thread
#pragma unroll
    for (int t = 0; t < 6; t++) {
        int e = tid + t * 256;
        int mat = e >= 768;
        int idx = mat ? (e - 768) : e;
        int m = idx / 24, c4 = (idx % 24) * 4;
        const float* src = mat ? Km + (size_t)(n0 + m) * KQVN
                               : V + (size_t)(m0 + m) * KQVN;
        float4 v = *(const float4*)(src + kbase + c4);
        float* dst = mat ? &Bs[m][c4] : &As[m][c4];
        dst[0] = v.x; dst[1] = v.y; dst[2] = v.z; dst[3] = v.w;
    }
    __syncthreads();

    float a00 = 0, a01 = 0, a10 = 0, a11 = 0;
#pragma unroll
    for (int kk = 0; kk < VKT_CHUNK; kk += 4) {
        float4 av0 = *(const float4*)&As[ty][kk];
        float4 av1 = *(const float4*)&As[ty + 16][kk];
        float4 bv0 = *(const float4*)&Bs[tx][kk];
        float4 bv1 = *(const float4*)&Bs[tx + 16][kk];
        a00 += av0.x * bv0.x + av0.y * bv0.y + av0.z * bv0.z + av0.w * bv0.w;
        a01 += av0.x * bv1.x + av0.y * bv1.y + av0.z * bv1.z + av0.w * bv1.w;
        a10 += av1.x * bv0.x + av1.y * bv0.y + av1.z * bv0.z + av1.w * bv0.w;
        a11 += av1.x * bv1.x + av1.y * bv1.y + av1.z * bv1.z + av1.w * bv1.w;
    }
    float* p = part + blockIdx.z * (Hs * Hs);
    p[(m0 + ty) * Hs + (n0 + tx)]           = a00;
    p[(m0 + ty) * Hs + (n0 + tx + 16)]      = a01;
    p[(m0 + ty + 16) * Hs + (n0 + tx)]      = a10;
    p[(m0 + ty + 16) * Hs + (n0 + tx + 16)] = a11;
}

__global__ void vkt_reduce_kernel(const float* __restrict__ part, float* __restrict__ vkt) {
    int idx = blockIdx.x * blockDim.x + threadIdx.x;
    if (idx < Hs * Hs) {
        float s = 0.f;
#pragma unroll
        for (int c = 0; c < VKT_SPLIT; c++) s += part[c * (Hs * Hs) + idx];
        vkt[idx] = s;
    }
}

// ---------------- C = f @ C_prev + i @ vkT   (96x96), + split ----------------
__global__ void c_kernel(const float* __restrict__ f, const float* __restrict__ i_,
                         const float* __restrict__ C_prev, const float* __restrict__ vkt,
                         float* __restrict__ outC, unsigned short* __restrict__ Cs_u16) {
    __shared__ float fs[Hs], is[Hs];
    int b = blockIdx.x, n = threadIdx.x;
    fs[n] = f[b * Hs + n];
    is[n] = i_[b * Hs + n];
    __syncthreads();
    float acc = 0.f;
    for (int h = 0; h < Hs; h++)
        acc += fs[h] * C_prev[h * Hs + n] + is[h] * vkt[h * Hs + n];
    outC[b * Hs + n] = acc;
    __nv_bfloat16* Cs = (__nv_bfloat16*)Cs_u16;
    __nv_bfloat16 hi = __float2bfloat16(acc);
    Cs[b * 192 + n] = hi;
    Cs[b * 192 + 96 + n] = __float2bfloat16(acc - __bfloat162float(hi));
}

// ---------------- launch ----------------
extern "C" void kernel_launch(void* const* d_in, const int* in_sizes, int n_in,
                              void* d_out, int out_size) {
    const float* x      = (const float*)d_in[0];
    const float* h_prev = (const float*)d_in[1];
    const float* C_prev = (const float*)d_in[2];
    const float* n_prev = (const float*)d_in[3];
    const float* wix_w  = (const float*)d_in[4];
    const float* wix_b  = (const float*)d_in[5];
    const float* wfx_w  = (const float*)d_in[6];
    const float* wfx_b  = (const float*)d_in[7];
    const float* Wox_w  = (const float*)d_in[8];
    const float* Wox_b  = (const float*)d_in[9];
    const float* Wkqv_w = (const float*)d_in[10];
    const float* Wkqv_b = (const float*)d_in[11];

    float* out   = (float*)d_out;
    float* out_h = out;                       // [96, 9216]
    float* out_C = out + Bsz * H2;            // [96, 96]
    float* out_n = out_C + Bsz * Hs;          // [96, 9216]

    float *p_i, *p_f, *p_o, *p_kqv, *p_part, *p_vkt;
    int* p_denom;
    unsigned short *p_AT, *p_BT, *p_npT, *p_kT, *p_xs, *p_hps, *p_fis, *p_Cs;
    cudaGetSymbolAddress((void**)&p_i,     g_i);
    cudaGetSymbolAddress((void**)&p_f,     g_f);
    cudaGetSymbolAddress((void**)&p_o,     g_o);
    cudaGetSymbolAddress((void**)&p_kqv,   g_kqv);
    cudaGetSymbolAddress((void**)&p_part,  g_vkT_part);
    cudaGetSymbolAddress((void**)&p_vkt,   g_vkT);
    cudaGetSymbolAddress((void**)&p_denom, g_denom);
    cudaGetSymbolAddress((void**)&p_AT,    g_AT);
    cudaGetSymbolAddress((void**)&p_BT,    g_BT);
    cudaGetSymbolAddress((void**)&p_npT,   g_npT);
    cudaGetSymbolAddress((void**)&p_kT,    g_kT);
    cudaGetSymbolAddress((void**)&p_xs,    g_xs);
    cudaGetSymbolAddress((void**)&p_hps,   g_hps);
    cudaGetSymbolAddress((void**)&p_fis,   g_fis);
    cudaGetSymbolAddress((void**)&p_Cs,    g_Cs);

    const int DENOM_SMEM = 2 * 128 * SMN_LD * 2;                 // 102400
    const int PREB_SMEM  = (96 + 32) * 200 * 2;                  // 51200
    const int CONV_SMEM  = (96 * 72 + 64 * 72 + 64 * 192) * 2;   // 47616
    cudaFuncSetAttribute(denom_mma_kernel,
                         cudaFuncAttributeMaxDynamicSharedMemorySize, DENOM_SMEM);
    cudaFuncSetAttribute(hmma_preB<2>,
                         cudaFuncAttributeMaxDynamicSharedMemorySize, PREB_SMEM);
    cudaFuncSetAttribute(hmma_preB<3>,
                         cudaFuncAttributeMaxDynamicSharedMemorySize, PREB_SMEM);
    cudaFuncSetAttribute(hmma_conv_uber,
                         cudaFuncAttributeMaxDynamicSharedMemorySize, CONV_SMEM);

    // preamble: npT transpose-split | x/h splits + denom zero | gates (one launch)
    preamble_kernel<<<3096, 256>>>(x, h_prev, n_prev, wix_w, wix_b, wfx_w, wfx_b,
                                   p_xs, p_hps, p_npT, p_i, p_f, p_fis, p_denom);

    // kqv (+ fused kT/qT splits) and o in ONE launch
    hmma_conv_uber<<<576, 256, CONV_SMEM>>>(p_xs, p_hps, Wkqv_w, Wkqv_b, Wox_w, Wox_b,
                                            p_kqv, p_o, p_kT, p_BT);

    // n = f @ n_prev + i @ k  (HMMA, N32 tiles) + fused AT transpose-split
    hmma_preB<2><<<H2 / 32, 256, PREB_SMEM>>>(p_fis, 384, p_npT, p_kT, 2,
                                              nullptr, nullptr, out_n, H2, p_AT);

    // vkT = v @ k^T  (96-way split-K, float4 LDS)
    vkt_part_kernel<<<dim3(3, 3, VKT_SPLIT), 256>>>(p_kqv, p_part);
    vkt_reduce_kernel<<<36, 256>>>(p_part, p_vkt);

    // C = f @ C_prev + i @ vkT (+ split)
    c_kernel<<<Bsz, Hs>>>(p_f, p_i, C_prev, p_vkt, out_C, p_Cs);

    // denom = max_c |n^T q|  (A-resident, 6 B tiles per CTA)
    denom_mma_kernel<<<dim3(72, 12), 256, DENOM_SMEM>>>(p_AT, p_BT, p_denom);

    // h = o * (C @ q) / denom  (N32 tiles)
    hmma_preB<3><<<H2 / 32, 256, PREB_SMEM>>>(p_Cs, 192, p_BT, nullptr, 1,
                                              p_o, p_denom, out_h, H2, nullptr);
}